// round 10
// baseline (speedup 1.0000x reference)
#include <cuda_runtime.h>
#include <cuda_fp16.h>
#include <math.h>
#include <stdint.h>

// Problem constants
#define BATCH 4
#define TSEQ  1024
#define NEC   1024
#define NH    16
#define HSZ   64
#define MT    (BATCH*TSEQ)      // 4096 rows
#define EPSGN 0.00064f
#define NM    ((size_t)NEC*NEC) // 1M
#define S_ELT ((size_t)MT*NEC)

// ---------------------------------------------------------------------------
// Scratch (device globals)
// ---------------------------------------------------------------------------
__device__ float    g_xx   [S_ELT];
__device__ float    g_mix  [S_ELT];
__device__ float    g_hmaa [(size_t)MT*128];
__device__ float    g_hgate[(size_t)MT*128];
__device__ float    g_hdec [(size_t)MT*64];
__device__ float    g_haaa [(size_t)MT*16];
__device__ float    g_hma  [(size_t)MT*16];
__device__ float    g_hkkk [(size_t)MT*16];
__device__ float    g_hmk  [(size_t)MT*16];
__device__ float    g_xwa  [S_ELT];          // fp32 (group 1)
__device__ __half   g_ahi  [3][S_ELT];       // xrg, xk, xv hi planes
__device__ __half   g_alo  [3][S_ELT];       // lo planes
__device__ __half   g_zhi  [S_ELT];
__device__ __half   g_zlo  [S_ELT];
__device__ __half   g_whi  [4*NM];           // Wr,Wk,Wv,Wo hi
__device__ __half   g_wlo  [4*NM];
__device__ float    g_r    [S_ELT];
__device__ float    g_gg   [S_ELT];
__device__ float    g_k    [S_ELT];
__device__ float    g_v    [S_ELT];
__device__ float    g_w    [S_ELT];
__device__ float    g_kk   [S_ELT];
__device__ float    g_a    [S_ELT];
__device__ float    g_ma   [S_ELT];
__device__ float    g_mk   [S_ELT];
__device__ float    g_b    [S_ELT];
__device__ float    g_y    [S_ELT];

enum { EPI_NONE=0, EPI_W=3, EPI_ADD=4, EPI_SIG=5 };

// ---------------------------------------------------------------------------
// helpers
// ---------------------------------------------------------------------------
__device__ __forceinline__ void mma_f16(float* c, const uint32_t* a, const uint32_t* b){
    asm volatile("mma.sync.aligned.m16n8k16.row.col.f32.f16.f16.f32 "
        "{%0,%1,%2,%3},{%4,%5,%6,%7},{%8,%9},{%0,%1,%2,%3};\n"
        : "+f"(c[0]), "+f"(c[1]), "+f"(c[2]), "+f"(c[3])
        : "r"(a[0]), "r"(a[1]), "r"(a[2]), "r"(a[3]), "r"(b[0]), "r"(b[1]));
}
__device__ __forceinline__ void ldsm_x4(uint32_t* r, uint32_t addr){
    asm volatile("ldmatrix.sync.aligned.m8n8.x4.shared.b16 {%0,%1,%2,%3}, [%4];"
        : "=r"(r[0]),"=r"(r[1]),"=r"(r[2]),"=r"(r[3]) : "r"(addr));
}
__device__ __forceinline__ void cpa16(uint32_t dst, const void* src){
    asm volatile("cp.async.cg.shared.global [%0],[%1],16;\n"::"r"(dst),"l"(src));
}
__device__ __forceinline__ void cpa4(uint32_t dst, const void* src){
    asm volatile("cp.async.ca.shared.global [%0],[%1],4;\n"::"r"(dst),"l"(src));
}
#define CP_COMMIT() asm volatile("cp.async.commit_group;\n")
#define CP_WAIT0()  asm volatile("cp.async.wait_group 0;\n")
#define CP_WAIT1()  asm volatile("cp.async.wait_group 1;\n")

// ---------------------------------------------------------------------------
// Token shift
// ---------------------------------------------------------------------------
__global__ void shift_kernel(const float* __restrict__ x,
                             const float* __restrict__ tmaax,
                             float* __restrict__ xx,
                             float* __restrict__ mix)
{
    size_t i = (size_t)blockIdx.x * blockDim.x + threadIdx.x;
    if (i >= S_ELT) return;
    int c = (int)(i % NEC);
    size_t row = i / NEC;
    int t = (int)(row % TSEQ);
    float xv = x[i];
    float xp = (t > 0) ? x[i - NEC] : 0.f;
    float d = xp - xv;
    xx[i]  = d;
    mix[i] = fmaf(d, tmaax[c], xv);
}

// ---------------------------------------------------------------------------
// Weight pack (fp16 hi/lo planes)
// ---------------------------------------------------------------------------
__global__ void wpack_kernel(const float* __restrict__ Wr, const float* __restrict__ Wk,
                             const float* __restrict__ Wv, const float* __restrict__ Wo,
                             __half* __restrict__ whi, __half* __restrict__ wlo)
{
    size_t i = (size_t)blockIdx.x * blockDim.x + threadIdx.x;
    if (i >= 4*NM) return;
    int seg = (int)(i >> 20);
    size_t off = i & (NM - 1);
    const float* src = (seg==0) ? Wr : (seg==1) ? Wk : (seg==2) ? Wv : Wo;
    float v = src[off];
    __half hi = __float2half_rn(v);
    whi[i] = hi;
    wlo[i] = __float2half_rn(v - __half2float(hi));
}

// ---------------------------------------------------------------------------
// fp16 split-2 NT GEMM via ldmatrix: C = (Ah+Al) * (Bh+Bl)^T
// hi/lo as separate half planes. Tile 128x128xBK32, 256 threads,
// cp.async double-buffered, 2 CTA/SM. 3 products AhBh+AhBl+AlBh.
// B tile is [n][k] row-major, so B fragments use NON-transposed ldmatrix
// (register = consecutive-k pair at fixed n, n = lane/4) — same mapping as
// the verified manual loads in the R8 kernel.
// ---------------------------------------------------------------------------
#define G6_LDH  40                 // halves per smem row (32 + 8 pad)
#define G6_TILEB (128*G6_LDH*2)    // 10240 B per tile
#define G6_STGB  (4*G6_TILEB)      // 40960 B per stage: Ah, Al, Bh, Bl

struct G6Args { const __half* Ah[3]; const __half* Al[3];
                const __half* Bh[3]; const __half* Bl[3]; float* C[3]; };

__global__ __launch_bounds__(256, 2)
void gemm_tc6(G6Args args, int N, int K)
{
    extern __shared__ __align__(16) uint8_t sm6[];
    const int z = blockIdx.z;
    const int tid = threadIdx.x;
    const int bm0 = blockIdx.y*128, bn0 = blockIdx.x*128;
    const int warp = tid>>5, lane = tid&31, grp = lane>>2, q = lane&3;
    const int wm = (warp&1)*64, wn = (warp>>1)*32;
    const uint32_t sbase = (uint32_t)__cvta_generic_to_shared(sm6);

    float acc[4][4][4];
    #pragma unroll
    for (int mi=0;mi<4;mi++)
        #pragma unroll
        for (int ni=0;ni<4;ni++)
            #pragma unroll
            for (int e=0;e<4;e++) acc[mi][ni][e]=0.f;

    // loader: thread covers row r = tid>>1, k-half pi = tid&1, all 4 tiles
    const int lr = tid>>1, pi = tid&1;
    const __half* srcAh = args.Ah[z] + (size_t)(bm0+lr)*K + pi*16;
    const __half* srcAl = args.Al[z] + (size_t)(bm0+lr)*K + pi*16;
    const __half* srcBh = args.Bh[z] + (size_t)(bn0+lr)*K + pi*16;
    const __half* srcBl = args.Bl[z] + (size_t)(bn0+lr)*K + pi*16;
    const uint32_t dr = (uint32_t)(lr*G6_LDH + pi*16)*2;

#define G6_LOAD(st, kb) do {                                                  \
        uint32_t _b = sbase + (st)*G6_STGB + dr;                              \
        cpa16(_b,                         srcAh + (kb));                      \
        cpa16(_b + 16,                    srcAh + (kb) + 8);                  \
        cpa16(_b + G6_TILEB,              srcAl + (kb));                      \
        cpa16(_b + G6_TILEB + 16,         srcAl + (kb) + 8);                  \
        cpa16(_b + 2*G6_TILEB,            srcBh + (kb));                      \
        cpa16(_b + 2*G6_TILEB + 16,       srcBh + (kb) + 8);                  \
        cpa16(_b + 3*G6_TILEB,            srcBl + (kb));                      \
        cpa16(_b + 3*G6_TILEB + 16,       srcBl + (kb) + 8);                  \
    } while(0)

    G6_LOAD(0, 0); CP_COMMIT();

    // ldmatrix per-lane address offsets (within a tile), bytes.
    // A (x4, non-trans): matrices (m0-7,k0-7),(m8-15,k0-7),(m0-7,k8-15),(m8-15,k8-15)
    //   -> lanes 0-7: m0-7 @k; 8-15: m8-15 @k; 16-23: m0-7 @k+8; 24-31: m8-15 @k+8
    // B (x4, non-trans on [n][k]): matrices (n0-7,k0-7),(n0-7,k8-15),(n8-15,k0-7),(n8-15,k8-15)
    //   -> lanes 0-7: n0-7 @k; 8-15: n0-7 @k+8; 16-23: n8-15 @k; 24-31: n8-15 @k+8
    uint32_t aoff[4], boff[2];
    {
        int arow = (lane & 7) + ((lane >> 3) & 1) * 8;
        int acol = ((lane >> 4) & 1) * 8;
        #pragma unroll
        for (int mi = 0; mi < 4; mi++)
            aoff[mi] = (uint32_t)((wm + mi*16 + arow)*G6_LDH + acol)*2;
        int brow = (lane & 7) + ((lane >> 4) & 1) * 8;
        int bcol = ((lane >> 3) & 1) * 8;
        #pragma unroll
        for (int u = 0; u < 2; u++)
            boff[u] = (uint32_t)((wn + u*16 + brow)*G6_LDH + bcol)*2;
    }

    int p = 0;
    for (int kb = 0; kb < K; kb += 32) {
        CP_WAIT0();
        __syncthreads();
        if (kb + 32 < K) { G6_LOAD(p^1, kb+32); CP_COMMIT(); }

        const uint32_t sA = sbase + p*G6_STGB;
        const uint32_t sB = sA + 2*G6_TILEB;

        #pragma unroll
        for (int kc = 0; kc < 32; kc += 16) {
            uint32_t ah[4][4], al[4][4], bh[4][2], bl[4][2];
            #pragma unroll
            for (int mi = 0; mi < 4; mi++) {
                ldsm_x4(ah[mi], sA + aoff[mi] + kc*2);
                ldsm_x4(al[mi], sA + G6_TILEB + aoff[mi] + kc*2);
            }
            #pragma unroll
            for (int u = 0; u < 2; u++) {
                uint32_t rb[4], rl[4];
                ldsm_x4(rb, sB + boff[u] + kc*2);
                ldsm_x4(rl, sB + G6_TILEB + boff[u] + kc*2);
                bh[u*2+0][0]=rb[0]; bh[u*2+0][1]=rb[1];
                bh[u*2+1][0]=rb[2]; bh[u*2+1][1]=rb[3];
                bl[u*2+0][0]=rl[0]; bl[u*2+0][1]=rl[1];
                bl[u*2+1][0]=rl[2]; bl[u*2+1][1]=rl[3];
            }
            #pragma unroll
            for (int mi = 0; mi < 4; mi++)
                #pragma unroll
                for (int ni = 0; ni < 4; ni++) {
                    mma_f16(acc[mi][ni], ah[mi], bh[ni]);
                    mma_f16(acc[mi][ni], ah[mi], bl[ni]);
                    mma_f16(acc[mi][ni], al[mi], bh[ni]);
                }
        }
        __syncthreads();
        p ^= 1;
    }

    float* C = args.C[z];
    #pragma unroll
    for (int mi = 0; mi < 4; mi++) {
        int row0 = bm0 + wm + mi*16 + grp;
        #pragma unroll
        for (int ni = 0; ni < 4; ni++) {
            int col = bn0 + wn + ni*8 + 2*q;
            *(float2*)&C[(size_t)row0*N + col]     = make_float2(acc[mi][ni][0], acc[mi][ni][1]);
            *(float2*)&C[(size_t)(row0+8)*N + col] = make_float2(acc[mi][ni][2], acc[mi][ni][3]);
        }
    }
#undef G6_LOAD
}

// ---------------------------------------------------------------------------
// Grouped NT LoRA-hidden kernel: C = act(A @ B_tile^T), K=1024.
// A is fp32 or (hi,lo) half planes.
// ---------------------------------------------------------------------------
struct NTTile { const float* B; float* C; int ldc; int nvalid; int tanhf; int asel; };
struct NTArgs { const void* Aptr[3]; const void* Aptr2[3]; int apk[3]; NTTile t[12]; };

__global__ __launch_bounds__(128)
void lora_nt_kernel(NTArgs args)
{
    constexpr int BK=32, K=NEC;
    __shared__ __align__(16) float As[BK][132];
    __shared__ __align__(16) float Bs[BK][36];
    NTTile tl = args.t[blockIdx.x];
    const int apk = args.apk[tl.asel];
    const int bm0 = blockIdx.y*128;
    const int tid = threadIdx.x;
    const int tx = tid & 7;
    const int ty = tid >> 3;

    float acc[8][4];
    #pragma unroll
    for (int i=0;i<8;i++)
        #pragma unroll
        for (int j=0;j<4;j++) acc[i][j]=0.f;

    for (int kb = 0; kb < K; kb += BK) {
        if (apk) {
            const __half* Ahp = (const __half*)args.Aptr[tl.asel];
            const __half* Alp = (const __half*)args.Aptr2[tl.asel];
            #pragma unroll
            for (int l = 0; l < 8; l++) {
                int idx = tid + l*128;
                int r = idx >> 3, c = (idx & 7)*4;
                uint2 uh = *(const uint2*)(Ahp + (size_t)(bm0+r)*K + kb + c);
                uint2 ul = *(const uint2*)(Alp + (size_t)(bm0+r)*K + kb + c);
                float2 h0 = __half22float2(*(__half2*)&uh.x);
                float2 h1 = __half22float2(*(__half2*)&uh.y);
                float2 l0 = __half22float2(*(__half2*)&ul.x);
                float2 l1 = __half22float2(*(__half2*)&ul.y);
                As[c+0][r]=h0.x+l0.x; As[c+1][r]=h0.y+l0.y;
                As[c+2][r]=h1.x+l1.x; As[c+3][r]=h1.y+l1.y;
            }
        } else {
            const float* A = (const float*)args.Aptr[tl.asel];
            #pragma unroll
            for (int l = 0; l < 8; l++) {
                int idx = tid + l*128;
                int r = idx >> 3, c = (idx & 7)*4;
                float4 val = *(const float4*)(A + (size_t)(bm0+r)*K + kb + c);
                As[c+0][r]=val.x; As[c+1][r]=val.y; As[c+2][r]=val.z; As[c+3][r]=val.w;
            }
        }
        #pragma unroll
        for (int l = 0; l < 2; l++) {
            int idx = tid + l*128;
            int r = idx >> 3, c = (idx & 7)*4;
            float4 val = (r < tl.nvalid) ?
                *(const float4*)(tl.B + (size_t)r*K + kb + c) : make_float4(0,0,0,0);
            Bs[c+0][r]=val.x; Bs[c+1][r]=val.y; Bs[c+2][r]=val.z; Bs[c+3][r]=val.w;
        }
        __syncthreads();
        #pragma unroll
        for (int kk = 0; kk < BK; kk++) {
            float4 m0 = *(const float4*)&As[kk][ty*8];
            float4 m1 = *(const float4*)&As[kk][ty*8+4];
            float4 rn = *(const float4*)&Bs[kk][tx*4];
            float rm[8] = {m0.x,m0.y,m0.z,m0.w,m1.x,m1.y,m1.z,m1.w};
            #pragma unroll
            for (int i=0;i<8;i++) {
                acc[i][0] = fmaf(rm[i], rn.x, acc[i][0]);
                acc[i][1] = fmaf(rm[i], rn.y, acc[i][1]);
                acc[i][2] = fmaf(rm[i], rn.z, acc[i][2]);
                acc[i][3] = fmaf(rm[i], rn.w, acc[i][3]);
            }
        }
        __syncthreads();
    }
    #pragma unroll
    for (int i=0;i<8;i++) {
        int row = bm0 + ty*8 + i;
        #pragma unroll
        for (int j=0;j<4;j++) {
            int col = tx*4 + j;
            if (col < tl.nvalid) {
                float vv = acc[i][j];
                if (tl.tanhf) vv = tanhf(vv);
                tl.C[(size_t)row*tl.ldc + col] = vv;
            }
        }
    }
}

// ---------------------------------------------------------------------------
// Fused xm kernel: val = x + xx*(Ag @ Bg + time_maa[g]).
// g==1 -> fp32 (xwa); g 0/2/3 -> (hi,lo) half planes slot 0/1/2.
// ---------------------------------------------------------------------------
__global__ __launch_bounds__(256, 2)
void xm_kernel(const float* __restrict__ hmaa,
               const float* __restrict__ maa_w2,
               const float* __restrict__ x,
               const float* __restrict__ xx,
               const float* __restrict__ time_maa,
               float* __restrict__ xwa,
               __half* __restrict__ ahibase,
               __half* __restrict__ alobase)
{
    constexpr int BM=128, BN=128, BK=32;
    __shared__ float As[BK][BM+1];
    __shared__ float Bs[BK][BN];
    const int g = blockIdx.z;
    const float* A = hmaa + g*32;
    const float* B = maa_w2 + (size_t)g*32*NEC;
    const int slot = (g==0) ? 0 : (g==2) ? 1 : 2;
    __half* HI = ahibase + (size_t)slot*S_ELT;
    __half* LO = alobase + (size_t)slot*S_ELT;
    const float* tm = time_maa + g*NEC;
    const int bm0 = blockIdx.y*BM, bn0 = blockIdx.x*BN;
    const int tid = threadIdx.x;
    const int tx = tid & 15, ty = tid >> 4;

    float acc[8][8];
    #pragma unroll
    for (int i=0;i<8;i++)
        #pragma unroll
        for (int j=0;j<8;j++) acc[i][j]=0.f;

    #pragma unroll
    for (int l = 0; l < 4; l++) {
        int idx = tid + l*256;
        int r = idx >> 3, c = (idx & 7)*4;
        float4 val = *(const float4*)(A + (size_t)(bm0+r)*128 + c);
        As[c+0][r]=val.x; As[c+1][r]=val.y; As[c+2][r]=val.z; As[c+3][r]=val.w;
    }
    #pragma unroll
    for (int l = 0; l < 4; l++) {
        int idx = tid + l*256;
        int r = idx >> 5, c = (idx & 31)*4;
        *(float4*)&Bs[r][c] = *(const float4*)(B + (size_t)r*NEC + bn0 + c);
    }
    __syncthreads();
    #pragma unroll
    for (int kk = 0; kk < BK; kk++) {
        float rm[8], rn[8];
        #pragma unroll
        for (int i=0;i<8;i++) rm[i] = As[kk][ty*8+i];
        #pragma unroll
        for (int j=0;j<8;j++) rn[j] = Bs[kk][tx*8+j];
        #pragma unroll
        for (int i=0;i<8;i++)
            #pragma unroll
            for (int j=0;j<8;j++) acc[i][j] = fmaf(rm[i], rn[j], acc[i][j]);
    }
    #pragma unroll
    for (int i=0;i<8;i++) {
        int row = bm0 + ty*8 + i;
        #pragma unroll
        for (int j=0;j<8;j+=2) {
            int col = bn0 + tx*8 + j;
            size_t idx = (size_t)row*NEC + col;
            float2 xv = *(const float2*)&x[idx];
            float2 dv = *(const float2*)&xx[idx];
            float v0 = fmaf(dv.x, acc[i][j]   + tm[col],   xv.x);
            float v1 = fmaf(dv.y, acc[i][j+1] + tm[col+1], xv.y);
            if (g == 1) {
                *(float2*)&xwa[idx] = make_float2(v0, v1);
            } else {
                __half h0 = __float2half_rn(v0), h1 = __float2half_rn(v1);
                __half l0 = __float2half_rn(v0 - __half2float(h0));
                __half l1 = __float2half_rn(v1 - __half2float(h1));
                *(__half2*)&HI[idx] = __halves2half2(h0, h1);
                *(__half2*)&LO[idx] = __halves2half2(l0, l1);
            }
        }
    }
}

// ---------------------------------------------------------------------------
// Grouped second-stage NN kernel
// ---------------------------------------------------------------------------
struct NNGroup { const float* A; const float* B; float* C; int K; int epi;
                 const float* e0; const float* e2; };
struct NNArgs { NNGroup g[6]; };

__global__ __launch_bounds__(256)
void lora_nn_kernel(NNArgs args)
{
    constexpr int BM=128, BN=128, BK=16;
    __shared__ float As[BK][BM+1];
    __shared__ float Bs[BK][BN];
    NNGroup grp = args.g[blockIdx.z];
    const int K = grp.K;
    const int bm0 = blockIdx.y*BM, bn0 = blockIdx.x*BN;
    const int tid = threadIdx.x;
    const int tx = tid & 15, ty = tid >> 4;

    float acc[8][8];
    #pragma unroll
    for (int i=0;i<8;i++)
        #pragma unroll
        for (int j=0;j<8;j++) acc[i][j]=0.f;

    for (int kb = 0; kb < K; kb += BK) {
        #pragma unroll
        for (int l = 0; l < 2; l++) {
            int idx = tid + l*256;
            int r = idx >> 2, c = (idx & 3)*4;
            float4 val = *(const float4*)(grp.A + (size_t)(bm0+r)*K + kb + c);
            As[c+0][r]=val.x; As[c+1][r]=val.y; As[c+2][r]=val.z; As[c+3][r]=val.w;
        }
        #pragma unroll
        for (int l = 0; l < 2; l++) {
            int idx = tid + l*256;
            int r = idx >> 5, c = (idx & 31)*4;
            *(float4*)&Bs[r][c] = *(const float4*)(grp.B + (size_t)(kb+r)*NEC + bn0 + c);
        }
        __syncthreads();
        #pragma unroll
        for (int kk = 0; kk < BK; kk++) {
            float rm[8], rn[8];
            #pragma unroll
            for (int i=0;i<8;i++) rm[i] = As[kk][ty*8+i];
            #pragma unroll
            for (int j=0;j<8;j++) rn[j] = Bs[kk][tx*8+j];
            #pragma unroll
            for (int i=0;i<8;i++)
                #pragma unroll
                for (int j=0;j<8;j++) acc[i][j] = fmaf(rm[i], rn[j], acc[i][j]);
        }
        __syncthreads();
    }
    #pragma unroll
    for (int i=0;i<8;i++) {
        int row = bm0 + ty*8 + i;
        #pragma unroll
        for (int j=0;j<8;j++) {
            int col = bn0 + tx*8 + j;
            size_t idx = (size_t)row*NEC + col;
            float vv = acc[i][j], outv;
            switch (grp.epi) {
                case EPI_W: {
                    float tt = -(grp.e2[col] + vv);
                    float sp = (tt > 15.f) ? tt : log1pf(expf(tt));
                    outv = -sp - 0.5f;
                } break;
                case EPI_ADD: outv = grp.e0[idx] + vv; break;
                case EPI_SIG: {
                    float u = grp.e2[col] + vv;
                    outv = 1.f / (1.f + expf(-u));
                } break;
                default: outv = vv;
            }
            grp.C[idx] = outv;
        }
    }
}

// ---------------------------------------------------------------------------
// warp sum
// ---------------------------------------------------------------------------
__device__ __forceinline__ float warp_sum(float v)
{
    #pragma unroll
    for (int o = 16; o > 0; o >>= 1) v += __shfl_xor_sync(0xffffffffu, v, o);
    return v;
}

// ---------------------------------------------------------------------------
// prep
// ---------------------------------------------------------------------------
__global__ void prep_kernel(float* kptr, float* kkptr,
                            const float* __restrict__ a,
                            const float* __restrict__ ma,
                            const float* __restrict__ mk,
                            float* wptr,
                            float* __restrict__ b)
{
    int m = blockIdx.x;
    int h = threadIdx.x >> 5;
    int lane = threadIdx.x & 31;
    size_t base = (size_t)m*NEC + h*HSZ;
    size_t i0 = base + lane, i1 = i0 + 32;

    float kk0 = kkptr[i0], kk1 = kkptr[i1];
    float ss = warp_sum(kk0*kk0 + kk1*kk1);
    float inv = 1.f / fmaxf(sqrtf(ss), 1e-12f);
    float n0 = kk0*inv, n1 = kk1*inv;
    kkptr[i0] = n0; kkptr[i1] = n1;

    float a0 = a[i0], a1 = a[i1];
    b[i0] = -n0*a0; b[i1] = -n1*a1;

    float ma0 = ma[i0], ma1 = ma[i1];
    float k0v = kptr[i0], k1v = kptr[i1];
    float w0 = wptr[i0], w1 = wptr[i1];
    float mk0 = mk[i0], mk1 = mk[i1];
    kptr[i0] = k0v * (ma0 + a0*(1.f - ma0)) * expf(w0*mk0);
    kptr[i1] = k1v * (ma1 + a1*(1.f - ma1)) * expf(w1*mk1);
    wptr[i0] = expf(-expf(w0));
    wptr[i1] = expf(-expf(w1));
}

// ---------------------------------------------------------------------------
// RWKV7 recurrence v4: 2 blocks per head; 32 rows x 8-way column split;
// 3-stage cp.async ring.
// ---------------------------------------------------------------------------
__global__ __launch_bounds__(256)
void wkv7_kernel(const float* __restrict__ q, const float* __restrict__ w,
                 const float* __restrict__ k, const float* __restrict__ v,
                 const float* __restrict__ a, const float* __restrict__ b,
                 float* __restrict__ y)
{
    const int blk = blockIdx.x;            // 0..127
    const int bh = blk >> 1, rh = blk & 1;
    const int batch = bh >> 4, h = bh & 15;
    const int tid = threadIdx.x;
    const int il = tid >> 3, qd = tid & 7;

    __shared__ __align__(16) float buf[3][352];

    float s[8];
    #pragma unroll
    for (int j = 0; j < 8; j++) s[j] = 0.f;

    const size_t base = (size_t)batch * TSEQ * NEC + (size_t)h * HSZ;

    const float* table[4] = {q, w, k, a};
    const float* s0 = table[tid>>6] + base + (tid & 63);
    const float* s1 = nullptr;
    if (tid < 64)       s1 = b + base + tid;
    else if (tid < 96)  s1 = v + base + rh*32 + (tid - 64);
    const uint32_t sb = (uint32_t)__cvta_generic_to_shared(buf);
    const uint32_t d0 = sb + (uint32_t)tid*4;
    const uint32_t d1 = sb + (uint32_t)(256 + tid)*4;
    const uint32_t STRB = 352*4;

    cpa4(d0, s0);
    if (tid < 96) cpa4(d1, s1);
    CP_COMMIT();
    cpa4(d0 + STRB, s0 + NEC);
    if (tid < 96) cpa4(d1 + STRB, s1 + NEC);
    CP_COMMIT();

    const size_t ybase = base + (size_t)rh*32 + il;

    int p = 0;
    for (int t = 0; t < TSEQ; t++) {
        CP_WAIT1();
        __syncthreads();

        {
            int st = p + 2; if (st >= 3) st -= 3;
            if (t + 2 < TSEQ) {
                size_t o = (size_t)(t+2)*NEC;
                cpa4(d0 + (uint32_t)st*STRB, s0 + o);
                if (tid < 96) cpa4(d1 + (uint32_t)st*STRB, s1 + o);
            }
            CP_COMMIT();
        }

        const float* bb = buf[p];
        const int co = qd*8;
        const float4* q4 = (const float4*)(bb +   0 + co);
        const float4* w4 = (const float4*)(bb +  64 + co);
        const float4* k4 = (const float4*)(bb + 128 + co);
        const float4* a4 = (const float4*)(bb + 192 + co);
        const float4* b4 = (const float4*)(bb + 256 + co);
        float vi = bb[320 + il];

        float4 av0 = a4[0], av1 = a4[1];
        float sa0 = fmaf(s[0], av0.x, s[4]*av1.x);
        float sa1 = fmaf(s[1], av0.y, s[5]*av1.y);
        float sa2 = fmaf(s[2], av0.z, s[6]*av1.z);
        float sa3 = fmaf(s[3], av0.w, s[7]*av1.w);
        float sa = (sa0+sa1) + (sa2+sa3);
        sa += __shfl_xor_sync(0xffffffffu, sa, 1);
        sa += __shfl_xor_sync(0xffffffffu, sa, 2);
        sa += __shfl_xor_sync(0xffffffffu, sa, 4);

        float4 wv0 = w4[0], wv1 = w4[1];
        float4 kv0 = k4[0], kv1 = k4[1];
        float4 bv0 = b4[0], bv1 = b4[1];
        float4 qv0 = q4[0], qv1 = q4[1];

        float t0 = fmaf(s[0], wv0.x, fmaf(sa, bv0.x, vi*kv0.x));
        float t1 = fmaf(s[1], wv0.y, fmaf(sa, bv0.y, vi*kv0.y));
        float t2 = fmaf(s[2], wv0.z, fmaf(sa, bv0.z, vi*kv0.z));
        float t3 = fmaf(s[3], wv0.w, fmaf(sa, bv0.w, vi*kv0.w));
        float t4 = fmaf(s[4], wv1.x, fmaf(sa, bv1.x, vi*kv1.x));
        float t5 = fmaf(s[5], wv1.y, fmaf(sa, bv1.y, vi*kv1.y));
        float t6 = fmaf(s[6], wv1.z, fmaf(sa, bv1.z, vi*kv1.z));
        float t7 = fmaf(s[7], wv1.w, fmaf(sa, bv1.w, vi*kv1.w));
        s[0]=t0; s[1]=t1; s[2]=t2; s[3]=t3; s[4]=t4; s[5]=t5; s[6]=t6; s[7]=t7;

        float y0 = fmaf(t0, qv0.x, t4*qv1.x);
        float y1 = fmaf(t1, qv0.y, t5*qv1.y);
        float y2 = fmaf(t2, qv0.z, t6*qv1.z);
        float y3 = fmaf(t3, qv0.w, t7*qv1.w);
        float yi = (y0+y1) + (y2+y3);
        yi += __shfl_xor_sync(0xffffffffu, yi, 1);
        yi += __shfl_xor_sync(0xffffffffu, yi, 2);
        yi += __shfl_xor_sync(0xffffffffu, yi, 4);
        if (qd == 0) y[ybase + (size_t)t*NEC] = yi;

        if (++p == 3) p = 0;
    }
}

// ---------------------------------------------------------------------------
// GroupNorm + bonus + gate -> (hi,lo) half planes of z
// ---------------------------------------------------------------------------
__global__ void gn_kernel(const float* __restrict__ y,
                          const float* __restrict__ r,
                          const float* __restrict__ k,
                          const float* __restrict__ v,
                          const float* __restrict__ gg,
                          const float* __restrict__ ln_w,
                          const float* __restrict__ ln_b,
                          const float* __restrict__ faaaa,
                          __half* __restrict__ zhi,
                          __half* __restrict__ zlo)
{
    int m = blockIdx.x;
    int h = threadIdx.x >> 5;
    int lane = threadIdx.x & 31;
    size_t base = (size_t)m*NEC + h*HSZ;
    int c0 = h*HSZ + lane, c1 = c0 + 32;
    size_t i0 = base + lane, i1 = i0 + 32;

    float y0 = y[i0], y1 = y[i1];
    float mu = warp_sum(y0 + y1) * (1.f/64.f);
    float d0 = y0 - mu, d1 = y1 - mu;
    float var = warp_sum(d0*d0 + d1*d1) * (1.f/64.f);
    float rstd = rsqrtf(var + EPSGN);
    float yn0 = d0*rstd*ln_w[c0] + ln_b[c0];
    float yn1 = d1*rstd*ln_w[c1] + ln_b[c1];

    float r0 = r[i0], r1 = r[i1];
    float k0v = k[i0], k1v = k[i1];
    float rk = warp_sum(r0*k0v*faaaa[c0] + r1*k1v*faaaa[c1]);

    float v0 = v[i0], v1 = v[i1];
    float z0 = (yn0 + rk*v0) * gg[i0];
    float z1 = (yn1 + rk*v1) * gg[i1];

    __half h0 = __float2half_rn(z0), h1 = __float2half_rn(z1);
    zhi[i0] = h0; zlo[i0] = __float2half_rn(z0 - __half2float(h0));
    zhi[i1] = h1; zlo[i1] = __float2half_rn(z1 - __half2float(h1));
}

// ---------------------------------------------------------------------------
// Host side
// ---------------------------------------------------------------------------
extern "C" void kernel_launch(void* const* d_in, const int* in_sizes, int n_in,
                              void* d_out, int out_size)
{
    const float* x          = (const float*)d_in[0];
    const float* time_maa_x = (const float*)d_in[1];
    const float* time_maa   = (const float*)d_in[2];
    const float* maa_w1     = (const float*)d_in[3];
    const float* maa_w2     = (const float*)d_in[4];
    const float* decay_w1   = (const float*)d_in[5];
    const float* decay_w2   = (const float*)d_in[6];
    const float* aaa_w1     = (const float*)d_in[7];
    const float* aaa_w2     = (const float*)d_in[8];
    const float* kkk_w1     = (const float*)d_in[9];
    const float* kkk_w2     = (const float*)d_in[10];
    const float* gate_w1    = (const float*)d_in[11];
    const float* gate_w2    = (const float*)d_in[12];
    const float* ma_w1      = (const float*)d_in[13];
    const float* ma_w2      = (const float*)d_in[14];
    const float* mk_w1      = (const float*)d_in[15];
    const float* mk_w2      = (const float*)d_in[16];
    const float* time_decay = (const float*)d_in[17];
    const float* time_faaaa = (const float*)d_in[18];
    const float* time_aaaaa = (const float*)d_in[19];
    const float* time_misc_a= (const float*)d_in[20];
    const float* time_misc_k= (const float*)d_in[21];
    const float* Wr         = (const float*)d_in[22];
    const float* Wk         = (const float*)d_in[23];
    const float* Wv         = (const float*)d_in[24];
    const float* Wo         = (const float*)d_in[25];
    const float* ln_w       = (const float*)d_in[26];
    const float* ln_b       = (const float*)d_in[27];
    float* out = (float*)d_out;

    float *xx,*mix,*hmaa,*hgate,*hdec,*haaa,*hma,*hkkk,*hmk,*xwa;
    __half *ahi,*alo,*zhi,*zlo,*whi,*wlo;
    float *r,*gg,*k,*v,*w,*kk,*a,*ma,*mk,*b,*y;
    cudaGetSymbolAddress((void**)&xx,   g_xx);
    cudaGetSymbolAddress((void**)&mix,  g_mix);
    cudaGetSymbolAddress((void**)&hmaa, g_hmaa);
    cudaGetSymbolAddress((void**)&hgate,g_hgate);
    cudaGetSymbolAddress((void**)&hdec, g_hdec);
    cudaGetSymbolAddress((void**)&haaa, g_haaa);
    cudaGetSymbolAddress((void**)&hma,  g_hma);
    cudaGetSymbolAddress((void**)&hkkk, g_hkkk);
    cudaGetSymbolAddress((void**)&hmk,  g_hmk);
    cudaGetSymbolAddress((void**)&xwa,  g_xwa);
    cudaGetSymbolAddress((void**)&ahi,  g_ahi);
    cudaGetSymbolAddress((void**)&alo,  g_alo);
    cudaGetSymbolAddress((void**)&zhi,  g_zhi);
    cudaGetSymbolAddress((void**)&zlo,  g_zlo);
    cudaGetSymbolAddress((void**)&whi,  g_whi);
    cudaGetSymbolAddress((void**)&wlo,  g_wlo);
    cudaGetSymbolAddress((void**)&r,    g_r);
    cudaGetSymbolAddress((void**)&gg,   g_gg);
    cudaGetSymbolAddress((void**)&k,    g_k);
    cudaGetSymbolAddress((void**)&v,    g_v);
    cudaGetSymbolAddress((void**)&w,    g_w);
    cudaGetSymbolAddress((void**)&kk,   g_kk);
    cudaGetSymbolAddress((void**)&a,    g_a);
    cudaGetSymbolAddress((void**)&ma,   g_ma);
    cudaGetSymbolAddress((void**)&mk,   g_mk);
    cudaGetSymbolAddress((void**)&b,    g_b);
    cudaGetSymbolAddress((void**)&y,    g_y);

    static bool attr_done = false;
    if (!attr_done) {
        cudaFuncSetAttribute(gemm_tc6, cudaFuncAttributeMaxDynamicSharedMemorySize,
                             2*G6_STGB);
        attr_done = true;
    }
    const int g6_smem = 2*G6_STGB;

    // 1) token shift
    shift_kernel<<<(unsigned)((S_ELT + 255)/256), 256>>>(x, time_maa_x, xx, mix);

    // 2) weight fp16 hi/lo pack
    wpack_kernel<<<(unsigned)((4*NM + 255)/256), 256>>>(Wr, Wk, Wv, Wo, whi, wlo);

    // 3) maa hidden (4 tiles)
    {
        NTArgs na = {};
        na.Aptr[0] = mix; na.apk[0] = 0;
        for (int i = 0; i < 4; i++)
            na.t[i] = { maa_w1 + (size_t)i*32*NEC, hmaa + i*32, 128, 32, 1, 0 };
        lora_nt_kernel<<<dim3(4, MT/128), 128>>>(na);
    }

    // 4) xm fused (4 groups; planes for 0/2/3, fp32 for 1)
    xm_kernel<<<dim3(8, MT/128, 4), 256>>>(hmaa, maa_w2, x, xx, time_maa, xwa, ahi, alo);

    // 5) hidden group 2 (10 tiles)
    {
        NTArgs na = {};
        na.Aptr[0] = ahi + 0*S_ELT; na.Aptr2[0] = alo + 0*S_ELT; na.apk[0] = 1;  // xrg
        na.Aptr[1] = xwa;           na.apk[1] = 0;                               // xwa
        na.Aptr[2] = ahi + 1*S_ELT; na.Aptr2[2] = alo + 1*S_ELT; na.apk[2] = 1;  // xk
        int ti = 0;
        for (int i = 0; i < 4; i++)
            na.t[ti++] = { gate_w1 + (size_t)i*32*NEC, hgate + i*32, 128, 32, 1, 0 };
        for (int i = 0; i < 2; i++)
            na.t[ti++] = { decay_w1 + (size_t)i*32*NEC, hdec + i*32, 64, 32, 1, 1 };
        na.t[ti++] = { aaa_w1, haaa, 16, 16, 0, 1 };
        na.t[ti++] = { ma_w1,  hma,  16, 16, 0, 1 };
        na.t[ti++] = { kkk_w1, hkkk, 16, 16, 1, 2 };
        na.t[ti++] = { mk_w1,  hmk,  16, 16, 0, 2 };
        lora_nt_kernel<<<dim3(10, MT/128), 128>>>(na);
    }

    // 6) big GEMMs r,k,v fused in one launch (grid.z = 3)
    {
        G6Args ga = {};
        for (int z = 0; z < 3; z++) {
            ga.Ah[z] = ahi + (size_t)z*S_ELT;
            ga.Al[z] = alo + (size_t)z*S_ELT;
            ga.Bh[z] = whi + (size_t)z*NM;
            ga.Bl[z] = wlo + (size_t)z*NM;
        }
        ga.C[0] = r; ga.C[1] = k; ga.C[2] = v;
        gemm_tc6<<<dim3(8,32,3), 256, g6_smem>>>(ga, NEC, NEC);
    }

    // 7) second stage (6 groups)
    {
        NNArgs nn = {};
        nn.g[0] = { hgate, gate_w2,  gg, 128, EPI_NONE, nullptr, nullptr };
        nn.g[1] = { hdec,  decay_w2, w,   64, EPI_W,    nullptr, time_decay };
        nn.g[2] = { hkkk,  kkk_w2,   kk,  16, EPI_ADD,  k,       nullptr };
        nn.g[3] = { haaa,  aaa_w2,   a,   16, EPI_SIG,  nullptr, time_aaaaa };
        nn.g[4] = { hma,   ma_w2,    ma,  16, EPI_SIG,  nullptr, time_misc_a };
        nn.g[5] = { hmk,   mk_w2,    mk,  16, EPI_SIG,  nullptr, time_misc_k };
        lora_nn_kernel<<<dim3(8, MT/128, 6), 256>>>(nn);
    }

    // 8) prep
    prep_kernel<<<MT, 512>>>(k, kk, a, ma, mk, w, b);

    // 9) recurrence (2 blocks per head)
    wkv7_kernel<<<BATCH*NH*2, 256>>>(r, w, k, v, kk, b, y);

    // 10) groupnorm + bonus + gate -> z hi/lo planes
    gn_kernel<<<MT, 512>>>(y, r, k, v, gg, ln_w, ln_b, time_faaaa, zhi, zlo);

    // 11) out = z @ Wo.T
    {
        G6Args ga = {};
        ga.Ah[0] = zhi; ga.Al[0] = zlo;
        ga.Bh[0] = whi + 3*NM; ga.Bl[0] = wlo + 3*NM;
        ga.C[0] = out;
        gemm_tc6<<<dim3(8,32,1), 256, g6_smem>>>(ga, NEC, NEC);
    }
}

// round 11
// speedup vs baseline: 1.0818x; 1.0818x over previous
#include <cuda_runtime.h>
#include <cuda_fp16.h>
#include <math.h>
#include <stdint.h>

// Problem constants
#define BATCH 4
#define TSEQ  1024
#define NEC   1024
#define NH    16
#define HSZ   64
#define MT    (BATCH*TSEQ)      // 4096 rows
#define EPSGN 0.00064f
#define NM    ((size_t)NEC*NEC) // 1M

// ---------------------------------------------------------------------------
// Scratch (device globals)
// ---------------------------------------------------------------------------
__device__ float    g_xx   [(size_t)MT*NEC];
__device__ float    g_mix  [(size_t)MT*NEC];
__device__ float    g_hmaa [(size_t)MT*128];
__device__ float    g_hgate[(size_t)MT*128];
__device__ float    g_hdec [(size_t)MT*64];
__device__ float    g_haaa [(size_t)MT*16];
__device__ float    g_hma  [(size_t)MT*16];
__device__ float    g_hkkk [(size_t)MT*16];
__device__ float    g_hmk  [(size_t)MT*16];
__device__ float    g_xm   [4][(size_t)MT*NEC];  // g1 fp32; g0/2/3 packed half2
__device__ __half   g_whalf[3*NM];               // Wr,Wk,Wv plain fp16
__device__ uint32_t g_wopk [NM];                 // Wo packed (hi,lo)
__device__ uint32_t g_zpk  [(size_t)MT*NEC];
__device__ float    g_r    [(size_t)MT*NEC];
__device__ float    g_gg   [(size_t)MT*NEC];
__device__ float    g_k    [(size_t)MT*NEC];
__device__ float    g_v    [(size_t)MT*NEC];
__device__ float    g_w    [(size_t)MT*NEC];
__device__ float    g_kk   [(size_t)MT*NEC];
__device__ float    g_a    [(size_t)MT*NEC];
__device__ float    g_ma   [(size_t)MT*NEC];
__device__ float    g_mk   [(size_t)MT*NEC];
__device__ float    g_b    [(size_t)MT*NEC];
__device__ float    g_y    [(size_t)MT*NEC];

enum { EPI_NONE=0, EPI_W=3, EPI_ADD=4, EPI_SIG=5 };

// ---------------------------------------------------------------------------
// fp16 split helpers
// ---------------------------------------------------------------------------
__device__ __forceinline__ uint32_t packf(float v){
    __half hi = __float2half_rn(v);
    __half lo = __float2half_rn(v - __half2float(hi));
    __half2 h2 = __halves2half2(hi, lo);
    return *reinterpret_cast<uint32_t*>(&h2);
}
__device__ __forceinline__ float unpackf(uint32_t u){
    __half2 h = *reinterpret_cast<__half2*>(&u);
    return __low2float(h) + __high2float(h);
}
__device__ __forceinline__ void mma_f16(float* c, const uint32_t* a, const uint32_t* b){
    asm volatile("mma.sync.aligned.m16n8k16.row.col.f32.f16.f16.f32 "
        "{%0,%1,%2,%3},{%4,%5,%6,%7},{%8,%9},{%0,%1,%2,%3};\n"
        : "+f"(c[0]), "+f"(c[1]), "+f"(c[2]), "+f"(c[3])
        : "r"(a[0]), "r"(a[1]), "r"(a[2]), "r"(a[3]), "r"(b[0]), "r"(b[1]));
}
__device__ __forceinline__ void cpa16(uint32_t dst, const void* src){
    asm volatile("cp.async.cg.shared.global [%0],[%1],16;\n"::"r"(dst),"l"(src));
}
__device__ __forceinline__ void cpa4(uint32_t dst, const void* src){
    asm volatile("cp.async.ca.shared.global [%0],[%1],4;\n"::"r"(dst),"l"(src));
}
#define CP_COMMIT() asm volatile("cp.async.commit_group;\n")
#define CP_WAIT0()  asm volatile("cp.async.wait_group 0;\n")
#define CP_WAIT1()  asm volatile("cp.async.wait_group 1;\n")

// ---------------------------------------------------------------------------
// Token shift
// ---------------------------------------------------------------------------
__global__ void shift_kernel(const float* __restrict__ x,
                             const float* __restrict__ tmaax,
                             float* __restrict__ xx,
                             float* __restrict__ mix)
{
    size_t i = (size_t)blockIdx.x * blockDim.x + threadIdx.x;
    if (i >= (size_t)MT * NEC) return;
    int c = (int)(i % NEC);
    size_t row = i / NEC;
    int t = (int)(row % TSEQ);
    float xv = x[i];
    float xp = (t > 0) ? x[i - NEC] : 0.f;
    float d = xp - xv;
    xx[i]  = d;
    mix[i] = fmaf(d, tmaax[c], xv);
}

// ---------------------------------------------------------------------------
// Weight pack: Wr,Wk,Wv -> plain fp16; Wo -> packed (hi,lo)
// ---------------------------------------------------------------------------
__global__ void wpack_kernel(const float* __restrict__ Wr, const float* __restrict__ Wk,
                             const float* __restrict__ Wv, const float* __restrict__ Wo,
                             __half* __restrict__ whalf, uint32_t* __restrict__ wopk)
{
    size_t i = (size_t)blockIdx.x * blockDim.x + threadIdx.x;
    if (i >= 4*NM) return;
    int seg = (int)(i >> 20);
    size_t off = i & (NM - 1);
    if (seg < 3) {
        const float* src = (seg==0) ? Wr : (seg==1) ? Wk : Wv;
        whalf[i] = __float2half_rn(src[off]);
    } else {
        wopk[off] = packf(Wo[off]);
    }
}

// ---------------------------------------------------------------------------
// 2-product NT GEMM: C = (Ah+Al) * Bh^T.  A packed (hi,lo) words, B plain fp16.
// Exact activations, fp16 weights (error ~2^-11 relative, random-walks to ~2e-4).
// Tile 128x128xBK32, 256 threads, cp.async double-buffered, 2 CTA/SM.
// ---------------------------------------------------------------------------
#define G5_LDSW 36                 // A words per smem row (32+4 pad)
#define G5_AW   (128*G5_LDSW)      // 4608 words
#define G5_LDHB 40                 // B halves per smem row (32+8 pad)
#define G5_BW   (128*G5_LDHB/2)    // 2560 words
#define G5_STG  (G5_AW + G5_BW)    // 7168 words per stage

struct G5Args { const uint32_t* A[3]; const __half* B[3]; float* C[3]; };

__global__ __launch_bounds__(256, 2)
void gemm_tc5(G5Args args, int N, int K)
{
    extern __shared__ uint32_t sm5[];
    const int z = blockIdx.z;
    const uint32_t* Apk = args.A[z];
    const __half* Bhp = args.B[z];
    float* C = args.C[z];
    const int tid = threadIdx.x;
    const int bm0 = blockIdx.y*128, bn0 = blockIdx.x*128;
    const int warp = tid>>5, lane = tid&31, grp = lane>>2, q = lane&3;
    const int wm = (warp&1)*64, wn = (warp>>1)*32;
    const uint32_t sbase = (uint32_t)__cvta_generic_to_shared(sm5);

    float acc[4][4][4];
    #pragma unroll
    for (int mi=0;mi<4;mi++)
        #pragma unroll
        for (int ni=0;ni<4;ni++)
            #pragma unroll
            for (int e=0;e<4;e++) acc[mi][ni][e]=0.f;

    // A loader: 4 x 16B per thread per stage (1024 chunks)
    const uint32_t* asrc[4]; uint32_t adst[4];
    #pragma unroll
    for (int l = 0; l < 4; l++) {
        int idx = tid + l*256;
        int r = idx >> 3, c4 = idx & 7;
        asrc[l] = Apk + (size_t)(bm0+r)*K + c4*4;
        adst[l] = sbase + (uint32_t)(r*G5_LDSW + c4*4)*4;
    }
    // B loader: 2 x 16B per thread per stage (512 chunks; 4 per row)
    const __half* bsrc[2]; uint32_t bdst[2];
    #pragma unroll
    for (int l = 0; l < 2; l++) {
        int idx = tid + l*256;
        int r = idx >> 2, c4 = idx & 3;
        bsrc[l] = Bhp + (size_t)(bn0+r)*K + c4*8;
        bdst[l] = sbase + G5_AW*4 + (uint32_t)(r*G5_LDHB + c4*8)*2;
    }

#define G5_LOAD(st, kb) do {                                   \
        uint32_t _o = (st)*G5_STG*4;                           \
        _Pragma("unroll")                                      \
        for (int l = 0; l < 4; l++)                            \
            cpa16(adst[l] + _o, asrc[l] + (kb));               \
        _Pragma("unroll")                                      \
        for (int l = 0; l < 2; l++)                            \
            cpa16(bdst[l] + _o, bsrc[l] + (kb));               \
    } while(0)

    G5_LOAD(0, 0); CP_COMMIT();

    int p = 0;
    for (int kb = 0; kb < K; kb += 32) {
        CP_WAIT0();
        __syncthreads();
        if (kb + 32 < K) { G5_LOAD(p^1, kb+32); CP_COMMIT(); }

        const uint32_t* SA = sm5 + p*G5_STG;
        const __half*   SB = (const __half*)(sm5 + p*G5_STG + G5_AW);

        #pragma unroll
        for (int kc = 0; kc < 32; kc += 16) {
            uint32_t ah[4][4], al[4][4], bh[4][2];
            #pragma unroll
            for (int mi = 0; mi < 4; mi++) {
                int r0 = (wm + mi*16 + grp)*G5_LDSW + kc + 2*q;
                uint2 w0 = *(const uint2*)&SA[r0];
                uint2 w1 = *(const uint2*)&SA[r0 + 8*G5_LDSW];
                uint2 w2 = *(const uint2*)&SA[r0 + 8];
                uint2 w3 = *(const uint2*)&SA[r0 + 8*G5_LDSW + 8];
                ah[mi][0]=__byte_perm(w0.x,w0.y,0x5410); al[mi][0]=__byte_perm(w0.x,w0.y,0x7632);
                ah[mi][1]=__byte_perm(w1.x,w1.y,0x5410); al[mi][1]=__byte_perm(w1.x,w1.y,0x7632);
                ah[mi][2]=__byte_perm(w2.x,w2.y,0x5410); al[mi][2]=__byte_perm(w2.x,w2.y,0x7632);
                ah[mi][3]=__byte_perm(w3.x,w3.y,0x5410); al[mi][3]=__byte_perm(w3.x,w3.y,0x7632);
            }
            #pragma unroll
            for (int ni = 0; ni < 4; ni++) {
                int c0 = (wn + ni*8 + grp)*G5_LDHB + kc + 2*q;
                bh[ni][0] = *(const uint32_t*)&SB[c0];
                bh[ni][1] = *(const uint32_t*)&SB[c0 + 8];
            }
            #pragma unroll
            for (int mi = 0; mi < 4; mi++)
                #pragma unroll
                for (int ni = 0; ni < 4; ni++) {
                    mma_f16(acc[mi][ni], ah[mi], bh[ni]);
                    mma_f16(acc[mi][ni], al[mi], bh[ni]);
                }
        }
        __syncthreads();
        p ^= 1;
    }

    #pragma unroll
    for (int mi = 0; mi < 4; mi++) {
        int row0 = bm0 + wm + mi*16 + grp;
        #pragma unroll
        for (int ni = 0; ni < 4; ni++) {
            int col = bn0 + wn + ni*8 + 2*q;
            *(float2*)&C[(size_t)row0*N + col]     = make_float2(acc[mi][ni][0], acc[mi][ni][1]);
            *(float2*)&C[(size_t)(row0+8)*N + col] = make_float2(acc[mi][ni][2], acc[mi][ni][3]);
        }
    }
#undef G5_LOAD
}

// ---------------------------------------------------------------------------
// 3-product NT GEMM (Wo only): both operands packed (hi,lo) words.
// Same as the proven R8 kernel.
// ---------------------------------------------------------------------------
#define G4_LDS 36
#define G4_STG 9216

__global__ __launch_bounds__(256, 2)
void gemm_tc4(const uint32_t* __restrict__ Apk,
              const uint32_t* __restrict__ Bpk,
              float* __restrict__ C, int N, int K)
{
    extern __shared__ uint32_t sm4[];
    const int tid = threadIdx.x;
    const int bm0 = blockIdx.y*128, bn0 = blockIdx.x*128;
    const int warp = tid>>5, lane = tid&31, grp = lane>>2, q = lane&3;
    const int wm = (warp&1)*64, wn = (warp>>1)*32;
    const uint32_t sbase = (uint32_t)__cvta_generic_to_shared(sm4);

    float acc[4][4][4];
    #pragma unroll
    for (int mi=0;mi<4;mi++)
        #pragma unroll
        for (int ni=0;ni<4;ni++)
            #pragma unroll
            for (int e=0;e<4;e++) acc[mi][ni][e]=0.f;

    const uint32_t* asrc[4]; const uint32_t* bsrc[4];
    uint32_t adst[4], bdst[4];
    #pragma unroll
    for (int l = 0; l < 4; l++) {
        int idx = tid + l*256;
        int r = idx >> 3, c4 = idx & 7;
        asrc[l] = Apk + (size_t)(bm0+r)*K + c4*4;
        bsrc[l] = Bpk + (size_t)(bn0+r)*K + c4*4;
        adst[l] = sbase + (uint32_t)(r*G4_LDS + c4*4)*4;
        bdst[l] = sbase + (uint32_t)(4608 + r*G4_LDS + c4*4)*4;
    }

#define G4_LOAD(st, kb) do {                                   \
        uint32_t _o = (st)*G4_STG*4;                           \
        _Pragma("unroll")                                      \
        for (int l = 0; l < 4; l++) {                          \
            cpa16(adst[l] + _o, asrc[l] + (kb));               \
            cpa16(bdst[l] + _o, bsrc[l] + (kb));               \
        }                                                      \
    } while(0)

    G4_LOAD(0, 0); CP_COMMIT();

    int p = 0;
    for (int kb = 0; kb < K; kb += 32) {
        CP_WAIT0();
        __syncthreads();
        if (kb + 32 < K) { G4_LOAD(p^1, kb+32); CP_COMMIT(); }

        const uint32_t* S = sm4 + p*G4_STG;

        #pragma unroll
        for (int kc = 0; kc < 32; kc += 16) {
            uint32_t ah[4][4], al[4][4], bh[4][2], bl[4][2];
            #pragma unroll
            for (int mi = 0; mi < 4; mi++) {
                int r0 = (wm + mi*16 + grp)*G4_LDS + kc + 2*q;
                uint2 w0 = *(const uint2*)&S[r0];
                uint2 w1 = *(const uint2*)&S[r0 + 8*G4_LDS];
                uint2 w2 = *(const uint2*)&S[r0 + 8];
                uint2 w3 = *(const uint2*)&S[r0 + 8*G4_LDS + 8];
                ah[mi][0]=__byte_perm(w0.x,w0.y,0x5410); al[mi][0]=__byte_perm(w0.x,w0.y,0x7632);
                ah[mi][1]=__byte_perm(w1.x,w1.y,0x5410); al[mi][1]=__byte_perm(w1.x,w1.y,0x7632);
                ah[mi][2]=__byte_perm(w2.x,w2.y,0x5410); al[mi][2]=__byte_perm(w2.x,w2.y,0x7632);
                ah[mi][3]=__byte_perm(w3.x,w3.y,0x5410); al[mi][3]=__byte_perm(w3.x,w3.y,0x7632);
            }
            #pragma unroll
            for (int ni = 0; ni < 4; ni++) {
                int c0 = 4608 + (wn + ni*8 + grp)*G4_LDS + kc + 2*q;
                uint2 u0 = *(const uint2*)&S[c0];
                uint2 u1 = *(const uint2*)&S[c0 + 8];
                bh[ni][0]=__byte_perm(u0.x,u0.y,0x5410); bl[ni][0]=__byte_perm(u0.x,u0.y,0x7632);
                bh[ni][1]=__byte_perm(u1.x,u1.y,0x5410); bl[ni][1]=__byte_perm(u1.x,u1.y,0x7632);
            }
            #pragma unroll
            for (int mi = 0; mi < 4; mi++)
                #pragma unroll
                for (int ni = 0; ni < 4; ni++) {
                    mma_f16(acc[mi][ni], ah[mi], bh[ni]);
                    mma_f16(acc[mi][ni], ah[mi], bl[ni]);
                    mma_f16(acc[mi][ni], al[mi], bh[ni]);
                }
        }
        __syncthreads();
        p ^= 1;
    }

    #pragma unroll
    for (int mi = 0; mi < 4; mi++) {
        int row0 = bm0 + wm + mi*16 + grp;
        #pragma unroll
        for (int ni = 0; ni < 4; ni++) {
            int col = bn0 + wn + ni*8 + 2*q;
            *(float2*)&C[(size_t)row0*N + col]     = make_float2(acc[mi][ni][0], acc[mi][ni][1]);
            *(float2*)&C[(size_t)(row0+8)*N + col] = make_float2(acc[mi][ni][2], acc[mi][ni][3]);
        }
    }
#undef G4_LOAD
}

// ---------------------------------------------------------------------------
// Grouped NT LoRA-hidden kernel: C = act(A @ B_tile^T), K=1024.
// ---------------------------------------------------------------------------
struct NTTile { const float* B; float* C; int ldc; int nvalid; int tanhf; int asel; };
struct NTArgs { const void* Aptr[3]; int apk[3]; NTTile t[12]; };

__global__ __launch_bounds__(128)
void lora_nt_kernel(NTArgs args)
{
    constexpr int BK=32, K=NEC;
    __shared__ __align__(16) float As[BK][132];
    __shared__ __align__(16) float Bs[BK][36];
    NTTile tl = args.t[blockIdx.x];
    const int apk = args.apk[tl.asel];
    const int bm0 = blockIdx.y*128;
    const int tid = threadIdx.x;
    const int tx = tid & 7;
    const int ty = tid >> 3;

    float acc[8][4];
    #pragma unroll
    for (int i=0;i<8;i++)
        #pragma unroll
        for (int j=0;j<4;j++) acc[i][j]=0.f;

    for (int kb = 0; kb < K; kb += BK) {
        if (apk) {
            const uint32_t* A = (const uint32_t*)args.Aptr[tl.asel];
            #pragma unroll
            for (int l = 0; l < 8; l++) {
                int idx = tid + l*128;
                int r = idx >> 3, c = (idx & 7)*4;
                uint4 u = *(const uint4*)(A + (size_t)(bm0+r)*K + kb + c);
                As[c+0][r]=unpackf(u.x); As[c+1][r]=unpackf(u.y);
                As[c+2][r]=unpackf(u.z); As[c+3][r]=unpackf(u.w);
            }
        } else {
            const float* A = (const float*)args.Aptr[tl.asel];
            #pragma unroll
            for (int l = 0; l < 8; l++) {
                int idx = tid + l*128;
                int r = idx >> 3, c = (idx & 7)*4;
                float4 val = *(const float4*)(A + (size_t)(bm0+r)*K + kb + c);
                As[c+0][r]=val.x; As[c+1][r]=val.y; As[c+2][r]=val.z; As[c+3][r]=val.w;
            }
        }
        #pragma unroll
        for (int l = 0; l < 2; l++) {
            int idx = tid + l*128;
            int r = idx >> 3, c = (idx & 7)*4;
            float4 val = (r < tl.nvalid) ?
                *(const float4*)(tl.B + (size_t)r*K + kb + c) : make_float4(0,0,0,0);
            Bs[c+0][r]=val.x; Bs[c+1][r]=val.y; Bs[c+2][r]=val.z; Bs[c+3][r]=val.w;
        }
        __syncthreads();
        #pragma unroll
        for (int kk = 0; kk < BK; kk++) {
            float4 m0 = *(const float4*)&As[kk][ty*8];
            float4 m1 = *(const float4*)&As[kk][ty*8+4];
            float4 rn = *(const float4*)&Bs[kk][tx*4];
            float rm[8] = {m0.x,m0.y,m0.z,m0.w,m1.x,m1.y,m1.z,m1.w};
            #pragma unroll
            for (int i=0;i<8;i++) {
                acc[i][0] = fmaf(rm[i], rn.x, acc[i][0]);
                acc[i][1] = fmaf(rm[i], rn.y, acc[i][1]);
                acc[i][2] = fmaf(rm[i], rn.z, acc[i][2]);
                acc[i][3] = fmaf(rm[i], rn.w, acc[i][3]);
            }
        }
        __syncthreads();
    }
    #pragma unroll
    for (int i=0;i<8;i++) {
        int row = bm0 + ty*8 + i;
        #pragma unroll
        for (int j=0;j<4;j++) {
            int col = tx*4 + j;
            if (col < tl.nvalid) {
                float vv = acc[i][j];
                if (tl.tanhf) vv = tanhf(vv);
                tl.C[(size_t)row*tl.ldc + col] = vv;
            }
        }
    }
}

// ---------------------------------------------------------------------------
// Fused xm kernel: per group g, val = x + xx*(Ag @ Bg + time_maa[g]).
// g==1 -> fp32 out (xwa); else packed (hi,lo) fp16 out.
// ---------------------------------------------------------------------------
__global__ __launch_bounds__(256)
void xm_kernel(const float* __restrict__ hmaa,
               const float* __restrict__ maa_w2,
               const float* __restrict__ x,
               const float* __restrict__ xx,
               const float* __restrict__ time_maa,
               float* __restrict__ xmbase)
{
    constexpr int BM=128, BN=128, BK=32;
    __shared__ float As[BK][BM+1];
    __shared__ float Bs[BK][BN];
    const int g = blockIdx.z;
    const float* A = hmaa + g*32;
    const float* B = maa_w2 + (size_t)g*32*NEC;
    float* C = xmbase + (size_t)g*MT*NEC;
    const float* tm = time_maa + g*NEC;
    const int bm0 = blockIdx.y*BM, bn0 = blockIdx.x*BN;
    const int tid = threadIdx.x;
    const int tx = tid & 15, ty = tid >> 4;

    float acc[8][8];
    #pragma unroll
    for (int i=0;i<8;i++)
        #pragma unroll
        for (int j=0;j<8;j++) acc[i][j]=0.f;

    #pragma unroll
    for (int l = 0; l < 4; l++) {
        int idx = tid + l*256;
        int r = idx >> 3, c = (idx & 7)*4;
        float4 val = *(const float4*)(A + (size_t)(bm0+r)*128 + c);
        As[c+0][r]=val.x; As[c+1][r]=val.y; As[c+2][r]=val.z; As[c+3][r]=val.w;
    }
    #pragma unroll
    for (int l = 0; l < 4; l++) {
        int idx = tid + l*256;
        int r = idx >> 5, c = (idx & 31)*4;
        *(float4*)&Bs[r][c] = *(const float4*)(B + (size_t)r*NEC + bn0 + c);
    }
    __syncthreads();
    #pragma unroll
    for (int kk = 0; kk < BK; kk++) {
        float rm[8], rn[8];
        #pragma unroll
        for (int i=0;i<8;i++) rm[i] = As[kk][ty*8+i];
        #pragma unroll
        for (int j=0;j<8;j++) rn[j] = Bs[kk][tx*8+j];
        #pragma unroll
        for (int i=0;i<8;i++)
            #pragma unroll
            for (int j=0;j<8;j++) acc[i][j] = fmaf(rm[i], rn[j], acc[i][j]);
    }
    #pragma unroll
    for (int i=0;i<8;i++) {
        int row = bm0 + ty*8 + i;
        #pragma unroll
        for (int j=0;j<8;j+=2) {
            int col = bn0 + tx*8 + j;
            size_t idx = (size_t)row*NEC + col;
            float2 xv = *(const float2*)&x[idx];
            float2 dv = *(const float2*)&xx[idx];
            float v0 = fmaf(dv.x, acc[i][j]   + tm[col],   xv.x);
            float v1 = fmaf(dv.y, acc[i][j+1] + tm[col+1], xv.y);
            if (g == 1) {
                *(float2*)&C[idx] = make_float2(v0, v1);
            } else {
                uint2 pk = make_uint2(packf(v0), packf(v1));
                *(uint2*)&((uint32_t*)C)[idx] = pk;
            }
        }
    }
}

// ---------------------------------------------------------------------------
// Grouped second-stage NN kernel
// ---------------------------------------------------------------------------
struct NNGroup { const float* A; const float* B; float* C; int K; int epi;
                 const float* e0; const float* e2; };
struct NNArgs { NNGroup g[6]; };

__global__ __launch_bounds__(256)
void lora_nn_kernel(NNArgs args)
{
    constexpr int BM=128, BN=128, BK=16;
    __shared__ float As[BK][BM+1];
    __shared__ float Bs[BK][BN];
    NNGroup grp = args.g[blockIdx.z];
    const int K = grp.K;
    const int bm0 = blockIdx.y*BM, bn0 = blockIdx.x*BN;
    const int tid = threadIdx.x;
    const int tx = tid & 15, ty = tid >> 4;

    float acc[8][8];
    #pragma unroll
    for (int i=0;i<8;i++)
        #pragma unroll
        for (int j=0;j<8;j++) acc[i][j]=0.f;

    for (int kb = 0; kb < K; kb += BK) {
        #pragma unroll
        for (int l = 0; l < 2; l++) {
            int idx = tid + l*256;
            int r = idx >> 2, c = (idx & 3)*4;
            float4 val = *(const float4*)(grp.A + (size_t)(bm0+r)*K + kb + c);
            As[c+0][r]=val.x; As[c+1][r]=val.y; As[c+2][r]=val.z; As[c+3][r]=val.w;
        }
        #pragma unroll
        for (int l = 0; l < 2; l++) {
            int idx = tid + l*256;
            int r = idx >> 5, c = (idx & 31)*4;
            *(float4*)&Bs[r][c] = *(const float4*)(grp.B + (size_t)(kb+r)*NEC + bn0 + c);
        }
        __syncthreads();
        #pragma unroll
        for (int kk = 0; kk < BK; kk++) {
            float rm[8], rn[8];
            #pragma unroll
            for (int i=0;i<8;i++) rm[i] = As[kk][ty*8+i];
            #pragma unroll
            for (int j=0;j<8;j++) rn[j] = Bs[kk][tx*8+j];
            #pragma unroll
            for (int i=0;i<8;i++)
                #pragma unroll
                for (int j=0;j<8;j++) acc[i][j] = fmaf(rm[i], rn[j], acc[i][j]);
        }
        __syncthreads();
    }
    #pragma unroll
    for (int i=0;i<8;i++) {
        int row = bm0 + ty*8 + i;
        #pragma unroll
        for (int j=0;j<8;j++) {
            int col = bn0 + tx*8 + j;
            size_t idx = (size_t)row*NEC + col;
            float vv = acc[i][j], outv;
            switch (grp.epi) {
                case EPI_W: {
                    float tt = -(grp.e2[col] + vv);
                    float sp = (tt > 15.f) ? tt : log1pf(expf(tt));
                    outv = -sp - 0.5f;
                } break;
                case EPI_ADD: outv = grp.e0[idx] + vv; break;
                case EPI_SIG: {
                    float u = grp.e2[col] + vv;
                    outv = 1.f / (1.f + expf(-u));
                } break;
                default: outv = vv;
            }
            grp.C[idx] = outv;
        }
    }
}

// ---------------------------------------------------------------------------
// warp sum
// ---------------------------------------------------------------------------
__device__ __forceinline__ float warp_sum(float v)
{
    #pragma unroll
    for (int o = 16; o > 0; o >>= 1) v += __shfl_xor_sync(0xffffffffu, v, o);
    return v;
}

// ---------------------------------------------------------------------------
// prep
// ---------------------------------------------------------------------------
__global__ void prep_kernel(float* kptr, float* kkptr,
                            const float* __restrict__ a,
                            const float* __restrict__ ma,
                            const float* __restrict__ mk,
                            float* wptr,
                            float* __restrict__ b)
{
    int m = blockIdx.x;
    int h = threadIdx.x >> 5;
    int lane = threadIdx.x & 31;
    size_t base = (size_t)m*NEC + h*HSZ;
    size_t i0 = base + lane, i1 = i0 + 32;

    float kk0 = kkptr[i0], kk1 = kkptr[i1];
    float ss = warp_sum(kk0*kk0 + kk1*kk1);
    float inv = 1.f / fmaxf(sqrtf(ss), 1e-12f);
    float n0 = kk0*inv, n1 = kk1*inv;
    kkptr[i0] = n0; kkptr[i1] = n1;

    float a0 = a[i0], a1 = a[i1];
    b[i0] = -n0*a0; b[i1] = -n1*a1;

    float ma0 = ma[i0], ma1 = ma[i1];
    float k0v = kptr[i0], k1v = kptr[i1];
    float w0 = wptr[i0], w1 = wptr[i1];
    float mk0 = mk[i0], mk1 = mk[i1];
    kptr[i0] = k0v * (ma0 + a0*(1.f - ma0)) * expf(w0*mk0);
    kptr[i1] = k1v * (ma1 + a1*(1.f - ma1)) * expf(w1*mk1);
    wptr[i0] = expf(-expf(w0));
    wptr[i1] = expf(-expf(w1));
}

// ---------------------------------------------------------------------------
// RWKV7 recurrence v4: 2 blocks per head; 32 rows x 8-way column split;
// 3-stage cp.async ring.
// ---------------------------------------------------------------------------
__global__ __launch_bounds__(256)
void wkv7_kernel(const float* __restrict__ q, const float* __restrict__ w,
                 const float* __restrict__ k, const float* __restrict__ v,
                 const float* __restrict__ a, const float* __restrict__ b,
                 float* __restrict__ y)
{
    const int blk = blockIdx.x;            // 0..127
    const int bh = blk >> 1, rh = blk & 1;
    const int batch = bh >> 4, h = bh & 15;
    const int tid = threadIdx.x;
    const int il = tid >> 3, qd = tid & 7;

    __shared__ __align__(16) float buf[3][352];

    float s[8];
    #pragma unroll
    for (int j = 0; j < 8; j++) s[j] = 0.f;

    const size_t base = (size_t)batch * TSEQ * NEC + (size_t)h * HSZ;

    const float* table[4] = {q, w, k, a};
    const float* s0 = table[tid>>6] + base + (tid & 63);
    const float* s1 = nullptr;
    if (tid < 64)       s1 = b + base + tid;
    else if (tid < 96)  s1 = v + base + rh*32 + (tid - 64);
    const uint32_t sb = (uint32_t)__cvta_generic_to_shared(buf);
    const uint32_t d0 = sb + (uint32_t)tid*4;
    const uint32_t d1 = sb + (uint32_t)(256 + tid)*4;
    const uint32_t STRB = 352*4;

    cpa4(d0, s0);
    if (tid < 96) cpa4(d1, s1);
    CP_COMMIT();
    cpa4(d0 + STRB, s0 + NEC);
    if (tid < 96) cpa4(d1 + STRB, s1 + NEC);
    CP_COMMIT();

    const size_t ybase = base + (size_t)rh*32 + il;

    int p = 0;
    for (int t = 0; t < TSEQ; t++) {
        CP_WAIT1();
        __syncthreads();

        {
            int st = p + 2; if (st >= 3) st -= 3;
            if (t + 2 < TSEQ) {
                size_t o = (size_t)(t+2)*NEC;
                cpa4(d0 + (uint32_t)st*STRB, s0 + o);
                if (tid < 96) cpa4(d1 + (uint32_t)st*STRB, s1 + o);
            }
            CP_COMMIT();
        }

        const float* bb = buf[p];
        const int co = qd*8;
        const float4* q4 = (const float4*)(bb +   0 + co);
        const float4* w4 = (const float4*)(bb +  64 + co);
        const float4* k4 = (const float4*)(bb + 128 + co);
        const float4* a4 = (const float4*)(bb + 192 + co);
        const float4* b4 = (const float4*)(bb + 256 + co);
        float vi = bb[320 + il];

        float4 av0 = a4[0], av1 = a4[1];
        float sa0 = fmaf(s[0], av0.x, s[4]*av1.x);
        float sa1 = fmaf(s[1], av0.y, s[5]*av1.y);
        float sa2 = fmaf(s[2], av0.z, s[6]*av1.z);
        float sa3 = fmaf(s[3], av0.w, s[7]*av1.w);
        float sa = (sa0+sa1) + (sa2+sa3);
        sa += __shfl_xor_sync(0xffffffffu, sa, 1);
        sa += __shfl_xor_sync(0xffffffffu, sa, 2);
        sa += __shfl_xor_sync(0xffffffffu, sa, 4);

        float4 wv0 = w4[0], wv1 = w4[1];
        float4 kv0 = k4[0], kv1 = k4[1];
        float4 bv0 = b4[0], bv1 = b4[1];
        float4 qv0 = q4[0], qv1 = q4[1];

        float t0 = fmaf(s[0], wv0.x, fmaf(sa, bv0.x, vi*kv0.x));
        float t1 = fmaf(s[1], wv0.y, fmaf(sa, bv0.y, vi*kv0.y));
        float t2 = fmaf(s[2], wv0.z, fmaf(sa, bv0.z, vi*kv0.z));
        float t3 = fmaf(s[3], wv0.w, fmaf(sa, bv0.w, vi*kv0.w));
        float t4 = fmaf(s[4], wv1.x, fmaf(sa, bv1.x, vi*kv1.x));
        float t5 = fmaf(s[5], wv1.y, fmaf(sa, bv1.y, vi*kv1.y));
        float t6 = fmaf(s[6], wv1.z, fmaf(sa, bv1.z, vi*kv1.z));
        float t7 = fmaf(s[7], wv1.w, fmaf(sa, bv1.w, vi*kv1.w));
        s[0]=t0; s[1]=t1; s[2]=t2; s[3]=t3; s[4]=t4; s[5]=t5; s[6]=t6; s[7]=t7;

        float y0 = fmaf(t0, qv0.x, t4*qv1.x);
        float y1 = fmaf(t1, qv0.y, t5*qv1.y);
        float y2 = fmaf(t2, qv0.z, t6*qv1.z);
        float y3 = fmaf(t3, qv0.w, t7*qv1.w);
        float yi = (y0+y1) + (y2+y3);
        yi += __shfl_xor_sync(0xffffffffu, yi, 1);
        yi += __shfl_xor_sync(0xffffffffu, yi, 2);
        yi += __shfl_xor_sync(0xffffffffu, yi, 4);
        if (qd == 0) y[ybase + (size_t)t*NEC] = yi;

        if (++p == 3) p = 0;
    }
}

// ---------------------------------------------------------------------------
// GroupNorm + bonus + gate -> packed z
// ---------------------------------------------------------------------------
__global__ void gn_kernel(const float* __restrict__ y,
                          const float* __restrict__ r,
                          const float* __restrict__ k,
                          const float* __restrict__ v,
                          const float* __restrict__ gg,
                          const float* __restrict__ ln_w,
                          const float* __restrict__ ln_b,
                          const float* __restrict__ faaaa,
                          uint32_t* __restrict__ zpk)
{
    int m = blockIdx.x;
    int h = threadIdx.x >> 5;
    int lane = threadIdx.x & 31;
    size_t base = (size_t)m*NEC + h*HSZ;
    int c0 = h*HSZ + lane, c1 = c0 + 32;
    size_t i0 = base + lane, i1 = i0 + 32;

    float y0 = y[i0], y1 = y[i1];
    float mu = warp_sum(y0 + y1) * (1.f/64.f);
    float d0 = y0 - mu, d1 = y1 - mu;
    float var = warp_sum(d0*d0 + d1*d1) * (1.f/64.f);
    float rstd = rsqrtf(var + EPSGN);
    float yn0 = d0*rstd*ln_w[c0] + ln_b[c0];
    float yn1 = d1*rstd*ln_w[c1] + ln_b[c1];

    float r0 = r[i0], r1 = r[i1];
    float k0v = k[i0], k1v = k[i1];
    float rk = warp_sum(r0*k0v*faaaa[c0] + r1*k1v*faaaa[c1]);

    float v0 = v[i0], v1 = v[i1];
    zpk[i0] = packf((yn0 + rk*v0) * gg[i0]);
    zpk[i1] = packf((yn1 + rk*v1) * gg[i1]);
}

// ---------------------------------------------------------------------------
// Host side
// ---------------------------------------------------------------------------
extern "C" void kernel_launch(void* const* d_in, const int* in_sizes, int n_in,
                              void* d_out, int out_size)
{
    const float* x          = (const float*)d_in[0];
    const float* time_maa_x = (const float*)d_in[1];
    const float* time_maa   = (const float*)d_in[2];
    const float* maa_w1     = (const float*)d_in[3];
    const float* maa_w2     = (const float*)d_in[4];
    const float* decay_w1   = (const float*)d_in[5];
    const float* decay_w2   = (const float*)d_in[6];
    const float* aaa_w1     = (const float*)d_in[7];
    const float* aaa_w2     = (const float*)d_in[8];
    const float* kkk_w1     = (const float*)d_in[9];
    const float* kkk_w2     = (const float*)d_in[10];
    const float* gate_w1    = (const float*)d_in[11];
    const float* gate_w2    = (const float*)d_in[12];
    const float* ma_w1      = (const float*)d_in[13];
    const float* ma_w2      = (const float*)d_in[14];
    const float* mk_w1      = (const float*)d_in[15];
    const float* mk_w2      = (const float*)d_in[16];
    const float* time_decay = (const float*)d_in[17];
    const float* time_faaaa = (const float*)d_in[18];
    const float* time_aaaaa = (const float*)d_in[19];
    const float* time_misc_a= (const float*)d_in[20];
    const float* time_misc_k= (const float*)d_in[21];
    const float* Wr         = (const float*)d_in[22];
    const float* Wk         = (const float*)d_in[23];
    const float* Wv         = (const float*)d_in[24];
    const float* Wo         = (const float*)d_in[25];
    const float* ln_w       = (const float*)d_in[26];
    const float* ln_b       = (const float*)d_in[27];
    float* out = (float*)d_out;

    float *xx,*mix,*hmaa,*hgate,*hdec,*haaa,*hma,*hkkk,*hmk,*xm;
    __half *whalf; uint32_t *wopk,*zpk;
    float *r,*gg,*k,*v,*w,*kk,*a,*ma,*mk,*b,*y;
    cudaGetSymbolAddress((void**)&xx,   g_xx);
    cudaGetSymbolAddress((void**)&mix,  g_mix);
    cudaGetSymbolAddress((void**)&hmaa, g_hmaa);
    cudaGetSymbolAddress((void**)&hgate,g_hgate);
    cudaGetSymbolAddress((void**)&hdec, g_hdec);
    cudaGetSymbolAddress((void**)&haaa, g_haaa);
    cudaGetSymbolAddress((void**)&hma,  g_hma);
    cudaGetSymbolAddress((void**)&hkkk, g_hkkk);
    cudaGetSymbolAddress((void**)&hmk,  g_hmk);
    cudaGetSymbolAddress((void**)&xm,   g_xm);
    cudaGetSymbolAddress((void**)&whalf,g_whalf);
    cudaGetSymbolAddress((void**)&wopk, g_wopk);
    cudaGetSymbolAddress((void**)&zpk,  g_zpk);
    cudaGetSymbolAddress((void**)&r,    g_r);
    cudaGetSymbolAddress((void**)&gg,   g_gg);
    cudaGetSymbolAddress((void**)&k,    g_k);
    cudaGetSymbolAddress((void**)&v,    g_v);
    cudaGetSymbolAddress((void**)&w,    g_w);
    cudaGetSymbolAddress((void**)&kk,   g_kk);
    cudaGetSymbolAddress((void**)&a,    g_a);
    cudaGetSymbolAddress((void**)&ma,   g_ma);
    cudaGetSymbolAddress((void**)&mk,   g_mk);
    cudaGetSymbolAddress((void**)&b,    g_b);
    cudaGetSymbolAddress((void**)&y,    g_y);

    const size_t S = (size_t)MT*NEC;
    const uint32_t* xrg_pk = (const uint32_t*)(xm + 0*S);
    const float*    xwa    = xm + 1*S;
    const uint32_t* xk_pk  = (const uint32_t*)(xm + 2*S);
    const uint32_t* xv_pk  = (const uint32_t*)(xm + 3*S);

    static bool attr_done = false;
    if (!attr_done) {
        cudaFuncSetAttribute(gemm_tc4, cudaFuncAttributeMaxDynamicSharedMemorySize,
                             2*G4_STG*4);
        cudaFuncSetAttribute(gemm_tc5, cudaFuncAttributeMaxDynamicSharedMemorySize,
                             2*G5_STG*4);
        attr_done = true;
    }
    const int g4_smem = 2*G4_STG*4;
    const int g5_smem = 2*G5_STG*4;

    // 1) token shift
    shift_kernel<<<(unsigned)((S + 255)/256), 256>>>(x, time_maa_x, xx, mix);

    // 2) weight pack: Wr/Wk/Wv fp16, Wo packed hi/lo
    wpack_kernel<<<(unsigned)((4*NM + 255)/256), 256>>>(Wr, Wk, Wv, Wo, whalf, wopk);

    // 3) maa hidden (4 tiles)
    {
        NTArgs na = {};
        na.Aptr[0] = mix; na.apk[0] = 0;
        for (int i = 0; i < 4; i++)
            na.t[i] = { maa_w1 + (size_t)i*32*NEC, hmaa + i*32, 128, 32, 1, 0 };
        lora_nt_kernel<<<dim3(4, MT/128), 128>>>(na);
    }

    // 4) xm fused (4 groups; packed for 0/2/3, fp32 for 1)
    xm_kernel<<<dim3(8, MT/128, 4), 256>>>(hmaa, maa_w2, x, xx, time_maa, xm);

    // 5) hidden group 2 (10 tiles)
    {
        NTArgs na = {};
        na.Aptr[0] = xrg_pk; na.apk[0] = 1;
        na.Aptr[1] = xwa;    na.apk[1] = 0;
        na.Aptr[2] = xk_pk;  na.apk[2] = 1;
        int ti = 0;
        for (int i = 0; i < 4; i++)
            na.t[ti++] = { gate_w1 + (size_t)i*32*NEC, hgate + i*32, 128, 32, 1, 0 };
        for (int i = 0; i < 2; i++)
            na.t[ti++] = { decay_w1 + (size_t)i*32*NEC, hdec + i*32, 64, 32, 1, 1 };
        na.t[ti++] = { aaa_w1, haaa, 16, 16, 0, 1 };
        na.t[ti++] = { ma_w1,  hma,  16, 16, 0, 1 };
        na.t[ti++] = { kkk_w1, hkkk, 16, 16, 1, 2 };
        na.t[ti++] = { mk_w1,  hmk,  16, 16, 0, 2 };
        lora_nt_kernel<<<dim3(10, MT/128), 128>>>(na);
    }

    // 6) big GEMMs r,k,v: 2-product (exact activations x fp16 weights), fused
    {
        G5Args ga = {};
        ga.A[0] = xrg_pk; ga.B[0] = whalf + 0*NM; ga.C[0] = r;
        ga.A[1] = xk_pk;  ga.B[1] = whalf + 1*NM; ga.C[1] = k;
        ga.A[2] = xv_pk;  ga.B[2] = whalf + 2*NM; ga.C[2] = v;
        gemm_tc5<<<dim3(8,32,3), 256, g5_smem>>>(ga, NEC, NEC);
    }

    // 7) second stage (6 groups)
    {
        NNArgs nn = {};
        nn.g[0] = { hgate, gate_w2,  gg, 128, EPI_NONE, nullptr, nullptr };
        nn.g[1] = { hdec,  decay_w2, w,   64, EPI_W,    nullptr, time_decay };
        nn.g[2] = { hkkk,  kkk_w2,   kk,  16, EPI_ADD,  k,       nullptr };
        nn.g[3] = { haaa,  aaa_w2,   a,   16, EPI_SIG,  nullptr, time_aaaaa };
        nn.g[4] = { hma,   ma_w2,    ma,  16, EPI_SIG,  nullptr, time_misc_a };
        nn.g[5] = { hmk,   mk_w2,    mk,  16, EPI_SIG,  nullptr, time_misc_k };
        lora_nn_kernel<<<dim3(8, MT/128, 6), 256>>>(nn);
    }

    // 8) prep
    prep_kernel<<<MT, 512>>>(k, kk, a, ma, mk, w, b);

    // 9) recurrence (2 blocks per head)
    wkv7_kernel<<<BATCH*NH*2, 256>>>(r, w, k, v, kk, b, y);

    // 10) groupnorm + bonus + gate -> packed z
    gn_kernel<<<MT, 512>>>(y, r, k, v, gg, ln_w, ln_b, time_faaaa, zpk);

    // 11) out = z @ Wo.T (3-product, full precision path)
    gemm_tc4<<<dim3(8,32), 256, g4_smem>>>(zpk, wopk, out, NEC, NEC);
}

// round 12
// speedup vs baseline: 1.1251x; 1.0400x over previous
#include <cuda_runtime.h>
#include <cuda_fp16.h>
#include <math.h>
#include <stdint.h>

// Problem constants
#define BATCH 4
#define TSEQ  1024
#define NEC   1024
#define NH    16
#define HSZ   64
#define MT    (BATCH*TSEQ)      // 4096 rows
#define EPSGN 0.00064f
#define NM    ((size_t)NEC*NEC) // 1M

// ---------------------------------------------------------------------------
// Scratch (device globals)
// ---------------------------------------------------------------------------
__device__ float    g_xx   [(size_t)MT*NEC];
__device__ float    g_mix  [(size_t)MT*NEC];
__device__ float    g_hmaa [(size_t)MT*128];
__device__ float    g_hgate[(size_t)MT*128];
__device__ float    g_hdec [(size_t)MT*64];
__device__ float    g_haaa [(size_t)MT*16];
__device__ float    g_hma  [(size_t)MT*16];
__device__ float    g_hkkk [(size_t)MT*16];
__device__ float    g_hmk  [(size_t)MT*16];
__device__ float    g_xm   [4][(size_t)MT*NEC];  // g1 fp32; g0/2/3 packed half2
__device__ __half   g_whalf[4*NM];               // Wr,Wk,Wv,Wo plain fp16
__device__ uint32_t g_zpk  [(size_t)MT*NEC];
__device__ float    g_r    [(size_t)MT*NEC];
__device__ float    g_gg   [(size_t)MT*NEC];
__device__ float    g_k    [(size_t)MT*NEC];
__device__ float    g_v    [(size_t)MT*NEC];
__device__ float    g_w    [(size_t)MT*NEC];
__device__ float    g_kk   [(size_t)MT*NEC];
__device__ float    g_a    [(size_t)MT*NEC];
__device__ float    g_ma   [(size_t)MT*NEC];
__device__ float    g_mk   [(size_t)MT*NEC];
__device__ float    g_b    [(size_t)MT*NEC];
__device__ float    g_y    [(size_t)MT*NEC];

enum { EPI_NONE=0, EPI_W=3, EPI_SIG=5 };

// ---------------------------------------------------------------------------
// fp16 split helpers
// ---------------------------------------------------------------------------
__device__ __forceinline__ uint32_t packf(float v){
    __half hi = __float2half_rn(v);
    __half lo = __float2half_rn(v - __half2float(hi));
    __half2 h2 = __halves2half2(hi, lo);
    return *reinterpret_cast<uint32_t*>(&h2);
}
__device__ __forceinline__ float unpackf(uint32_t u){
    __half2 h = *reinterpret_cast<__half2*>(&u);
    return __low2float(h) + __high2float(h);
}
__device__ __forceinline__ void mma_f16(float* c, const uint32_t* a, const uint32_t* b){
    asm volatile("mma.sync.aligned.m16n8k16.row.col.f32.f16.f16.f32 "
        "{%0,%1,%2,%3},{%4,%5,%6,%7},{%8,%9},{%0,%1,%2,%3};\n"
        : "+f"(c[0]), "+f"(c[1]), "+f"(c[2]), "+f"(c[3])
        : "r"(a[0]), "r"(a[1]), "r"(a[2]), "r"(a[3]), "r"(b[0]), "r"(b[1]));
}
__device__ __forceinline__ void cpa16(uint32_t dst, const void* src){
    asm volatile("cp.async.cg.shared.global [%0],[%1],16;\n"::"r"(dst),"l"(src));
}
__device__ __forceinline__ void cpa4(uint32_t dst, const void* src){
    asm volatile("cp.async.ca.shared.global [%0],[%1],4;\n"::"r"(dst),"l"(src));
}
#define CP_COMMIT() asm volatile("cp.async.commit_group;\n")
#define CP_WAIT0()  asm volatile("cp.async.wait_group 0;\n")
#define CP_WAIT1()  asm volatile("cp.async.wait_group 1;\n")

// ---------------------------------------------------------------------------
// Token shift (float4)
// ---------------------------------------------------------------------------
__global__ void shift_kernel(const float* __restrict__ x,
                             const float* __restrict__ tmaax,
                             float* __restrict__ xx,
                             float* __restrict__ mix)
{
    size_t i4 = (size_t)blockIdx.x * blockDim.x + threadIdx.x;
    if (i4 >= (size_t)MT * NEC / 4) return;
    size_t idx = i4 * 4;
    int c = (int)(idx % NEC);
    size_t row = idx / NEC;
    int t = (int)(row % TSEQ);
    float4 xv = *(const float4*)&x[idx];
    float4 xp = (t > 0) ? *(const float4*)&x[idx - NEC] : make_float4(0,0,0,0);
    float4 tm = *(const float4*)&tmaax[c];
    float4 d  = make_float4(xp.x-xv.x, xp.y-xv.y, xp.z-xv.z, xp.w-xv.w);
    *(float4*)&xx[idx] = d;
    float4 m;
    m.x = fmaf(d.x, tm.x, xv.x);
    m.y = fmaf(d.y, tm.y, xv.y);
    m.z = fmaf(d.z, tm.z, xv.z);
    m.w = fmaf(d.w, tm.w, xv.w);
    *(float4*)&mix[idx] = m;
}

// ---------------------------------------------------------------------------
// Weight pack: all four weights -> plain fp16 (half2 stores)
// ---------------------------------------------------------------------------
__global__ void wpack_kernel(const float* __restrict__ Wr, const float* __restrict__ Wk,
                             const float* __restrict__ Wv, const float* __restrict__ Wo,
                             __half* __restrict__ whalf)
{
    size_t i = (size_t)blockIdx.x * blockDim.x + threadIdx.x;   // 2 elems each
    if (i >= 2*NM) return;
    int seg = (int)(i >> 19);                // NM/2 = 2^19 per segment
    size_t off2 = (i & ((NM>>1) - 1)) * 2;
    const float* src = (seg==0) ? Wr : (seg==1) ? Wk : (seg==2) ? Wv : Wo;
    float2 v = *(const float2*)&src[off2];
    __half2 h = __halves2half2(__float2half_rn(v.x), __float2half_rn(v.y));
    *(__half2*)&whalf[(size_t)seg*NM + off2] = h;
}

// ---------------------------------------------------------------------------
// 2-product NT GEMM: C = (Ah+Al) * Bh^T.  A packed (hi,lo) words, B plain fp16.
// Tile 128x128xBK32, 256 threads, cp.async double-buffered, 2 CTA/SM.
// ---------------------------------------------------------------------------
#define G5_LDSW 36                 // A words per smem row (32+4 pad)
#define G5_AW   (128*G5_LDSW)      // 4608 words
#define G5_LDHB 40                 // B halves per smem row (32+8 pad)
#define G5_BW   (128*G5_LDHB/2)    // 2560 words
#define G5_STG  (G5_AW + G5_BW)    // 7168 words per stage

struct G5Args { const uint32_t* A[3]; const __half* B[3]; float* C[3]; };

__global__ __launch_bounds__(256, 2)
void gemm_tc5(G5Args args, int N, int K)
{
    extern __shared__ uint32_t sm5[];
    const int z = blockIdx.z;
    const uint32_t* Apk = args.A[z];
    const __half* Bhp = args.B[z];
    float* C = args.C[z];
    const int tid = threadIdx.x;
    const int bm0 = blockIdx.y*128, bn0 = blockIdx.x*128;
    const int warp = tid>>5, lane = tid&31, grp = lane>>2, q = lane&3;
    const int wm = (warp&1)*64, wn = (warp>>1)*32;
    const uint32_t sbase = (uint32_t)__cvta_generic_to_shared(sm5);

    float acc[4][4][4];
    #pragma unroll
    for (int mi=0;mi<4;mi++)
        #pragma unroll
        for (int ni=0;ni<4;ni++)
            #pragma unroll
            for (int e=0;e<4;e++) acc[mi][ni][e]=0.f;

    const uint32_t* asrc[4]; uint32_t adst[4];
    #pragma unroll
    for (int l = 0; l < 4; l++) {
        int idx = tid + l*256;
        int r = idx >> 3, c4 = idx & 7;
        asrc[l] = Apk + (size_t)(bm0+r)*K + c4*4;
        adst[l] = sbase + (uint32_t)(r*G5_LDSW + c4*4)*4;
    }
    const __half* bsrc[2]; uint32_t bdst[2];
    #pragma unroll
    for (int l = 0; l < 2; l++) {
        int idx = tid + l*256;
        int r = idx >> 2, c4 = idx & 3;
        bsrc[l] = Bhp + (size_t)(bn0+r)*K + c4*8;
        bdst[l] = sbase + G5_AW*4 + (uint32_t)(r*G5_LDHB + c4*8)*2;
    }

#define G5_LOAD(st, kb) do {                                   \
        uint32_t _o = (st)*G5_STG*4;                           \
        _Pragma("unroll")                                      \
        for (int l = 0; l < 4; l++)                            \
            cpa16(adst[l] + _o, asrc[l] + (kb));               \
        _Pragma("unroll")                                      \
        for (int l = 0; l < 2; l++)                            \
            cpa16(bdst[l] + _o, bsrc[l] + (kb));               \
    } while(0)

    G5_LOAD(0, 0); CP_COMMIT();

    int p = 0;
    for (int kb = 0; kb < K; kb += 32) {
        CP_WAIT0();
        __syncthreads();
        if (kb + 32 < K) { G5_LOAD(p^1, kb+32); CP_COMMIT(); }

        const uint32_t* SA = sm5 + p*G5_STG;
        const __half*   SB = (const __half*)(sm5 + p*G5_STG + G5_AW);

        #pragma unroll
        for (int kc = 0; kc < 32; kc += 16) {
            uint32_t ah[4][4], al[4][4], bh[4][2];
            #pragma unroll
            for (int mi = 0; mi < 4; mi++) {
                int r0 = (wm + mi*16 + grp)*G5_LDSW + kc + 2*q;
                uint2 w0 = *(const uint2*)&SA[r0];
                uint2 w1 = *(const uint2*)&SA[r0 + 8*G5_LDSW];
                uint2 w2 = *(const uint2*)&SA[r0 + 8];
                uint2 w3 = *(const uint2*)&SA[r0 + 8*G5_LDSW + 8];
                ah[mi][0]=__byte_perm(w0.x,w0.y,0x5410); al[mi][0]=__byte_perm(w0.x,w0.y,0x7632);
                ah[mi][1]=__byte_perm(w1.x,w1.y,0x5410); al[mi][1]=__byte_perm(w1.x,w1.y,0x7632);
                ah[mi][2]=__byte_perm(w2.x,w2.y,0x5410); al[mi][2]=__byte_perm(w2.x,w2.y,0x7632);
                ah[mi][3]=__byte_perm(w3.x,w3.y,0x5410); al[mi][3]=__byte_perm(w3.x,w3.y,0x7632);
            }
            #pragma unroll
            for (int ni = 0; ni < 4; ni++) {
                int c0 = (wn + ni*8 + grp)*G5_LDHB + kc + 2*q;
                bh[ni][0] = *(const uint32_t*)&SB[c0];
                bh[ni][1] = *(const uint32_t*)&SB[c0 + 8];
            }
            #pragma unroll
            for (int mi = 0; mi < 4; mi++)
                #pragma unroll
                for (int ni = 0; ni < 4; ni++) {
                    mma_f16(acc[mi][ni], ah[mi], bh[ni]);
                    mma_f16(acc[mi][ni], al[mi], bh[ni]);
                }
        }
        __syncthreads();
        p ^= 1;
    }

    #pragma unroll
    for (int mi = 0; mi < 4; mi++) {
        int row0 = bm0 + wm + mi*16 + grp;
        #pragma unroll
        for (int ni = 0; ni < 4; ni++) {
            int col = bn0 + wn + ni*8 + 2*q;
            *(float2*)&C[(size_t)row0*N + col]     = make_float2(acc[mi][ni][0], acc[mi][ni][1]);
            *(float2*)&C[(size_t)(row0+8)*N + col] = make_float2(acc[mi][ni][2], acc[mi][ni][3]);
        }
    }
#undef G5_LOAD
}

// ---------------------------------------------------------------------------
// Grouped NT LoRA-hidden kernel: C = act(A @ B_tile^T), K=1024.
// ---------------------------------------------------------------------------
struct NTTile { const float* B; float* C; int ldc; int nvalid; int tanhf; int asel; };
struct NTArgs { const void* Aptr[3]; int apk[3]; NTTile t[12]; };

__global__ __launch_bounds__(128)
void lora_nt_kernel(NTArgs args)
{
    constexpr int BK=32, K=NEC;
    __shared__ __align__(16) float As[BK][132];
    __shared__ __align__(16) float Bs[BK][36];
    NTTile tl = args.t[blockIdx.x];
    const int apk = args.apk[tl.asel];
    const int bm0 = blockIdx.y*128;
    const int tid = threadIdx.x;
    const int tx = tid & 7;
    const int ty = tid >> 3;

    float acc[8][4];
    #pragma unroll
    for (int i=0;i<8;i++)
        #pragma unroll
        for (int j=0;j<4;j++) acc[i][j]=0.f;

    for (int kb = 0; kb < K; kb += BK) {
        if (apk) {
            const uint32_t* A = (const uint32_t*)args.Aptr[tl.asel];
            #pragma unroll
            for (int l = 0; l < 8; l++) {
                int idx = tid + l*128;
                int r = idx >> 3, c = (idx & 7)*4;
                uint4 u = *(const uint4*)(A + (size_t)(bm0+r)*K + kb + c);
                As[c+0][r]=unpackf(u.x); As[c+1][r]=unpackf(u.y);
                As[c+2][r]=unpackf(u.z); As[c+3][r]=unpackf(u.w);
            }
        } else {
            const float* A = (const float*)args.Aptr[tl.asel];
            #pragma unroll
            for (int l = 0; l < 8; l++) {
                int idx = tid + l*128;
                int r = idx >> 3, c = (idx & 7)*4;
                float4 val = *(const float4*)(A + (size_t)(bm0+r)*K + kb + c);
                As[c+0][r]=val.x; As[c+1][r]=val.y; As[c+2][r]=val.z; As[c+3][r]=val.w;
            }
        }
        #pragma unroll
        for (int l = 0; l < 2; l++) {
            int idx = tid + l*128;
            int r = idx >> 3, c = (idx & 7)*4;
            float4 val = (r < tl.nvalid) ?
                *(const float4*)(tl.B + (size_t)r*K + kb + c) : make_float4(0,0,0,0);
            Bs[c+0][r]=val.x; Bs[c+1][r]=val.y; Bs[c+2][r]=val.z; Bs[c+3][r]=val.w;
        }
        __syncthreads();
        #pragma unroll
        for (int kk = 0; kk < BK; kk++) {
            float4 m0 = *(const float4*)&As[kk][ty*8];
            float4 m1 = *(const float4*)&As[kk][ty*8+4];
            float4 rn = *(const float4*)&Bs[kk][tx*4];
            float rm[8] = {m0.x,m0.y,m0.z,m0.w,m1.x,m1.y,m1.z,m1.w};
            #pragma unroll
            for (int i=0;i<8;i++) {
                acc[i][0] = fmaf(rm[i], rn.x, acc[i][0]);
                acc[i][1] = fmaf(rm[i], rn.y, acc[i][1]);
                acc[i][2] = fmaf(rm[i], rn.z, acc[i][2]);
                acc[i][3] = fmaf(rm[i], rn.w, acc[i][3]);
            }
        }
        __syncthreads();
    }
    #pragma unroll
    for (int i=0;i<8;i++) {
        int row = bm0 + ty*8 + i;
        #pragma unroll
        for (int j=0;j<4;j++) {
            int col = tx*4 + j;
            if (col < tl.nvalid) {
                float vv = acc[i][j];
                if (tl.tanhf) vv = tanhf(vv);
                tl.C[(size_t)row*tl.ldc + col] = vv;
            }
        }
    }
}

// ---------------------------------------------------------------------------
// Fused xm kernel: per group g, val = x + xx*(Ag @ Bg + time_maa[g]).
// g==1 -> fp32 out (xwa); else packed (hi,lo) fp16 out.
// ---------------------------------------------------------------------------
__global__ __launch_bounds__(256, 2)
void xm_kernel(const float* __restrict__ hmaa,
               const float* __restrict__ maa_w2,
               const float* __restrict__ x,
               const float* __restrict__ xx,
               const float* __restrict__ time_maa,
               float* __restrict__ xmbase)
{
    constexpr int BM=128, BN=128, BK=32;
    __shared__ float As[BK][BM+1];
    __shared__ float Bs[BK][BN];
    const int g = blockIdx.z;
    const float* A = hmaa + g*32;
    const float* B = maa_w2 + (size_t)g*32*NEC;
    float* C = xmbase + (size_t)g*MT*NEC;
    const float* tm = time_maa + g*NEC;
    const int bm0 = blockIdx.y*BM, bn0 = blockIdx.x*BN;
    const int tid = threadIdx.x;
    const int tx = tid & 15, ty = tid >> 4;

    float acc[8][8];
    #pragma unroll
    for (int i=0;i<8;i++)
        #pragma unroll
        for (int j=0;j<8;j++) acc[i][j]=0.f;

    #pragma unroll
    for (int l = 0; l < 4; l++) {
        int idx = tid + l*256;
        int r = idx >> 3, c = (idx & 7)*4;
        float4 val = *(const float4*)(A + (size_t)(bm0+r)*128 + c);
        As[c+0][r]=val.x; As[c+1][r]=val.y; As[c+2][r]=val.z; As[c+3][r]=val.w;
    }
    #pragma unroll
    for (int l = 0; l < 4; l++) {
        int idx = tid + l*256;
        int r = idx >> 5, c = (idx & 31)*4;
        *(float4*)&Bs[r][c] = *(const float4*)(B + (size_t)r*NEC + bn0 + c);
    }
    __syncthreads();
    #pragma unroll
    for (int kk = 0; kk < BK; kk++) {
        float rm[8], rn[8];
        #pragma unroll
        for (int i=0;i<8;i++) rm[i] = As[kk][ty*8+i];
        #pragma unroll
        for (int j=0;j<8;j++) rn[j] = Bs[kk][tx*8+j];
        #pragma unroll
        for (int i=0;i<8;i++)
            #pragma unroll
            for (int j=0;j<8;j++) acc[i][j] = fmaf(rm[i], rn[j], acc[i][j]);
    }
    #pragma unroll
    for (int i=0;i<8;i++) {
        int row = bm0 + ty*8 + i;
        #pragma unroll
        for (int j=0;j<8;j+=2) {
            int col = bn0 + tx*8 + j;
            size_t idx = (size_t)row*NEC + col;
            float2 xv = *(const float2*)&x[idx];
            float2 dv = *(const float2*)&xx[idx];
            float v0 = fmaf(dv.x, acc[i][j]   + tm[col],   xv.x);
            float v1 = fmaf(dv.y, acc[i][j+1] + tm[col+1], xv.y);
            if (g == 1) {
                *(float2*)&C[idx] = make_float2(v0, v1);
            } else {
                uint2 pk = make_uint2(packf(v0), packf(v1));
                *(uint2*)&((uint32_t*)C)[idx] = pk;
            }
        }
    }
}

// ---------------------------------------------------------------------------
// Grouped second-stage NN kernel
// ---------------------------------------------------------------------------
struct NNGroup { const float* A; const float* B; float* C; int K; int epi;
                 const float* e2; };
struct NNArgs { NNGroup g[6]; };

__global__ __launch_bounds__(256)
void lora_nn_kernel(NNArgs args)
{
    constexpr int BM=128, BN=128, BK=16;
    __shared__ float As[BK][BM+1];
    __shared__ float Bs[BK][BN];
    NNGroup grp = args.g[blockIdx.z];
    const int K = grp.K;
    const int bm0 = blockIdx.y*BM, bn0 = blockIdx.x*BN;
    const int tid = threadIdx.x;
    const int tx = tid & 15, ty = tid >> 4;

    float acc[8][8];
    #pragma unroll
    for (int i=0;i<8;i++)
        #pragma unroll
        for (int j=0;j<8;j++) acc[i][j]=0.f;

    for (int kb = 0; kb < K; kb += BK) {
        #pragma unroll
        for (int l = 0; l < 2; l++) {
            int idx = tid + l*256;
            int r = idx >> 2, c = (idx & 3)*4;
            float4 val = *(const float4*)(grp.A + (size_t)(bm0+r)*K + kb + c);
            As[c+0][r]=val.x; As[c+1][r]=val.y; As[c+2][r]=val.z; As[c+3][r]=val.w;
        }
        #pragma unroll
        for (int l = 0; l < 2; l++) {
            int idx = tid + l*256;
            int r = idx >> 5, c = (idx & 31)*4;
            *(float4*)&Bs[r][c] = *(const float4*)(grp.B + (size_t)(kb+r)*NEC + bn0 + c);
        }
        __syncthreads();
        #pragma unroll
        for (int kk = 0; kk < BK; kk++) {
            float rm[8], rn[8];
            #pragma unroll
            for (int i=0;i<8;i++) rm[i] = As[kk][ty*8+i];
            #pragma unroll
            for (int j=0;j<8;j++) rn[j] = Bs[kk][tx*8+j];
            #pragma unroll
            for (int i=0;i<8;i++)
                #pragma unroll
                for (int j=0;j<8;j++) acc[i][j] = fmaf(rm[i], rn[j], acc[i][j]);
        }
        __syncthreads();
    }
    #pragma unroll
    for (int i=0;i<8;i++) {
        int row = bm0 + ty*8 + i;
        #pragma unroll
        for (int j=0;j<8;j++) {
            int col = bn0 + tx*8 + j;
            size_t idx = (size_t)row*NEC + col;
            float vv = acc[i][j], outv;
            switch (grp.epi) {
                case EPI_W: {
                    float tt = -(grp.e2[col] + vv);
                    float sp = (tt > 15.f) ? tt : log1pf(expf(tt));
                    outv = -sp - 0.5f;
                } break;
                case EPI_SIG: {
                    float u = grp.e2[col] + vv;
                    outv = 1.f / (1.f + expf(-u));
                } break;
                default: outv = vv;
            }
            grp.C[idx] = outv;
        }
    }
}

// ---------------------------------------------------------------------------
// warp sum
// ---------------------------------------------------------------------------
__device__ __forceinline__ float warp_sum(float v)
{
    #pragma unroll
    for (int o = 16; o > 0; o >>= 1) v += __shfl_xor_sync(0xffffffffu, v, o);
    return v;
}

// ---------------------------------------------------------------------------
// prep: kk = normalize(kkraw + k); b = -kk*a; k final; w transform
// ---------------------------------------------------------------------------
__global__ void prep_kernel(float* kptr, float* kkptr,
                            const float* __restrict__ a,
                            const float* __restrict__ ma,
                            const float* __restrict__ mk,
                            float* wptr,
                            float* __restrict__ b)
{
    int m = blockIdx.x;
    int h = threadIdx.x >> 5;
    int lane = threadIdx.x & 31;
    size_t base = (size_t)m*NEC + h*HSZ;
    size_t i0 = base + lane, i1 = i0 + 32;

    float k0v = kptr[i0], k1v = kptr[i1];
    float kk0 = kkptr[i0] + k0v, kk1 = kkptr[i1] + k1v;
    float ss = warp_sum(kk0*kk0 + kk1*kk1);
    float inv = 1.f / fmaxf(sqrtf(ss), 1e-12f);
    float n0 = kk0*inv, n1 = kk1*inv;
    kkptr[i0] = n0; kkptr[i1] = n1;

    float a0 = a[i0], a1 = a[i1];
    b[i0] = -n0*a0; b[i1] = -n1*a1;

    float ma0 = ma[i0], ma1 = ma[i1];
    float w0 = wptr[i0], w1 = wptr[i1];
    float mk0 = mk[i0], mk1 = mk[i1];
    kptr[i0] = k0v * (ma0 + a0*(1.f - ma0)) * expf(w0*mk0);
    kptr[i1] = k1v * (ma1 + a1*(1.f - ma1)) * expf(w1*mk1);
    wptr[i0] = expf(-expf(w0));
    wptr[i1] = expf(-expf(w1));
}

// ---------------------------------------------------------------------------
// RWKV7 recurrence v4: 2 blocks per head; 32 rows x 8-way column split;
// 3-stage cp.async ring.
// ---------------------------------------------------------------------------
__global__ __launch_bounds__(256)
void wkv7_kernel(const float* __restrict__ q, const float* __restrict__ w,
                 const float* __restrict__ k, const float* __restrict__ v,
                 const float* __restrict__ a, const float* __restrict__ b,
                 float* __restrict__ y)
{
    const int blk = blockIdx.x;            // 0..127
    const int bh = blk >> 1, rh = blk & 1;
    const int batch = bh >> 4, h = bh & 15;
    const int tid = threadIdx.x;
    const int il = tid >> 3, qd = tid & 7;

    __shared__ __align__(16) float buf[3][352];

    float s[8];
    #pragma unroll
    for (int j = 0; j < 8; j++) s[j] = 0.f;

    const size_t base = (size_t)batch * TSEQ * NEC + (size_t)h * HSZ;

    const float* table[4] = {q, w, k, a};
    const float* s0 = table[tid>>6] + base + (tid & 63);
    const float* s1 = nullptr;
    if (tid < 64)       s1 = b + base + tid;
    else if (tid < 96)  s1 = v + base + rh*32 + (tid - 64);
    const uint32_t sb = (uint32_t)__cvta_generic_to_shared(buf);
    const uint32_t d0 = sb + (uint32_t)tid*4;
    const uint32_t d1 = sb + (uint32_t)(256 + tid)*4;
    const uint32_t STRB = 352*4;

    cpa4(d0, s0);
    if (tid < 96) cpa4(d1, s1);
    CP_COMMIT();
    cpa4(d0 + STRB, s0 + NEC);
    if (tid < 96) cpa4(d1 + STRB, s1 + NEC);
    CP_COMMIT();

    const size_t ybase = base + (size_t)rh*32 + il;

    int p = 0;
    for (int t = 0; t < TSEQ; t++) {
        CP_WAIT1();
        __syncthreads();

        {
            int st = p + 2; if (st >= 3) st -= 3;
            if (t + 2 < TSEQ) {
                size_t o = (size_t)(t+2)*NEC;
                cpa4(d0 + (uint32_t)st*STRB, s0 + o);
                if (tid < 96) cpa4(d1 + (uint32_t)st*STRB, s1 + o);
            }
            CP_COMMIT();
        }

        const float* bb = buf[p];
        const int co = qd*8;
        const float4* q4 = (const float4*)(bb +   0 + co);
        const float4* w4 = (const float4*)(bb +  64 + co);
        const float4* k4 = (const float4*)(bb + 128 + co);
        const float4* a4 = (const float4*)(bb + 192 + co);
        const float4* b4 = (const float4*)(bb + 256 + co);
        float vi = bb[320 + il];

        float4 av0 = a4[0], av1 = a4[1];
        float sa0 = fmaf(s[0], av0.x, s[4]*av1.x);
        float sa1 = fmaf(s[1], av0.y, s[5]*av1.y);
        float sa2 = fmaf(s[2], av0.z, s[6]*av1.z);
        float sa3 = fmaf(s[3], av0.w, s[7]*av1.w);
        float sa = (sa0+sa1) + (sa2+sa3);
        sa += __shfl_xor_sync(0xffffffffu, sa, 1);
        sa += __shfl_xor_sync(0xffffffffu, sa, 2);
        sa += __shfl_xor_sync(0xffffffffu, sa, 4);

        float4 wv0 = w4[0], wv1 = w4[1];
        float4 kv0 = k4[0], kv1 = k4[1];
        float4 bv0 = b4[0], bv1 = b4[1];
        float4 qv0 = q4[0], qv1 = q4[1];

        float t0 = fmaf(s[0], wv0.x, fmaf(sa, bv0.x, vi*kv0.x));
        float t1 = fmaf(s[1], wv0.y, fmaf(sa, bv0.y, vi*kv0.y));
        float t2 = fmaf(s[2], wv0.z, fmaf(sa, bv0.z, vi*kv0.z));
        float t3 = fmaf(s[3], wv0.w, fmaf(sa, bv0.w, vi*kv0.w));
        float t4 = fmaf(s[4], wv1.x, fmaf(sa, bv1.x, vi*kv1.x));
        float t5 = fmaf(s[5], wv1.y, fmaf(sa, bv1.y, vi*kv1.y));
        float t6 = fmaf(s[6], wv1.z, fmaf(sa, bv1.z, vi*kv1.z));
        float t7 = fmaf(s[7], wv1.w, fmaf(sa, bv1.w, vi*kv1.w));
        s[0]=t0; s[1]=t1; s[2]=t2; s[3]=t3; s[4]=t4; s[5]=t5; s[6]=t6; s[7]=t7;

        float y0 = fmaf(t0, qv0.x, t4*qv1.x);
        float y1 = fmaf(t1, qv0.y, t5*qv1.y);
        float y2 = fmaf(t2, qv0.z, t6*qv1.z);
        float y3 = fmaf(t3, qv0.w, t7*qv1.w);
        float yi = (y0+y1) + (y2+y3);
        yi += __shfl_xor_sync(0xffffffffu, yi, 1);
        yi += __shfl_xor_sync(0xffffffffu, yi, 2);
        yi += __shfl_xor_sync(0xffffffffu, yi, 4);
        if (qd == 0) y[ybase + (size_t)t*NEC] = yi;

        if (++p == 3) p = 0;
    }
}

// ---------------------------------------------------------------------------
// GroupNorm + bonus + gate -> packed z
// ---------------------------------------------------------------------------
__global__ void gn_kernel(const float* __restrict__ y,
                          const float* __restrict__ r,
                          const float* __restrict__ k,
                          const float* __restrict__ v,
                          const float* __restrict__ gg,
                          const float* __restrict__ ln_w,
                          const float* __restrict__ ln_b,
                          const float* __restrict__ faaaa,
                          uint32_t* __restrict__ zpk)
{
    int m = blockIdx.x;
    int h = threadIdx.x >> 5;
    int lane = threadIdx.x & 31;
    size_t base = (size_t)m*NEC + h*HSZ;
    int c0 = h*HSZ + lane, c1 = c0 + 32;
    size_t i0 = base + lane, i1 = i0 + 32;

    float y0 = y[i0], y1 = y[i1];
    float mu = warp_sum(y0 + y1) * (1.f/64.f);
    float d0 = y0 - mu, d1 = y1 - mu;
    float var = warp_sum(d0*d0 + d1*d1) * (1.f/64.f);
    float rstd = rsqrtf(var + EPSGN);
    float yn0 = d0*rstd*ln_w[c0] + ln_b[c0];
    float yn1 = d1*rstd*ln_w[c1] + ln_b[c1];

    float r0 = r[i0], r1 = r[i1];
    float k0v = k[i0], k1v = k[i1];
    float rk = warp_sum(r0*k0v*faaaa[c0] + r1*k1v*faaaa[c1]);

    float v0 = v[i0], v1 = v[i1];
    zpk[i0] = packf((yn0 + rk*v0) * gg[i0]);
    zpk[i1] = packf((yn1 + rk*v1) * gg[i1]);
}

// ---------------------------------------------------------------------------
// Host side
// ---------------------------------------------------------------------------
extern "C" void kernel_launch(void* const* d_in, const int* in_sizes, int n_in,
                              void* d_out, int out_size)
{
    const float* x          = (const float*)d_in[0];
    const float* time_maa_x = (const float*)d_in[1];
    const float* time_maa   = (const float*)d_in[2];
    const float* maa_w1     = (const float*)d_in[3];
    const float* maa_w2     = (const float*)d_in[4];
    const float* decay_w1   = (const float*)d_in[5];
    const float* decay_w2   = (const float*)d_in[6];
    const float* aaa_w1     = (const float*)d_in[7];
    const float* aaa_w2     = (const float*)d_in[8];
    const float* kkk_w1     = (const float*)d_in[9];
    const float* kkk_w2     = (const float*)d_in[10];
    const float* gate_w1    = (const float*)d_in[11];
    const float* gate_w2    = (const float*)d_in[12];
    const float* ma_w1      = (const float*)d_in[13];
    const float* ma_w2      = (const float*)d_in[14];
    const float* mk_w1      = (const float*)d_in[15];
    const float* mk_w2      = (const float*)d_in[16];
    const float* time_decay = (const float*)d_in[17];
    const float* time_faaaa = (const float*)d_in[18];
    const float* time_aaaaa = (const float*)d_in[19];
    const float* time_misc_a= (const float*)d_in[20];
    const float* time_misc_k= (const float*)d_in[21];
    const float* Wr         = (const float*)d_in[22];
    const float* Wk         = (const float*)d_in[23];
    const float* Wv         = (const float*)d_in[24];
    const float* Wo         = (const float*)d_in[25];
    const float* ln_w       = (const float*)d_in[26];
    const float* ln_b       = (const float*)d_in[27];
    float* out = (float*)d_out;

    float *xx,*mix,*hmaa,*hgate,*hdec,*haaa,*hma,*hkkk,*hmk,*xm;
    __half *whalf; uint32_t *zpk;
    float *r,*gg,*k,*v,*w,*kk,*a,*ma,*mk,*b,*y;
    cudaGetSymbolAddress((void**)&xx,   g_xx);
    cudaGetSymbolAddress((void**)&mix,  g_mix);
    cudaGetSymbolAddress((void**)&hmaa, g_hmaa);
    cudaGetSymbolAddress((void**)&hgate,g_hgate);
    cudaGetSymbolAddress((void**)&hdec, g_hdec);
    cudaGetSymbolAddress((void**)&haaa, g_haaa);
    cudaGetSymbolAddress((void**)&hma,  g_hma);
    cudaGetSymbolAddress((void**)&hkkk, g_hkkk);
    cudaGetSymbolAddress((void**)&hmk,  g_hmk);
    cudaGetSymbolAddress((void**)&xm,   g_xm);
    cudaGetSymbolAddress((void**)&whalf,g_whalf);
    cudaGetSymbolAddress((void**)&zpk,  g_zpk);
    cudaGetSymbolAddress((void**)&r,    g_r);
    cudaGetSymbolAddress((void**)&gg,   g_gg);
    cudaGetSymbolAddress((void**)&k,    g_k);
    cudaGetSymbolAddress((void**)&v,    g_v);
    cudaGetSymbolAddress((void**)&w,    g_w);
    cudaGetSymbolAddress((void**)&kk,   g_kk);
    cudaGetSymbolAddress((void**)&a,    g_a);
    cudaGetSymbolAddress((void**)&ma,   g_ma);
    cudaGetSymbolAddress((void**)&mk,   g_mk);
    cudaGetSymbolAddress((void**)&b,    g_b);
    cudaGetSymbolAddress((void**)&y,    g_y);

    const size_t S = (size_t)MT*NEC;
    const uint32_t* xrg_pk = (const uint32_t*)(xm + 0*S);
    const float*    xwa    = xm + 1*S;
    const uint32_t* xk_pk  = (const uint32_t*)(xm + 2*S);
    const uint32_t* xv_pk  = (const uint32_t*)(xm + 3*S);

    static bool attr_done = false;
    if (!attr_done) {
        cudaFuncSetAttribute(gemm_tc5, cudaFuncAttributeMaxDynamicSharedMemorySize,
                             2*G5_STG*4);
        attr_done = true;
    }
    const int g5_smem = 2*G5_STG*4;

    // 1) token shift (float4)
    shift_kernel<<<(unsigned)((S/4 + 255)/256), 256>>>(x, time_maa_x, xx, mix);

    // 2) weight pack: all 4 -> plain fp16
    wpack_kernel<<<(unsigned)((2*NM + 255)/256), 256>>>(Wr, Wk, Wv, Wo, whalf);

    // 3) maa hidden (4 tiles)
    {
        NTArgs na = {};
        na.Aptr[0] = mix; na.apk[0] = 0;
        for (int i = 0; i < 4; i++)
            na.t[i] = { maa_w1 + (size_t)i*32*NEC, hmaa + i*32, 128, 32, 1, 0 };
        lora_nt_kernel<<<dim3(4, MT/128), 128>>>(na);
    }

    // 4) xm fused (4 groups; packed for 0/2/3, fp32 for 1)
    xm_kernel<<<dim3(8, MT/128, 4), 256>>>(hmaa, maa_w2, x, xx, time_maa, xm);

    // 5) hidden group 2 (10 tiles)
    {
        NTArgs na = {};
        na.Aptr[0] = xrg_pk; na.apk[0] = 1;
        na.Aptr[1] = xwa;    na.apk[1] = 0;
        na.Aptr[2] = xk_pk;  na.apk[2] = 1;
        int ti = 0;
        for (int i = 0; i < 4; i++)
            na.t[ti++] = { gate_w1 + (size_t)i*32*NEC, hgate + i*32, 128, 32, 1, 0 };
        for (int i = 0; i < 2; i++)
            na.t[ti++] = { decay_w1 + (size_t)i*32*NEC, hdec + i*32, 64, 32, 1, 1 };
        na.t[ti++] = { aaa_w1, haaa, 16, 16, 0, 1 };
        na.t[ti++] = { ma_w1,  hma,  16, 16, 0, 1 };
        na.t[ti++] = { kkk_w1, hkkk, 16, 16, 1, 2 };
        na.t[ti++] = { mk_w1,  hmk,  16, 16, 0, 2 };
        lora_nt_kernel<<<dim3(10, MT/128), 128>>>(na);
    }

    // 6) big GEMMs r,k,v: 2-product, fused (grid.z = 3)
    {
        G5Args ga = {};
        ga.A[0] = xrg_pk; ga.B[0] = whalf + 0*NM; ga.C[0] = r;
        ga.A[1] = xk_pk;  ga.B[1] = whalf + 1*NM; ga.C[1] = k;
        ga.A[2] = xv_pk;  ga.B[2] = whalf + 2*NM; ga.C[2] = v;
        gemm_tc5<<<dim3(8,32,3), 256, g5_smem>>>(ga, NEC, NEC);
    }

    // 7) second stage (6 groups; kk group writes raw LoRA output)
    {
        NNArgs nn = {};
        nn.g[0] = { hgate, gate_w2,  gg, 128, EPI_NONE, nullptr };
        nn.g[1] = { hdec,  decay_w2, w,   64, EPI_W,    time_decay };
        nn.g[2] = { hkkk,  kkk_w2,   kk,  16, EPI_NONE, nullptr };
        nn.g[3] = { haaa,  aaa_w2,   a,   16, EPI_SIG,  time_aaaaa };
        nn.g[4] = { hma,   ma_w2,    ma,  16, EPI_SIG,  time_misc_a };
        nn.g[5] = { hmk,   mk_w2,    mk,  16, EPI_SIG,  time_misc_k };
        lora_nn_kernel<<<dim3(8, MT/128, 6), 256>>>(nn);
    }

    // 8) prep (adds +k to kkraw before norm)
    prep_kernel<<<MT, 512>>>(k, kk, a, ma, mk, w, b);

    // 9) recurrence (2 blocks per head)
    wkv7_kernel<<<BATCH*NH*2, 256>>>(r, w, k, v, kk, b, y);

    // 10) groupnorm + bonus + gate -> packed z
    gn_kernel<<<MT, 512>>>(y, r, k, v, gg, ln_w, ln_b, time_faaaa, zpk);

    // 11) out = z @ Wo.T (2-product: exact z x fp16 Wo)
    {
        G5Args ga = {};
        ga.A[0] = zpk; ga.B[0] = whalf + 3*NM; ga.C[0] = out;
        gemm_tc5<<<dim3(8,32,1), 256, g5_smem>>>(ga, NEC, NEC);
    }
}

// round 13
// speedup vs baseline: 1.2211x; 1.0853x over previous
#include <cuda_runtime.h>
#include <cuda_fp16.h>
#include <math.h>
#include <stdint.h>

// Problem constants
#define BATCH 4
#define TSEQ  1024
#define NEC   1024
#define NH    16
#define HSZ   64
#define MT    (BATCH*TSEQ)      // 4096 rows
#define EPSGN 0.00064f
#define NM    ((size_t)NEC*NEC) // 1M
#define HIDW  ((size_t)128*NEC) // one hidden weight slice

// ---------------------------------------------------------------------------
// Scratch (device globals)
// ---------------------------------------------------------------------------
__device__ float    g_xx   [(size_t)MT*NEC];
__device__ float    g_mix  [(size_t)MT*NEC];
__device__ float    g_hmaa [(size_t)MT*128];
__device__ float    g_hgate[(size_t)MT*128];
__device__ float    g_hwaa [(size_t)MT*128];   // decay(0:64) aaa(64:80) ma(80:96)
__device__ float    g_hk   [(size_t)MT*128];   // kkk(0:16) mk(16:32)
__device__ uint32_t g_xm   [4][(size_t)MT*NEC]; // all packed (hi,lo) half2
__device__ __half   g_whalf[4*NM];             // Wr,Wk,Wv,Wo plain fp16
__device__ __half   g_whid [3*HIDW];           // hidden w1 slices fp16
__device__ uint32_t g_zpk  [(size_t)MT*NEC];
__device__ float    g_r    [(size_t)MT*NEC];
__device__ float    g_gg   [(size_t)MT*NEC];
__device__ float    g_k    [(size_t)MT*NEC];
__device__ float    g_v    [(size_t)MT*NEC];
__device__ float    g_w    [(size_t)MT*NEC];
__device__ float    g_kk   [(size_t)MT*NEC];
__device__ float    g_a    [(size_t)MT*NEC];
__device__ float    g_ma   [(size_t)MT*NEC];
__device__ float    g_mk   [(size_t)MT*NEC];
__device__ float    g_b    [(size_t)MT*NEC];
__device__ float    g_y    [(size_t)MT*NEC];

enum { EPI_NONE=0, EPI_W=3, EPI_SIG=5 };

// ---------------------------------------------------------------------------
// helpers
// ---------------------------------------------------------------------------
__device__ __forceinline__ uint32_t packf(float v){
    __half hi = __float2half_rn(v);
    __half lo = __float2half_rn(v - __half2float(hi));
    __half2 h2 = __halves2half2(hi, lo);
    return *reinterpret_cast<uint32_t*>(&h2);
}
__device__ __forceinline__ void mma_f16(float* c, const uint32_t* a, const uint32_t* b){
    asm volatile("mma.sync.aligned.m16n8k16.row.col.f32.f16.f16.f32 "
        "{%0,%1,%2,%3},{%4,%5,%6,%7},{%8,%9},{%0,%1,%2,%3};\n"
        : "+f"(c[0]), "+f"(c[1]), "+f"(c[2]), "+f"(c[3])
        : "r"(a[0]), "r"(a[1]), "r"(a[2]), "r"(a[3]), "r"(b[0]), "r"(b[1]));
}
__device__ __forceinline__ void cpa16(uint32_t dst, const void* src){
    asm volatile("cp.async.cg.shared.global [%0],[%1],16;\n"::"r"(dst),"l"(src));
}
__device__ __forceinline__ void cpa4(uint32_t dst, const void* src){
    asm volatile("cp.async.ca.shared.global [%0],[%1],4;\n"::"r"(dst),"l"(src));
}
#define CP_COMMIT() asm volatile("cp.async.commit_group;\n")
#define CP_WAIT0()  asm volatile("cp.async.wait_group 0;\n")
#define CP_WAIT1()  asm volatile("cp.async.wait_group 1;\n")

// ---------------------------------------------------------------------------
// Token shift (float4)
// ---------------------------------------------------------------------------
__global__ void shift_kernel(const float* __restrict__ x,
                             const float* __restrict__ tmaax,
                             float* __restrict__ xx,
                             float* __restrict__ mix)
{
    size_t i4 = (size_t)blockIdx.x * blockDim.x + threadIdx.x;
    if (i4 >= (size_t)MT * NEC / 4) return;
    size_t idx = i4 * 4;
    int c = (int)(idx % NEC);
    size_t row = idx / NEC;
    int t = (int)(row % TSEQ);
    float4 xv = *(const float4*)&x[idx];
    float4 xp = (t > 0) ? *(const float4*)&x[idx - NEC] : make_float4(0,0,0,0);
    float4 tm = *(const float4*)&tmaax[c];
    float4 d  = make_float4(xp.x-xv.x, xp.y-xv.y, xp.z-xv.z, xp.w-xv.w);
    *(float4*)&xx[idx] = d;
    float4 m;
    m.x = fmaf(d.x, tm.x, xv.x);
    m.y = fmaf(d.y, tm.y, xv.y);
    m.z = fmaf(d.z, tm.z, xv.z);
    m.w = fmaf(d.w, tm.w, xv.w);
    *(float4*)&mix[idx] = m;
}

// ---------------------------------------------------------------------------
// Weight pack: Wr/Wk/Wv/Wo -> fp16 (half2 stores)
// ---------------------------------------------------------------------------
__global__ void wpack_kernel(const float* __restrict__ Wr, const float* __restrict__ Wk,
                             const float* __restrict__ Wv, const float* __restrict__ Wo,
                             __half* __restrict__ whalf)
{
    size_t i = (size_t)blockIdx.x * blockDim.x + threadIdx.x;   // 2 elems each
    if (i >= 2*NM) return;
    int seg = (int)(i >> 19);
    size_t off2 = (i & ((NM>>1) - 1)) * 2;
    const float* src = (seg==0) ? Wr : (seg==1) ? Wk : (seg==2) ? Wv : Wo;
    float2 v = *(const float2*)&src[off2];
    __half2 h = __halves2half2(__float2half_rn(v.x), __float2half_rn(v.y));
    *(__half2*)&whalf[(size_t)seg*NM + off2] = h;
}

// ---------------------------------------------------------------------------
// Hidden weight pack: 3 padded slices [128][1024] fp16
//   s0 = gate_w1(128); s1 = decay(64)+aaa(16)+ma(16)+pad(32); s2 = kkk(16)+mk(16)+pad(96)
// ---------------------------------------------------------------------------
__global__ void wpack2_kernel(const float* __restrict__ gate_w1,
                              const float* __restrict__ decay_w1,
                              const float* __restrict__ aaa_w1,
                              const float* __restrict__ ma_w1,
                              const float* __restrict__ kkk_w1,
                              const float* __restrict__ mk_w1,
                              __half* __restrict__ whid)
{
    size_t i = (size_t)blockIdx.x * blockDim.x + threadIdx.x;
    if (i >= 3*HIDW) return;
    int slice = (int)(i / HIDW);
    size_t rem = i - (size_t)slice*HIDW;
    int row = (int)(rem >> 10);
    float v = 0.f;
    if (slice == 0) v = gate_w1[rem];
    else if (slice == 1) {
        if (row < 64)      v = decay_w1[rem];
        else if (row < 80) v = aaa_w1[rem - (size_t)64*NEC];
        else if (row < 96) v = ma_w1[rem - (size_t)80*NEC];
    } else {
        if (row < 16)      v = kkk_w1[rem];
        else if (row < 32) v = mk_w1[rem - (size_t)16*NEC];
    }
    whid[i] = __float2half_rn(v);
}

// ---------------------------------------------------------------------------
// 2-product NT GEMM mega-launch: grid (8, 32, 4).
//   z 0..2: C[4096,1024] = (Ah+Al) * Bh^T   (r/k/v)
//   z ==3 : blockIdx.x = hidden slice 0..2 (others exit); N=128, tanh-prefix epi.
// ---------------------------------------------------------------------------
#define G5_LDSW 36
#define G5_AW   (128*G5_LDSW)
#define G5_LDHB 40
#define G5_BW   (128*G5_LDHB/2)
#define G5_STG  (G5_AW + G5_BW)

struct G5Args {
    const uint32_t* A[3]; const __half* B[3]; float* C[3];
    const uint32_t* HA[3]; const __half* HB[3]; float* HC[3]; int tanhN[3];
    int nz;   // 3 = rkv+hidden, 1 = Wo only
};

__global__ __launch_bounds__(256, 2)
void gemm_tc5(G5Args args, int K)
{
    extern __shared__ uint32_t sm5[];
    const int z = blockIdx.z;
    const uint32_t* Apk; const __half* Bhp; float* C;
    int bn0, ldc, tanhN;
    if (z < args.nz) {
        Apk = args.A[z]; Bhp = args.B[z]; C = args.C[z];
        bn0 = blockIdx.x*128; ldc = NEC; tanhN = -1;
    } else {
        int s = blockIdx.x;
        if (s >= 3) return;
        Apk = args.HA[s]; Bhp = args.HB[s]; C = args.HC[s];
        bn0 = 0; ldc = 128; tanhN = args.tanhN[s];
    }
    const int tid = threadIdx.x;
    const int bm0 = blockIdx.y*128;
    const int warp = tid>>5, lane = tid&31, grp = lane>>2, q = lane&3;
    const int wm = (warp&1)*64, wn = (warp>>1)*32;
    const uint32_t sbase = (uint32_t)__cvta_generic_to_shared(sm5);

    float acc[4][4][4];
    #pragma unroll
    for (int mi=0;mi<4;mi++)
        #pragma unroll
        for (int ni=0;ni<4;ni++)
            #pragma unroll
            for (int e=0;e<4;e++) acc[mi][ni][e]=0.f;

    const uint32_t* asrc[4]; uint32_t adst[4];
    #pragma unroll
    for (int l = 0; l < 4; l++) {
        int idx = tid + l*256;
        int r = idx >> 3, c4 = idx & 7;
        asrc[l] = Apk + (size_t)(bm0+r)*K + c4*4;
        adst[l] = sbase + (uint32_t)(r*G5_LDSW + c4*4)*4;
    }
    const __half* bsrc[2]; uint32_t bdst[2];
    #pragma unroll
    for (int l = 0; l < 2; l++) {
        int idx = tid + l*256;
        int r = idx >> 2, c4 = idx & 3;
        bsrc[l] = Bhp + (size_t)(bn0+r)*K + c4*8;
        bdst[l] = sbase + G5_AW*4 + (uint32_t)(r*G5_LDHB + c4*8)*2;
    }

#define G5_LOAD(st, kb) do {                                   \
        uint32_t _o = (st)*G5_STG*4;                           \
        _Pragma("unroll")                                      \
        for (int l = 0; l < 4; l++)                            \
            cpa16(adst[l] + _o, asrc[l] + (kb));               \
        _Pragma("unroll")                                      \
        for (int l = 0; l < 2; l++)                            \
            cpa16(bdst[l] + _o, bsrc[l] + (kb));               \
    } while(0)

    G5_LOAD(0, 0); CP_COMMIT();

    int p = 0;
    for (int kb = 0; kb < K; kb += 32) {
        CP_WAIT0();
        __syncthreads();
        if (kb + 32 < K) { G5_LOAD(p^1, kb+32); CP_COMMIT(); }

        const uint32_t* SA = sm5 + p*G5_STG;
        const __half*   SB = (const __half*)(sm5 + p*G5_STG + G5_AW);

        #pragma unroll
        for (int kc = 0; kc < 32; kc += 16) {
            uint32_t ah[4][4], al[4][4], bh[4][2];
            #pragma unroll
            for (int mi = 0; mi < 4; mi++) {
                int r0 = (wm + mi*16 + grp)*G5_LDSW + kc + 2*q;
                uint2 w0 = *(const uint2*)&SA[r0];
                uint2 w1 = *(const uint2*)&SA[r0 + 8*G5_LDSW];
                uint2 w2 = *(const uint2*)&SA[r0 + 8];
                uint2 w3 = *(const uint2*)&SA[r0 + 8*G5_LDSW + 8];
                ah[mi][0]=__byte_perm(w0.x,w0.y,0x5410); al[mi][0]=__byte_perm(w0.x,w0.y,0x7632);
                ah[mi][1]=__byte_perm(w1.x,w1.y,0x5410); al[mi][1]=__byte_perm(w1.x,w1.y,0x7632);
                ah[mi][2]=__byte_perm(w2.x,w2.y,0x5410); al[mi][2]=__byte_perm(w2.x,w2.y,0x7632);
                ah[mi][3]=__byte_perm(w3.x,w3.y,0x5410); al[mi][3]=__byte_perm(w3.x,w3.y,0x7632);
            }
            #pragma unroll
            for (int ni = 0; ni < 4; ni++) {
                int c0 = (wn + ni*8 + grp)*G5_LDHB + kc + 2*q;
                bh[ni][0] = *(const uint32_t*)&SB[c0];
                bh[ni][1] = *(const uint32_t*)&SB[c0 + 8];
            }
            #pragma unroll
            for (int mi = 0; mi < 4; mi++)
                #pragma unroll
                for (int ni = 0; ni < 4; ni++) {
                    mma_f16(acc[mi][ni], ah[mi], bh[ni]);
                    mma_f16(acc[mi][ni], al[mi], bh[ni]);
                }
        }
        __syncthreads();
        p ^= 1;
    }

    #pragma unroll
    for (int mi = 0; mi < 4; mi++) {
        int row0 = bm0 + wm + mi*16 + grp;
        #pragma unroll
        for (int ni = 0; ni < 4; ni++) {
            int col = bn0 + wn + ni*8 + 2*q;
            float e0 = acc[mi][ni][0], e1 = acc[mi][ni][1];
            float e2 = acc[mi][ni][2], e3 = acc[mi][ni][3];
            if (tanhN >= 0) {
                if (col   < tanhN) { e0 = tanhf(e0); e2 = tanhf(e2); }
                if (col+1 < tanhN) { e1 = tanhf(e1); e3 = tanhf(e3); }
            }
            *(float2*)&C[(size_t)row0*ldc + col]     = make_float2(e0, e1);
            *(float2*)&C[(size_t)(row0+8)*ldc + col] = make_float2(e2, e3);
        }
    }
#undef G5_LOAD
}

// ---------------------------------------------------------------------------
// maa-hidden NT kernel (fp32, 4 tiles from mix): C = tanh(mix @ w1_tile^T)
// ---------------------------------------------------------------------------
struct NTTile { const float* B; float* C; };
struct NTArgs { const float* A; NTTile t[4]; };

__global__ __launch_bounds__(128)
void lora_nt_kernel(NTArgs args)
{
    constexpr int BK=32, K=NEC;
    __shared__ __align__(16) float As[BK][132];
    __shared__ __align__(16) float Bs[BK][36];
    NTTile tl = args.t[blockIdx.x];
    const float* A = args.A;
    const int bm0 = blockIdx.y*128;
    const int tid = threadIdx.x;
    const int tx = tid & 7;
    const int ty = tid >> 3;

    float acc[8][4];
    #pragma unroll
    for (int i=0;i<8;i++)
        #pragma unroll
        for (int j=0;j<4;j++) acc[i][j]=0.f;

    for (int kb = 0; kb < K; kb += BK) {
        #pragma unroll
        for (int l = 0; l < 8; l++) {
            int idx = tid + l*128;
            int r = idx >> 3, c = (idx & 7)*4;
            float4 val = *(const float4*)(A + (size_t)(bm0+r)*K + kb + c);
            As[c+0][r]=val.x; As[c+1][r]=val.y; As[c+2][r]=val.z; As[c+3][r]=val.w;
        }
        #pragma unroll
        for (int l = 0; l < 2; l++) {
            int idx = tid + l*128;
            int r = idx >> 3, c = (idx & 7)*4;
            float4 val = *(const float4*)(tl.B + (size_t)r*K + kb + c);
            Bs[c+0][r]=val.x; Bs[c+1][r]=val.y; Bs[c+2][r]=val.z; Bs[c+3][r]=val.w;
        }
        __syncthreads();
        #pragma unroll
        for (int kk = 0; kk < BK; kk++) {
            float4 m0 = *(const float4*)&As[kk][ty*8];
            float4 m1 = *(const float4*)&As[kk][ty*8+4];
            float4 rn = *(const float4*)&Bs[kk][tx*4];
            float rm[8] = {m0.x,m0.y,m0.z,m0.w,m1.x,m1.y,m1.z,m1.w};
            #pragma unroll
            for (int i=0;i<8;i++) {
                acc[i][0] = fmaf(rm[i], rn.x, acc[i][0]);
                acc[i][1] = fmaf(rm[i], rn.y, acc[i][1]);
                acc[i][2] = fmaf(rm[i], rn.z, acc[i][2]);
                acc[i][3] = fmaf(rm[i], rn.w, acc[i][3]);
            }
        }
        __syncthreads();
    }
    #pragma unroll
    for (int i=0;i<8;i++) {
        int row = bm0 + ty*8 + i;
        #pragma unroll
        for (int j=0;j<4;j++) {
            tl.C[(size_t)row*128 + tx*4 + j] = tanhf(acc[i][j]);
        }
    }
}

// ---------------------------------------------------------------------------
// Fused xm kernel: val = x + xx*(Ag @ Bg + time_maa[g]); all groups packed.
// ---------------------------------------------------------------------------
__global__ __launch_bounds__(256, 2)
void xm_kernel(const float* __restrict__ hmaa,
               const float* __restrict__ maa_w2,
               const float* __restrict__ x,
               const float* __restrict__ xx,
               const float* __restrict__ time_maa,
               uint32_t* __restrict__ xmbase)
{
    constexpr int BM=128, BN=128, BK=32;
    __shared__ float As[BK][BM+1];
    __shared__ float Bs[BK][BN];
    const int g = blockIdx.z;
    const float* A = hmaa + g*32;
    const float* B = maa_w2 + (size_t)g*32*NEC;
    uint32_t* C = xmbase + (size_t)g*MT*NEC;
    const float* tm = time_maa + g*NEC;
    const int bm0 = blockIdx.y*BM, bn0 = blockIdx.x*BN;
    const int tid = threadIdx.x;
    const int tx = tid & 15, ty = tid >> 4;

    float acc[8][8];
    #pragma unroll
    for (int i=0;i<8;i++)
        #pragma unroll
        for (int j=0;j<8;j++) acc[i][j]=0.f;

    #pragma unroll
    for (int l = 0; l < 4; l++) {
        int idx = tid + l*256;
        int r = idx >> 3, c = (idx & 7)*4;
        float4 val = *(const float4*)(A + (size_t)(bm0+r)*128 + c);
        As[c+0][r]=val.x; As[c+1][r]=val.y; As[c+2][r]=val.z; As[c+3][r]=val.w;
    }
    #pragma unroll
    for (int l = 0; l < 4; l++) {
        int idx = tid + l*256;
        int r = idx >> 5, c = (idx & 31)*4;
        *(float4*)&Bs[r][c] = *(const float4*)(B + (size_t)r*NEC + bn0 + c);
    }
    __syncthreads();
    #pragma unroll
    for (int kk = 0; kk < BK; kk++) {
        float rm[8], rn[8];
        #pragma unroll
        for (int i=0;i<8;i++) rm[i] = As[kk][ty*8+i];
        #pragma unroll
        for (int j=0;j<8;j++) rn[j] = Bs[kk][tx*8+j];
        #pragma unroll
        for (int i=0;i<8;i++)
            #pragma unroll
            for (int j=0;j<8;j++) acc[i][j] = fmaf(rm[i], rn[j], acc[i][j]);
    }
    #pragma unroll
    for (int i=0;i<8;i++) {
        int row = bm0 + ty*8 + i;
        #pragma unroll
        for (int j=0;j<8;j+=2) {
            int col = bn0 + tx*8 + j;
            size_t idx = (size_t)row*NEC + col;
            float2 xv = *(const float2*)&x[idx];
            float2 dv = *(const float2*)&xx[idx];
            float v0 = fmaf(dv.x, acc[i][j]   + tm[col],   xv.x);
            float v1 = fmaf(dv.y, acc[i][j+1] + tm[col+1], xv.y);
            *(uint2*)&C[idx] = make_uint2(packf(v0), packf(v1));
        }
    }
}

// ---------------------------------------------------------------------------
// Grouped second-stage NN kernel (A with lda + column offset)
// ---------------------------------------------------------------------------
struct NNGroup { const float* A; int lda; int koff; const float* B; float* C;
                 int K; int epi; const float* e2; };
struct NNArgs { NNGroup g[6]; };

__global__ __launch_bounds__(256)
void lora_nn_kernel(NNArgs args)
{
    constexpr int BM=128, BN=128, BK=16;
    __shared__ float As[BK][BM+1];
    __shared__ float Bs[BK][BN];
    NNGroup grp = args.g[blockIdx.z];
    const int K = grp.K;
    const int bm0 = blockIdx.y*BM, bn0 = blockIdx.x*BN;
    const int tid = threadIdx.x;
    const int tx = tid & 15, ty = tid >> 4;

    float acc[8][8];
    #pragma unroll
    for (int i=0;i<8;i++)
        #pragma unroll
        for (int j=0;j<8;j++) acc[i][j]=0.f;

    for (int kb = 0; kb < K; kb += BK) {
        #pragma unroll
        for (int l = 0; l < 2; l++) {
            int idx = tid + l*256;
            int r = idx >> 2, c = (idx & 3)*4;
            float4 val = *(const float4*)(grp.A + (size_t)(bm0+r)*grp.lda + grp.koff + kb + c);
            As[c+0][r]=val.x; As[c+1][r]=val.y; As[c+2][r]=val.z; As[c+3][r]=val.w;
        }
        #pragma unroll
        for (int l = 0; l < 2; l++) {
            int idx = tid + l*256;
            int r = idx >> 5, c = (idx & 31)*4;
            *(float4*)&Bs[r][c] = *(const float4*)(grp.B + (size_t)(kb+r)*NEC + bn0 + c);
        }
        __syncthreads();
        #pragma unroll
        for (int kk = 0; kk < BK; kk++) {
            float rm[8], rn[8];
            #pragma unroll
            for (int i=0;i<8;i++) rm[i] = As[kk][ty*8+i];
            #pragma unroll
            for (int j=0;j<8;j++) rn[j] = Bs[kk][tx*8+j];
            #pragma unroll
            for (int i=0;i<8;i++)
                #pragma unroll
                for (int j=0;j<8;j++) acc[i][j] = fmaf(rm[i], rn[j], acc[i][j]);
        }
        __syncthreads();
    }
    #pragma unroll
    for (int i=0;i<8;i++) {
        int row = bm0 + ty*8 + i;
        #pragma unroll
        for (int j=0;j<8;j++) {
            int col = bn0 + tx*8 + j;
            size_t idx = (size_t)row*NEC + col;
            float vv = acc[i][j], outv;
            switch (grp.epi) {
                case EPI_W: {
                    float tt = -(grp.e2[col] + vv);
                    float sp = (tt > 15.f) ? tt : log1pf(expf(tt));
                    outv = -sp - 0.5f;
                } break;
                case EPI_SIG: {
                    float u = grp.e2[col] + vv;
                    outv = 1.f / (1.f + expf(-u));
                } break;
                default: outv = vv;
            }
            grp.C[idx] = outv;
        }
    }
}

// ---------------------------------------------------------------------------
// warp sum
// ---------------------------------------------------------------------------
__device__ __forceinline__ float warp_sum(float v)
{
    #pragma unroll
    for (int o = 16; o > 0; o >>= 1) v += __shfl_xor_sync(0xffffffffu, v, o);
    return v;
}

// ---------------------------------------------------------------------------
// prep: kk = normalize(kkraw + k); b = -kk*a; k final; w transform
// ---------------------------------------------------------------------------
__global__ void prep_kernel(float* kptr, float* kkptr,
                            const float* __restrict__ a,
                            const float* __restrict__ ma,
                            const float* __restrict__ mk,
                            float* wptr,
                            float* __restrict__ b)
{
    int m = blockIdx.x;
    int h = threadIdx.x >> 5;
    int lane = threadIdx.x & 31;
    size_t base = (size_t)m*NEC + h*HSZ;
    size_t i0 = base + lane, i1 = i0 + 32;

    float k0v = kptr[i0], k1v = kptr[i1];
    float kk0 = kkptr[i0] + k0v, kk1 = kkptr[i1] + k1v;
    float ss = warp_sum(kk0*kk0 + kk1*kk1);
    float inv = 1.f / fmaxf(sqrtf(ss), 1e-12f);
    float n0 = kk0*inv, n1 = kk1*inv;
    kkptr[i0] = n0; kkptr[i1] = n1;

    float a0 = a[i0], a1 = a[i1];
    b[i0] = -n0*a0; b[i1] = -n1*a1;

    float ma0 = ma[i0], ma1 = ma[i1];
    float w0 = wptr[i0], w1 = wptr[i1];
    float mk0 = mk[i0], mk1 = mk[i1];
    kptr[i0] = k0v * (ma0 + a0*(1.f - ma0)) * expf(w0*mk0);
    kptr[i1] = k1v * (ma1 + a1*(1.f - ma1)) * expf(w1*mk1);
    wptr[i0] = expf(-expf(w0));
    wptr[i1] = expf(-expf(w1));
}

// ---------------------------------------------------------------------------
// RWKV7 recurrence v4: 2 blocks per head; 32 rows x 8-way column split;
// 3-stage cp.async ring.
// ---------------------------------------------------------------------------
__global__ __launch_bounds__(256)
void wkv7_kernel(const float* __restrict__ q, const float* __restrict__ w,
                 const float* __restrict__ k, const float* __restrict__ v,
                 const float* __restrict__ a, const float* __restrict__ b,
                 float* __restrict__ y)
{
    const int blk = blockIdx.x;            // 0..127
    const int bh = blk >> 1, rh = blk & 1;
    const int batch = bh >> 4, h = bh & 15;
    const int tid = threadIdx.x;
    const int il = tid >> 3, qd = tid & 7;

    __shared__ __align__(16) float buf[3][352];

    float s[8];
    #pragma unroll
    for (int j = 0; j < 8; j++) s[j] = 0.f;

    const size_t base = (size_t)batch * TSEQ * NEC + (size_t)h * HSZ;

    const float* table[4] = {q, w, k, a};
    const float* s0 = table[tid>>6] + base + (tid & 63);
    const float* s1 = nullptr;
    if (tid < 64)       s1 = b + base + tid;
    else if (tid < 96)  s1 = v + base + rh*32 + (tid - 64);
    const uint32_t sb = (uint32_t)__cvta_generic_to_shared(buf);
    const uint32_t d0 = sb + (uint32_t)tid*4;
    const uint32_t d1 = sb + (uint32_t)(256 + tid)*4;
    const uint32_t STRB = 352*4;

    cpa4(d0, s0);
    if (tid < 96) cpa4(d1, s1);
    CP_COMMIT();
    cpa4(d0 + STRB, s0 + NEC);
    if (tid < 96) cpa4(d1 + STRB, s1 + NEC);
    CP_COMMIT();

    const size_t ybase = base + (size_t)rh*32 + il;

    int p = 0;
    for (int t = 0; t < TSEQ; t++) {
        CP_WAIT1();
        __syncthreads();

        {
            int st = p + 2; if (st >= 3) st -= 3;
            if (t + 2 < TSEQ) {
                size_t o = (size_t)(t+2)*NEC;
                cpa4(d0 + (uint32_t)st*STRB, s0 + o);
                if (tid < 96) cpa4(d1 + (uint32_t)st*STRB, s1 + o);
            }
            CP_COMMIT();
        }

        const float* bb = buf[p];
        const int co = qd*8;
        const float4* q4 = (const float4*)(bb +   0 + co);
        const float4* w4 = (const float4*)(bb +  64 + co);
        const float4* k4 = (const float4*)(bb + 128 + co);
        const float4* a4 = (const float4*)(bb + 192 + co);
        const float4* b4 = (const float4*)(bb + 256 + co);
        float vi = bb[320 + il];

        float4 av0 = a4[0], av1 = a4[1];
        float sa0 = fmaf(s[0], av0.x, s[4]*av1.x);
        float sa1 = fmaf(s[1], av0.y, s[5]*av1.y);
        float sa2 = fmaf(s[2], av0.z, s[6]*av1.z);
        float sa3 = fmaf(s[3], av0.w, s[7]*av1.w);
        float sa = (sa0+sa1) + (sa2+sa3);
        sa += __shfl_xor_sync(0xffffffffu, sa, 1);
        sa += __shfl_xor_sync(0xffffffffu, sa, 2);
        sa += __shfl_xor_sync(0xffffffffu, sa, 4);

        float4 wv0 = w4[0], wv1 = w4[1];
        float4 kv0 = k4[0], kv1 = k4[1];
        float4 bv0 = b4[0], bv1 = b4[1];
        float4 qv0 = q4[0], qv1 = q4[1];

        float t0 = fmaf(s[0], wv0.x, fmaf(sa, bv0.x, vi*kv0.x));
        float t1 = fmaf(s[1], wv0.y, fmaf(sa, bv0.y, vi*kv0.y));
        float t2 = fmaf(s[2], wv0.z, fmaf(sa, bv0.z, vi*kv0.z));
        float t3 = fmaf(s[3], wv0.w, fmaf(sa, bv0.w, vi*kv0.w));
        float t4 = fmaf(s[4], wv1.x, fmaf(sa, bv1.x, vi*kv1.x));
        float t5 = fmaf(s[5], wv1.y, fmaf(sa, bv1.y, vi*kv1.y));
        float t6 = fmaf(s[6], wv1.z, fmaf(sa, bv1.z, vi*kv1.z));
        float t7 = fmaf(s[7], wv1.w, fmaf(sa, bv1.w, vi*kv1.w));
        s[0]=t0; s[1]=t1; s[2]=t2; s[3]=t3; s[4]=t4; s[5]=t5; s[6]=t6; s[7]=t7;

        float y0 = fmaf(t0, qv0.x, t4*qv1.x);
        float y1 = fmaf(t1, qv0.y, t5*qv1.y);
        float y2 = fmaf(t2, qv0.z, t6*qv1.z);
        float y3 = fmaf(t3, qv0.w, t7*qv1.w);
        float yi = (y0+y1) + (y2+y3);
        yi += __shfl_xor_sync(0xffffffffu, yi, 1);
        yi += __shfl_xor_sync(0xffffffffu, yi, 2);
        yi += __shfl_xor_sync(0xffffffffu, yi, 4);
        if (qd == 0) y[ybase + (size_t)t*NEC] = yi;

        if (++p == 3) p = 0;
    }
}

// ---------------------------------------------------------------------------
// GroupNorm + bonus + gate -> packed z
// ---------------------------------------------------------------------------
__global__ void gn_kernel(const float* __restrict__ y,
                          const float* __restrict__ r,
                          const float* __restrict__ k,
                          const float* __restrict__ v,
                          const float* __restrict__ gg,
                          const float* __restrict__ ln_w,
                          const float* __restrict__ ln_b,
                          const float* __restrict__ faaaa,
                          uint32_t* __restrict__ zpk)
{
    int m = blockIdx.x;
    int h = threadIdx.x >> 5;
    int lane = threadIdx.x & 31;
    size_t base = (size_t)m*NEC + h*HSZ;
    int c0 = h*HSZ + lane, c1 = c0 + 32;
    size_t i0 = base + lane, i1 = i0 + 32;

    float y0 = y[i0], y1 = y[i1];
    float mu = warp_sum(y0 + y1) * (1.f/64.f);
    float d0 = y0 - mu, d1 = y1 - mu;
    float var = warp_sum(d0*d0 + d1*d1) * (1.f/64.f);
    float rstd = rsqrtf(var + EPSGN);
    float yn0 = d0*rstd*ln_w[c0] + ln_b[c0];
    float yn1 = d1*rstd*ln_w[c1] + ln_b[c1];

    float r0 = r[i0], r1 = r[i1];
    float k0v = k[i0], k1v = k[i1];
    float rk = warp_sum(r0*k0v*faaaa[c0] + r1*k1v*faaaa[c1]);

    float v0 = v[i0], v1 = v[i1];
    zpk[i0] = packf((yn0 + rk*v0) * gg[i0]);
    zpk[i1] = packf((yn1 + rk*v1) * gg[i1]);
}

// ---------------------------------------------------------------------------
// Host side
// ---------------------------------------------------------------------------
extern "C" void kernel_launch(void* const* d_in, const int* in_sizes, int n_in,
                              void* d_out, int out_size)
{
    const float* x          = (const float*)d_in[0];
    const float* time_maa_x = (const float*)d_in[1];
    const float* time_maa   = (const float*)d_in[2];
    const float* maa_w1     = (const float*)d_in[3];
    const float* maa_w2     = (const float*)d_in[4];
    const float* decay_w1   = (const float*)d_in[5];
    const float* decay_w2   = (const float*)d_in[6];
    const float* aaa_w1     = (const float*)d_in[7];
    const float* aaa_w2     = (const float*)d_in[8];
    const float* kkk_w1     = (const float*)d_in[9];
    const float* kkk_w2     = (const float*)d_in[10];
    const float* gate_w1    = (const float*)d_in[11];
    const float* gate_w2    = (const float*)d_in[12];
    const float* ma_w1      = (const float*)d_in[13];
    const float* ma_w2      = (const float*)d_in[14];
    const float* mk_w1      = (const float*)d_in[15];
    const float* mk_w2      = (const float*)d_in[16];
    const float* time_decay = (const float*)d_in[17];
    const float* time_faaaa = (const float*)d_in[18];
    const float* time_aaaaa = (const float*)d_in[19];
    const float* time_misc_a= (const float*)d_in[20];
    const float* time_misc_k= (const float*)d_in[21];
    const float* Wr         = (const float*)d_in[22];
    const float* Wk         = (const float*)d_in[23];
    const float* Wv         = (const float*)d_in[24];
    const float* Wo         = (const float*)d_in[25];
    const float* ln_w       = (const float*)d_in[26];
    const float* ln_b       = (const float*)d_in[27];
    float* out = (float*)d_out;

    float *xx,*mix,*hmaa,*hgate,*hwaa,*hk;
    uint32_t *xm,*zpk; __half *whalf,*whid;
    float *r,*gg,*k,*v,*w,*kk,*a,*ma,*mk,*b,*y;
    cudaGetSymbolAddress((void**)&xx,   g_xx);
    cudaGetSymbolAddress((void**)&mix,  g_mix);
    cudaGetSymbolAddress((void**)&hmaa, g_hmaa);
    cudaGetSymbolAddress((void**)&hgate,g_hgate);
    cudaGetSymbolAddress((void**)&hwaa, g_hwaa);
    cudaGetSymbolAddress((void**)&hk,   g_hk);
    cudaGetSymbolAddress((void**)&xm,   g_xm);
    cudaGetSymbolAddress((void**)&whalf,g_whalf);
    cudaGetSymbolAddress((void**)&whid, g_whid);
    cudaGetSymbolAddress((void**)&zpk,  g_zpk);
    cudaGetSymbolAddress((void**)&r,    g_r);
    cudaGetSymbolAddress((void**)&gg,   g_gg);
    cudaGetSymbolAddress((void**)&k,    g_k);
    cudaGetSymbolAddress((void**)&v,    g_v);
    cudaGetSymbolAddress((void**)&w,    g_w);
    cudaGetSymbolAddress((void**)&kk,   g_kk);
    cudaGetSymbolAddress((void**)&a,    g_a);
    cudaGetSymbolAddress((void**)&ma,   g_ma);
    cudaGetSymbolAddress((void**)&mk,   g_mk);
    cudaGetSymbolAddress((void**)&b,    g_b);
    cudaGetSymbolAddress((void**)&y,    g_y);

    const size_t S = (size_t)MT*NEC;
    const uint32_t* xrg_pk = xm + 0*S;
    const uint32_t* xwa_pk = xm + 1*S;
    const uint32_t* xk_pk  = xm + 2*S;
    const uint32_t* xv_pk  = xm + 3*S;

    static bool attr_done = false;
    if (!attr_done) {
        cudaFuncSetAttribute(gemm_tc5, cudaFuncAttributeMaxDynamicSharedMemorySize,
                             2*G5_STG*4);
        attr_done = true;
    }
    const int g5_smem = 2*G5_STG*4;

    // 1) token shift
    shift_kernel<<<(unsigned)((S/4 + 255)/256), 256>>>(x, time_maa_x, xx, mix);

    // 2) weight packs
    wpack_kernel<<<(unsigned)((2*NM + 255)/256), 256>>>(Wr, Wk, Wv, Wo, whalf);
    wpack2_kernel<<<(unsigned)((3*HIDW + 255)/256), 256>>>(
        gate_w1, decay_w1, aaa_w1, ma_w1, kkk_w1, mk_w1, whid);

    // 3) maa hidden (fp32, 4 tiles)
    {
        NTArgs na = {};
        na.A = mix;
        for (int i = 0; i < 4; i++)
            na.t[i] = { maa_w1 + (size_t)i*32*NEC, hmaa + i*32 };
        lora_nt_kernel<<<dim3(4, MT/128), 128>>>(na);
    }

    // 4) xm fused (4 groups, all packed)
    xm_kernel<<<dim3(8, MT/128, 4), 256>>>(hmaa, maa_w2, x, xx, time_maa, xm);

    // 5) mega GEMM: r,k,v (z 0-2) + hidden slices (z 3)
    {
        G5Args ga = {};
        ga.nz = 3;
        ga.A[0] = xrg_pk; ga.B[0] = whalf + 0*NM; ga.C[0] = r;
        ga.A[1] = xk_pk;  ga.B[1] = whalf + 1*NM; ga.C[1] = k;
        ga.A[2] = xv_pk;  ga.B[2] = whalf + 2*NM; ga.C[2] = v;
        ga.HA[0] = xrg_pk; ga.HB[0] = whid + 0*HIDW; ga.HC[0] = hgate; ga.tanhN[0] = 128;
        ga.HA[1] = xwa_pk; ga.HB[1] = whid + 1*HIDW; ga.HC[1] = hwaa;  ga.tanhN[1] = 64;
        ga.HA[2] = xk_pk;  ga.HB[2] = whid + 2*HIDW; ga.HC[2] = hk;    ga.tanhN[2] = 16;
        gemm_tc5<<<dim3(8, 32, 4), 256, g5_smem>>>(ga, NEC);
    }

    // 6) second stage (6 groups from hidden slices)
    {
        NNArgs nn = {};
        nn.g[0] = { hgate, 128, 0,  gate_w2,  gg, 128, EPI_NONE, nullptr };
        nn.g[1] = { hwaa,  128, 0,  decay_w2, w,   64, EPI_W,    time_decay };
        nn.g[2] = { hk,    128, 0,  kkk_w2,   kk,  16, EPI_NONE, nullptr };
        nn.g[3] = { hwaa,  128, 64, aaa_w2,   a,   16, EPI_SIG,  time_aaaaa };
        nn.g[4] = { hwaa,  128, 80, ma_w2,    ma,  16, EPI_SIG,  time_misc_a };
        nn.g[5] = { hk,    128, 16, mk_w2,    mk,  16, EPI_SIG,  time_misc_k };
        lora_nn_kernel<<<dim3(8, MT/128, 6), 256>>>(nn);
    }

    // 7) prep (adds +k to kkraw before norm)
    prep_kernel<<<MT, 512>>>(k, kk, a, ma, mk, w, b);

    // 8) recurrence (2 blocks per head)
    wkv7_kernel<<<BATCH*NH*2, 256>>>(r, w, k, v, kk, b, y);

    // 9) groupnorm + bonus + gate -> packed z
    gn_kernel<<<MT, 512>>>(y, r, k, v, gg, ln_w, ln_b, time_faaaa, zpk);

    // 10) out = z @ Wo.T (2-product)
    {
        G5Args ga = {};
        ga.nz = 1;
        ga.A[0] = zpk; ga.B[0] = whalf + 3*NM; ga.C[0] = out;
        gemm_tc5<<<dim3(8, 32, 1), 256, g5_smem>>>(ga, NEC);
    }
}

// round 14
// speedup vs baseline: 1.2627x; 1.0341x over previous
#include <cuda_runtime.h>
#include <cuda_fp16.h>
#include <math.h>
#include <stdint.h>

// Problem constants
#define BATCH 4
#define TSEQ  1024
#define NEC   1024
#define NH    16
#define HSZ   64
#define MT    (BATCH*TSEQ)      // 4096 rows
#define EPSGN 0.00064f
#define NM    ((size_t)NEC*NEC) // 1M
#define HIDW  ((size_t)128*NEC) // one hidden weight slice

// ---------------------------------------------------------------------------
// Scratch (device globals)
// ---------------------------------------------------------------------------
__device__ float    g_xx   [(size_t)MT*NEC];
__device__ uint32_t g_mixpk[(size_t)MT*NEC];   // packed (hi,lo) mix
__device__ float    g_hmaa [(size_t)MT*128];
__device__ float    g_hgate[(size_t)MT*128];
__device__ float    g_hwaa [(size_t)MT*128];   // decay(0:64) aaa(64:80) ma(80:96)
__device__ float    g_hk   [(size_t)MT*128];   // kkk(0:16) mk(16:32)
__device__ uint32_t g_xm   [4][(size_t)MT*NEC]; // all packed (hi,lo) half2
__device__ __half   g_whalf[4*NM];             // Wr,Wk,Wv,Wo plain fp16
__device__ __half   g_whid [4*HIDW];           // hidden w1 slices fp16 (3) + maa_w1 (1)
__device__ uint32_t g_zpk  [(size_t)MT*NEC];
__device__ float    g_r    [(size_t)MT*NEC];
__device__ float    g_gg   [(size_t)MT*NEC];
__device__ float    g_k    [(size_t)MT*NEC];
__device__ float    g_v    [(size_t)MT*NEC];
__device__ float    g_w    [(size_t)MT*NEC];
__device__ float    g_kk   [(size_t)MT*NEC];
__device__ float    g_a    [(size_t)MT*NEC];
__device__ float    g_ma   [(size_t)MT*NEC];
__device__ float    g_mk   [(size_t)MT*NEC];
__device__ float    g_b    [(size_t)MT*NEC];
__device__ float    g_y    [(size_t)MT*NEC];

enum { EPI_NONE=0, EPI_W=3, EPI_SIG=5 };

// ---------------------------------------------------------------------------
// helpers
// ---------------------------------------------------------------------------
__device__ __forceinline__ uint32_t packf(float v){
    __half hi = __float2half_rn(v);
    __half lo = __float2half_rn(v - __half2float(hi));
    __half2 h2 = __halves2half2(hi, lo);
    return *reinterpret_cast<uint32_t*>(&h2);
}
__device__ __forceinline__ void mma_f16(float* c, const uint32_t* a, const uint32_t* b){
    asm volatile("mma.sync.aligned.m16n8k16.row.col.f32.f16.f16.f32 "
        "{%0,%1,%2,%3},{%4,%5,%6,%7},{%8,%9},{%0,%1,%2,%3};\n"
        : "+f"(c[0]), "+f"(c[1]), "+f"(c[2]), "+f"(c[3])
        : "r"(a[0]), "r"(a[1]), "r"(a[2]), "r"(a[3]), "r"(b[0]), "r"(b[1]));
}
__device__ __forceinline__ void cpa16(uint32_t dst, const void* src){
    asm volatile("cp.async.cg.shared.global [%0],[%1],16;\n"::"r"(dst),"l"(src));
}
__device__ __forceinline__ void cpa4(uint32_t dst, const void* src){
    asm volatile("cp.async.ca.shared.global [%0],[%1],4;\n"::"r"(dst),"l"(src));
}
#define CP_COMMIT() asm volatile("cp.async.commit_group;\n")
#define CP_WAIT0()  asm volatile("cp.async.wait_group 0;\n")
#define CP_WAIT1()  asm volatile("cp.async.wait_group 1;\n")

// ---------------------------------------------------------------------------
// Token shift (float4); mix written packed
// ---------------------------------------------------------------------------
__global__ void shift_kernel(const float* __restrict__ x,
                             const float* __restrict__ tmaax,
                             float* __restrict__ xx,
                             uint32_t* __restrict__ mixpk)
{
    size_t i4 = (size_t)blockIdx.x * blockDim.x + threadIdx.x;
    if (i4 >= (size_t)MT * NEC / 4) return;
    size_t idx = i4 * 4;
    int c = (int)(idx % NEC);
    size_t row = idx / NEC;
    int t = (int)(row % TSEQ);
    float4 xv = *(const float4*)&x[idx];
    float4 xp = (t > 0) ? *(const float4*)&x[idx - NEC] : make_float4(0,0,0,0);
    float4 tm = *(const float4*)&tmaax[c];
    float4 d  = make_float4(xp.x-xv.x, xp.y-xv.y, xp.z-xv.z, xp.w-xv.w);
    *(float4*)&xx[idx] = d;
    uint4 m;
    m.x = packf(fmaf(d.x, tm.x, xv.x));
    m.y = packf(fmaf(d.y, tm.y, xv.y));
    m.z = packf(fmaf(d.z, tm.z, xv.z));
    m.w = packf(fmaf(d.w, tm.w, xv.w));
    *(uint4*)&mixpk[idx] = m;
}

// ---------------------------------------------------------------------------
// Weight pack: Wr/Wk/Wv/Wo -> fp16 (half2 stores)
// ---------------------------------------------------------------------------
__global__ void wpack_kernel(const float* __restrict__ Wr, const float* __restrict__ Wk,
                             const float* __restrict__ Wv, const float* __restrict__ Wo,
                             __half* __restrict__ whalf)
{
    size_t i = (size_t)blockIdx.x * blockDim.x + threadIdx.x;   // 2 elems each
    if (i >= 2*NM) return;
    int seg = (int)(i >> 19);
    size_t off2 = (i & ((NM>>1) - 1)) * 2;
    const float* src = (seg==0) ? Wr : (seg==1) ? Wk : (seg==2) ? Wv : Wo;
    float2 v = *(const float2*)&src[off2];
    __half2 h = __halves2half2(__float2half_rn(v.x), __float2half_rn(v.y));
    *(__half2*)&whalf[(size_t)seg*NM + off2] = h;
}

// ---------------------------------------------------------------------------
// Hidden weight pack: 4 padded slices [128][1024] fp16
//   s0 = gate_w1(128); s1 = decay(64)+aaa(16)+ma(16)+pad(32);
//   s2 = kkk(16)+mk(16)+pad(96); s3 = maa_w1(128)
// ---------------------------------------------------------------------------
__global__ void wpack2_kernel(const float* __restrict__ gate_w1,
                              const float* __restrict__ decay_w1,
                              const float* __restrict__ aaa_w1,
                              const float* __restrict__ ma_w1,
                              const float* __restrict__ kkk_w1,
                              const float* __restrict__ mk_w1,
                              const float* __restrict__ maa_w1,
                              __half* __restrict__ whid)
{
    size_t i = (size_t)blockIdx.x * blockDim.x + threadIdx.x;
    if (i >= 4*HIDW) return;
    int slice = (int)(i / HIDW);
    size_t rem = i - (size_t)slice*HIDW;
    int row = (int)(rem >> 10);
    float v = 0.f;
    if (slice == 0) v = gate_w1[rem];
    else if (slice == 1) {
        if (row < 64)      v = decay_w1[rem];
        else if (row < 80) v = aaa_w1[rem - (size_t)64*NEC];
        else if (row < 96) v = ma_w1[rem - (size_t)80*NEC];
    } else if (slice == 2) {
        if (row < 16)      v = kkk_w1[rem];
        else if (row < 32) v = mk_w1[rem - (size_t)16*NEC];
    } else {
        v = maa_w1[rem];
    }
    whid[i] = __float2half_rn(v);
}

// ---------------------------------------------------------------------------
// 2-product NT GEMM: grid (gx, 32, nz + maybe-hidden).
//   z < nz: C[4096,1024] = (Ah+Al) * Bh^T
//   z >= nz: blockIdx.x = hidden slice (others exit); N=128, tanh-prefix epi.
// ---------------------------------------------------------------------------
#define G5_LDSW 36
#define G5_AW   (128*G5_LDSW)
#define G5_LDHB 40
#define G5_BW   (128*G5_LDHB/2)
#define G5_STG  (G5_AW + G5_BW)

struct G5Args {
    const uint32_t* A[3]; const __half* B[3]; float* C[3];
    const uint32_t* HA[3]; const __half* HB[3]; float* HC[3]; int tanhN[3];
    int nz;
};

__global__ __launch_bounds__(256, 2)
void gemm_tc5(G5Args args, int K)
{
    extern __shared__ uint32_t sm5[];
    const int z = blockIdx.z;
    const uint32_t* Apk; const __half* Bhp; float* C;
    int bn0, ldc, tanhN;
    if (z < args.nz) {
        Apk = args.A[z]; Bhp = args.B[z]; C = args.C[z];
        bn0 = blockIdx.x*128; ldc = NEC; tanhN = -1;
    } else {
        int s = blockIdx.x;
        if (s >= 3) return;
        Apk = args.HA[s]; Bhp = args.HB[s]; C = args.HC[s];
        if (!C) return;
        bn0 = 0; ldc = 128; tanhN = args.tanhN[s];
    }
    const int tid = threadIdx.x;
    const int bm0 = blockIdx.y*128;
    const int warp = tid>>5, lane = tid&31, grp = lane>>2, q = lane&3;
    const int wm = (warp&1)*64, wn = (warp>>1)*32;
    const uint32_t sbase = (uint32_t)__cvta_generic_to_shared(sm5);

    float acc[4][4][4];
    #pragma unroll
    for (int mi=0;mi<4;mi++)
        #pragma unroll
        for (int ni=0;ni<4;ni++)
            #pragma unroll
            for (int e=0;e<4;e++) acc[mi][ni][e]=0.f;

    const uint32_t* asrc[4]; uint32_t adst[4];
    #pragma unroll
    for (int l = 0; l < 4; l++) {
        int idx = tid + l*256;
        int r = idx >> 3, c4 = idx & 7;
        asrc[l] = Apk + (size_t)(bm0+r)*K + c4*4;
        adst[l] = sbase + (uint32_t)(r*G5_LDSW + c4*4)*4;
    }
    const __half* bsrc[2]; uint32_t bdst[2];
    #pragma unroll
    for (int l = 0; l < 2; l++) {
        int idx = tid + l*256;
        int r = idx >> 2, c4 = idx & 3;
        bsrc[l] = Bhp + (size_t)(bn0+r)*K + c4*8;
        bdst[l] = sbase + G5_AW*4 + (uint32_t)(r*G5_LDHB + c4*8)*2;
    }

#define G5_LOAD(st, kb) do {                                   \
        uint32_t _o = (st)*G5_STG*4;                           \
        _Pragma("unroll")                                      \
        for (int l = 0; l < 4; l++)                            \
            cpa16(adst[l] + _o, asrc[l] + (kb));               \
        _Pragma("unroll")                                      \
        for (int l = 0; l < 2; l++)                            \
            cpa16(bdst[l] + _o, bsrc[l] + (kb));               \
    } while(0)

    G5_LOAD(0, 0); CP_COMMIT();

    int p = 0;
    for (int kb = 0; kb < K; kb += 32) {
        CP_WAIT0();
        __syncthreads();
        if (kb + 32 < K) { G5_LOAD(p^1, kb+32); CP_COMMIT(); }

        const uint32_t* SA = sm5 + p*G5_STG;
        const __half*   SB = (const __half*)(sm5 + p*G5_STG + G5_AW);

        #pragma unroll
        for (int kc = 0; kc < 32; kc += 16) {
            uint32_t ah[4][4], al[4][4], bh[4][2];
            #pragma unroll
            for (int mi = 0; mi < 4; mi++) {
                int r0 = (wm + mi*16 + grp)*G5_LDSW + kc + 2*q;
                uint2 w0 = *(const uint2*)&SA[r0];
                uint2 w1 = *(const uint2*)&SA[r0 + 8*G5_LDSW];
                uint2 w2 = *(const uint2*)&SA[r0 + 8];
                uint2 w3 = *(const uint2*)&SA[r0 + 8*G5_LDSW + 8];
                ah[mi][0]=__byte_perm(w0.x,w0.y,0x5410); al[mi][0]=__byte_perm(w0.x,w0.y,0x7632);
                ah[mi][1]=__byte_perm(w1.x,w1.y,0x5410); al[mi][1]=__byte_perm(w1.x,w1.y,0x7632);
                ah[mi][2]=__byte_perm(w2.x,w2.y,0x5410); al[mi][2]=__byte_perm(w2.x,w2.y,0x7632);
                ah[mi][3]=__byte_perm(w3.x,w3.y,0x5410); al[mi][3]=__byte_perm(w3.x,w3.y,0x7632);
            }
            #pragma unroll
            for (int ni = 0; ni < 4; ni++) {
                int c0 = (wn + ni*8 + grp)*G5_LDHB + kc + 2*q;
                bh[ni][0] = *(const uint32_t*)&SB[c0];
                bh[ni][1] = *(const uint32_t*)&SB[c0 + 8];
            }
            #pragma unroll
            for (int mi = 0; mi < 4; mi++)
                #pragma unroll
                for (int ni = 0; ni < 4; ni++) {
                    mma_f16(acc[mi][ni], ah[mi], bh[ni]);
                    mma_f16(acc[mi][ni], al[mi], bh[ni]);
                }
        }
        __syncthreads();
        p ^= 1;
    }

    #pragma unroll
    for (int mi = 0; mi < 4; mi++) {
        int row0 = bm0 + wm + mi*16 + grp;
        #pragma unroll
        for (int ni = 0; ni < 4; ni++) {
            int col = bn0 + wn + ni*8 + 2*q;
            float e0 = acc[mi][ni][0], e1 = acc[mi][ni][1];
            float e2 = acc[mi][ni][2], e3 = acc[mi][ni][3];
            if (tanhN >= 0) {
                if (col   < tanhN) { e0 = tanhf(e0); e2 = tanhf(e2); }
                if (col+1 < tanhN) { e1 = tanhf(e1); e3 = tanhf(e3); }
            }
            *(float2*)&C[(size_t)row0*ldc + col]     = make_float2(e0, e1);
            *(float2*)&C[(size_t)(row0+8)*ldc + col] = make_float2(e2, e3);
        }
    }
#undef G5_LOAD
}

// ---------------------------------------------------------------------------
// Fused xm kernel: val = x + xx*(Ag @ Bg + time_maa[g]); all groups packed.
// ---------------------------------------------------------------------------
__global__ __launch_bounds__(256, 2)
void xm_kernel(const float* __restrict__ hmaa,
               const float* __restrict__ maa_w2,
               const float* __restrict__ x,
               const float* __restrict__ xx,
               const float* __restrict__ time_maa,
               uint32_t* __restrict__ xmbase)
{
    constexpr int BM=128, BN=128, BK=32;
    __shared__ float As[BK][BM+1];
    __shared__ float Bs[BK][BN];
    const int g = blockIdx.z;
    const float* A = hmaa + g*32;
    const float* B = maa_w2 + (size_t)g*32*NEC;
    uint32_t* C = xmbase + (size_t)g*MT*NEC;
    const float* tm = time_maa + g*NEC;
    const int bm0 = blockIdx.y*BM, bn0 = blockIdx.x*BN;
    const int tid = threadIdx.x;
    const int tx = tid & 15, ty = tid >> 4;

    float acc[8][8];
    #pragma unroll
    for (int i=0;i<8;i++)
        #pragma unroll
        for (int j=0;j<8;j++) acc[i][j]=0.f;

    #pragma unroll
    for (int l = 0; l < 4; l++) {
        int idx = tid + l*256;
        int r = idx >> 3, c = (idx & 7)*4;
        float4 val = *(const float4*)(A + (size_t)(bm0+r)*128 + c);
        As[c+0][r]=val.x; As[c+1][r]=val.y; As[c+2][r]=val.z; As[c+3][r]=val.w;
    }
    #pragma unroll
    for (int l = 0; l < 4; l++) {
        int idx = tid + l*256;
        int r = idx >> 5, c = (idx & 31)*4;
        *(float4*)&Bs[r][c] = *(const float4*)(B + (size_t)r*NEC + bn0 + c);
    }
    __syncthreads();
    #pragma unroll
    for (int kk = 0; kk < BK; kk++) {
        float rm[8], rn[8];
        #pragma unroll
        for (int i=0;i<8;i++) rm[i] = As[kk][ty*8+i];
        #pragma unroll
        for (int j=0;j<8;j++) rn[j] = Bs[kk][tx*8+j];
        #pragma unroll
        for (int i=0;i<8;i++)
            #pragma unroll
            for (int j=0;j<8;j++) acc[i][j] = fmaf(rm[i], rn[j], acc[i][j]);
    }
    #pragma unroll
    for (int i=0;i<8;i++) {
        int row = bm0 + ty*8 + i;
        #pragma unroll
        for (int j=0;j<8;j+=2) {
            int col = bn0 + tx*8 + j;
            size_t idx = (size_t)row*NEC + col;
            float2 xv = *(const float2*)&x[idx];
            float2 dv = *(const float2*)&xx[idx];
            float v0 = fmaf(dv.x, acc[i][j]   + tm[col],   xv.x);
            float v1 = fmaf(dv.y, acc[i][j+1] + tm[col+1], xv.y);
            *(uint2*)&C[idx] = make_uint2(packf(v0), packf(v1));
        }
    }
}

// ---------------------------------------------------------------------------
// Grouped second-stage NN kernel (A with lda + column offset)
// ---------------------------------------------------------------------------
struct NNGroup { const float* A; int lda; int koff; const float* B; float* C;
                 int K; int epi; const float* e2; };
struct NNArgs { NNGroup g[6]; };

__global__ __launch_bounds__(256)
void lora_nn_kernel(NNArgs args)
{
    constexpr int BM=128, BN=128, BK=16;
    __shared__ float As[BK][BM+1];
    __shared__ float Bs[BK][BN];
    NNGroup grp = args.g[blockIdx.z];
    const int K = grp.K;
    const int bm0 = blockIdx.y*BM, bn0 = blockIdx.x*BN;
    const int tid = threadIdx.x;
    const int tx = tid & 15, ty = tid >> 4;

    float acc[8][8];
    #pragma unroll
    for (int i=0;i<8;i++)
        #pragma unroll
        for (int j=0;j<8;j++) acc[i][j]=0.f;

    for (int kb = 0; kb < K; kb += BK) {
        #pragma unroll
        for (int l = 0; l < 2; l++) {
            int idx = tid + l*256;
            int r = idx >> 2, c = (idx & 3)*4;
            float4 val = *(const float4*)(grp.A + (size_t)(bm0+r)*grp.lda + grp.koff + kb + c);
            As[c+0][r]=val.x; As[c+1][r]=val.y; As[c+2][r]=val.z; As[c+3][r]=val.w;
        }
        #pragma unroll
        for (int l = 0; l < 2; l++) {
            int idx = tid + l*256;
            int r = idx >> 5, c = (idx & 31)*4;
            *(float4*)&Bs[r][c] = *(const float4*)(grp.B + (size_t)(kb+r)*NEC + bn0 + c);
        }
        __syncthreads();
        #pragma unroll
        for (int kk = 0; kk < BK; kk++) {
            float rm[8], rn[8];
            #pragma unroll
            for (int i=0;i<8;i++) rm[i] = As[kk][ty*8+i];
            #pragma unroll
            for (int j=0;j<8;j++) rn[j] = Bs[kk][tx*8+j];
            #pragma unroll
            for (int i=0;i<8;i++)
                #pragma unroll
                for (int j=0;j<8;j++) acc[i][j] = fmaf(rm[i], rn[j], acc[i][j]);
        }
        __syncthreads();
    }
    #pragma unroll
    for (int i=0;i<8;i++) {
        int row = bm0 + ty*8 + i;
        #pragma unroll
        for (int j=0;j<8;j++) {
            int col = bn0 + tx*8 + j;
            size_t idx = (size_t)row*NEC + col;
            float vv = acc[i][j], outv;
            switch (grp.epi) {
                case EPI_W: {
                    float tt = -(grp.e2[col] + vv);
                    float sp = (tt > 15.f) ? tt : log1pf(expf(tt));
                    outv = -sp - 0.5f;
                } break;
                case EPI_SIG: {
                    float u = grp.e2[col] + vv;
                    outv = 1.f / (1.f + expf(-u));
                } break;
                default: outv = vv;
            }
            grp.C[idx] = outv;
        }
    }
}

// ---------------------------------------------------------------------------
// warp sum
// ---------------------------------------------------------------------------
__device__ __forceinline__ float warp_sum(float v)
{
    #pragma unroll
    for (int o = 16; o > 0; o >>= 1) v += __shfl_xor_sync(0xffffffffu, v, o);
    return v;
}

// ---------------------------------------------------------------------------
// prep: kk = normalize(kkraw + k); b = -kk*a; k final; w transform
// ---------------------------------------------------------------------------
__global__ void prep_kernel(float* kptr, float* kkptr,
                            const float* __restrict__ a,
                            const float* __restrict__ ma,
                            const float* __restrict__ mk,
                            float* wptr,
                            float* __restrict__ b)
{
    int m = blockIdx.x;
    int h = threadIdx.x >> 5;
    int lane = threadIdx.x & 31;
    size_t base = (size_t)m*NEC + h*HSZ;
    size_t i0 = base + lane, i1 = i0 + 32;

    float k0v = kptr[i0], k1v = kptr[i1];
    float kk0 = kkptr[i0] + k0v, kk1 = kkptr[i1] + k1v;
    float ss = warp_sum(kk0*kk0 + kk1*kk1);
    float inv = 1.f / fmaxf(sqrtf(ss), 1e-12f);
    float n0 = kk0*inv, n1 = kk1*inv;
    kkptr[i0] = n0; kkptr[i1] = n1;

    float a0 = a[i0], a1 = a[i1];
    b[i0] = -n0*a0; b[i1] = -n1*a1;

    float ma0 = ma[i0], ma1 = ma[i1];
    float w0 = wptr[i0], w1 = wptr[i1];
    float mk0 = mk[i0], mk1 = mk[i1];
    kptr[i0] = k0v * (ma0 + a0*(1.f - ma0)) * expf(w0*mk0);
    kptr[i1] = k1v * (ma1 + a1*(1.f - ma1)) * expf(w1*mk1);
    wptr[i0] = expf(-expf(w0));
    wptr[i1] = expf(-expf(w1));
}

// ---------------------------------------------------------------------------
// RWKV7 recurrence v4: 2 blocks per head; 32 rows x 8-way column split;
// 3-stage cp.async ring.
// ---------------------------------------------------------------------------
__global__ __launch_bounds__(256)
void wkv7_kernel(const float* __restrict__ q, const float* __restrict__ w,
                 const float* __restrict__ k, const float* __restrict__ v,
                 const float* __restrict__ a, const float* __restrict__ b,
                 float* __restrict__ y)
{
    const int blk = blockIdx.x;            // 0..127
    const int bh = blk >> 1, rh = blk & 1;
    const int batch = bh >> 4, h = bh & 15;
    const int tid = threadIdx.x;
    const int il = tid >> 3, qd = tid & 7;

    __shared__ __align__(16) float buf[3][352];

    float s[8];
    #pragma unroll
    for (int j = 0; j < 8; j++) s[j] = 0.f;

    const size_t base = (size_t)batch * TSEQ * NEC + (size_t)h * HSZ;

    const float* table[4] = {q, w, k, a};
    const float* s0 = table[tid>>6] + base + (tid & 63);
    const float* s1 = nullptr;
    if (tid < 64)       s1 = b + base + tid;
    else if (tid < 96)  s1 = v + base + rh*32 + (tid - 64);
    const uint32_t sb = (uint32_t)__cvta_generic_to_shared(buf);
    const uint32_t d0 = sb + (uint32_t)tid*4;
    const uint32_t d1 = sb + (uint32_t)(256 + tid)*4;
    const uint32_t STRB = 352*4;

    cpa4(d0, s0);
    if (tid < 96) cpa4(d1, s1);
    CP_COMMIT();
    cpa4(d0 + STRB, s0 + NEC);
    if (tid < 96) cpa4(d1 + STRB, s1 + NEC);
    CP_COMMIT();

    const size_t ybase = base + (size_t)rh*32 + il;

    int p = 0;
    for (int t = 0; t < TSEQ; t++) {
        CP_WAIT1();
        __syncthreads();

        {
            int st = p + 2; if (st >= 3) st -= 3;
            if (t + 2 < TSEQ) {
                size_t o = (size_t)(t+2)*NEC;
                cpa4(d0 + (uint32_t)st*STRB, s0 + o);
                if (tid < 96) cpa4(d1 + (uint32_t)st*STRB, s1 + o);
            }
            CP_COMMIT();
        }

        const float* bb = buf[p];
        const int co = qd*8;
        const float4* q4 = (const float4*)(bb +   0 + co);
        const float4* w4 = (const float4*)(bb +  64 + co);
        const float4* k4 = (const float4*)(bb + 128 + co);
        const float4* a4 = (const float4*)(bb + 192 + co);
        const float4* b4 = (const float4*)(bb + 256 + co);
        float vi = bb[320 + il];

        float4 av0 = a4[0], av1 = a4[1];
        float sa0 = fmaf(s[0], av0.x, s[4]*av1.x);
        float sa1 = fmaf(s[1], av0.y, s[5]*av1.y);
        float sa2 = fmaf(s[2], av0.z, s[6]*av1.z);
        float sa3 = fmaf(s[3], av0.w, s[7]*av1.w);
        float sa = (sa0+sa1) + (sa2+sa3);
        sa += __shfl_xor_sync(0xffffffffu, sa, 1);
        sa += __shfl_xor_sync(0xffffffffu, sa, 2);
        sa += __shfl_xor_sync(0xffffffffu, sa, 4);

        float4 wv0 = w4[0], wv1 = w4[1];
        float4 kv0 = k4[0], kv1 = k4[1];
        float4 bv0 = b4[0], bv1 = b4[1];
        float4 qv0 = q4[0], qv1 = q4[1];

        float t0 = fmaf(s[0], wv0.x, fmaf(sa, bv0.x, vi*kv0.x));
        float t1 = fmaf(s[1], wv0.y, fmaf(sa, bv0.y, vi*kv0.y));
        float t2 = fmaf(s[2], wv0.z, fmaf(sa, bv0.z, vi*kv0.z));
        float t3 = fmaf(s[3], wv0.w, fmaf(sa, bv0.w, vi*kv0.w));
        float t4 = fmaf(s[4], wv1.x, fmaf(sa, bv1.x, vi*kv1.x));
        float t5 = fmaf(s[5], wv1.y, fmaf(sa, bv1.y, vi*kv1.y));
        float t6 = fmaf(s[6], wv1.z, fmaf(sa, bv1.z, vi*kv1.z));
        float t7 = fmaf(s[7], wv1.w, fmaf(sa, bv1.w, vi*kv1.w));
        s[0]=t0; s[1]=t1; s[2]=t2; s[3]=t3; s[4]=t4; s[5]=t5; s[6]=t6; s[7]=t7;

        float y0 = fmaf(t0, qv0.x, t4*qv1.x);
        float y1 = fmaf(t1, qv0.y, t5*qv1.y);
        float y2 = fmaf(t2, qv0.z, t6*qv1.z);
        float y3 = fmaf(t3, qv0.w, t7*qv1.w);
        float yi = (y0+y1) + (y2+y3);
        yi += __shfl_xor_sync(0xffffffffu, yi, 1);
        yi += __shfl_xor_sync(0xffffffffu, yi, 2);
        yi += __shfl_xor_sync(0xffffffffu, yi, 4);
        if (qd == 0) y[ybase + (size_t)t*NEC] = yi;

        if (++p == 3) p = 0;
    }
}

// ---------------------------------------------------------------------------
// GroupNorm + bonus + gate -> packed z
// ---------------------------------------------------------------------------
__global__ void gn_kernel(const float* __restrict__ y,
                          const float* __restrict__ r,
                          const float* __restrict__ k,
                          const float* __restrict__ v,
                          const float* __restrict__ gg,
                          const float* __restrict__ ln_w,
                          const float* __restrict__ ln_b,
                          const float* __restrict__ faaaa,
                          uint32_t* __restrict__ zpk)
{
    int m = blockIdx.x;
    int h = threadIdx.x >> 5;
    int lane = threadIdx.x & 31;
    size_t base = (size_t)m*NEC + h*HSZ;
    int c0 = h*HSZ + lane, c1 = c0 + 32;
    size_t i0 = base + lane, i1 = i0 + 32;

    float y0 = y[i0], y1 = y[i1];
    float mu = warp_sum(y0 + y1) * (1.f/64.f);
    float d0 = y0 - mu, d1 = y1 - mu;
    float var = warp_sum(d0*d0 + d1*d1) * (1.f/64.f);
    float rstd = rsqrtf(var + EPSGN);
    float yn0 = d0*rstd*ln_w[c0] + ln_b[c0];
    float yn1 = d1*rstd*ln_w[c1] + ln_b[c1];

    float r0 = r[i0], r1 = r[i1];
    float k0v = k[i0], k1v = k[i1];
    float rk = warp_sum(r0*k0v*faaaa[c0] + r1*k1v*faaaa[c1]);

    float v0 = v[i0], v1 = v[i1];
    zpk[i0] = packf((yn0 + rk*v0) * gg[i0]);
    zpk[i1] = packf((yn1 + rk*v1) * gg[i1]);
}

// ---------------------------------------------------------------------------
// Host side
// ---------------------------------------------------------------------------
extern "C" void kernel_launch(void* const* d_in, const int* in_sizes, int n_in,
                              void* d_out, int out_size)
{
    const float* x          = (const float*)d_in[0];
    const float* time_maa_x = (const float*)d_in[1];
    const float* time_maa   = (const float*)d_in[2];
    const float* maa_w1     = (const float*)d_in[3];
    const float* maa_w2     = (const float*)d_in[4];
    const float* decay_w1   = (const float*)d_in[5];
    const float* decay_w2   = (const float*)d_in[6];
    const float* aaa_w1     = (const float*)d_in[7];
    const float* aaa_w2     = (const float*)d_in[8];
    const float* kkk_w1     = (const float*)d_in[9];
    const float* kkk_w2     = (const float*)d_in[10];
    const float* gate_w1    = (const float*)d_in[11];
    const float* gate_w2    = (const float*)d_in[12];
    const float* ma_w1      = (const float*)d_in[13];
    const float* ma_w2      = (const float*)d_in[14];
    const float* mk_w1      = (const float*)d_in[15];
    const float* mk_w2      = (const float*)d_in[16];
    const float* time_decay = (const float*)d_in[17];
    const float* time_faaaa = (const float*)d_in[18];
    const float* time_aaaaa = (const float*)d_in[19];
    const float* time_misc_a= (const float*)d_in[20];
    const float* time_misc_k= (const float*)d_in[21];
    const float* Wr         = (const float*)d_in[22];
    const float* Wk         = (const float*)d_in[23];
    const float* Wv         = (const float*)d_in[24];
    const float* Wo         = (const float*)d_in[25];
    const float* ln_w       = (const float*)d_in[26];
    const float* ln_b       = (const float*)d_in[27];
    float* out = (float*)d_out;

    float *xx,*hmaa,*hgate,*hwaa,*hk;
    uint32_t *mixpk,*xm,*zpk; __half *whalf,*whid;
    float *r,*gg,*k,*v,*w,*kk,*a,*ma,*mk,*b,*y;
    cudaGetSymbolAddress((void**)&xx,   g_xx);
    cudaGetSymbolAddress((void**)&mixpk,g_mixpk);
    cudaGetSymbolAddress((void**)&hmaa, g_hmaa);
    cudaGetSymbolAddress((void**)&hgate,g_hgate);
    cudaGetSymbolAddress((void**)&hwaa, g_hwaa);
    cudaGetSymbolAddress((void**)&hk,   g_hk);
    cudaGetSymbolAddress((void**)&xm,   g_xm);
    cudaGetSymbolAddress((void**)&whalf,g_whalf);
    cudaGetSymbolAddress((void**)&whid, g_whid);
    cudaGetSymbolAddress((void**)&zpk,  g_zpk);
    cudaGetSymbolAddress((void**)&r,    g_r);
    cudaGetSymbolAddress((void**)&gg,   g_gg);
    cudaGetSymbolAddress((void**)&k,    g_k);
    cudaGetSymbolAddress((void**)&v,    g_v);
    cudaGetSymbolAddress((void**)&w,    g_w);
    cudaGetSymbolAddress((void**)&kk,   g_kk);
    cudaGetSymbolAddress((void**)&a,    g_a);
    cudaGetSymbolAddress((void**)&ma,   g_ma);
    cudaGetSymbolAddress((void**)&mk,   g_mk);
    cudaGetSymbolAddress((void**)&b,    g_b);
    cudaGetSymbolAddress((void**)&y,    g_y);

    const size_t S = (size_t)MT*NEC;
    const uint32_t* xrg_pk = xm + 0*S;
    const uint32_t* xwa_pk = xm + 1*S;
    const uint32_t* xk_pk  = xm + 2*S;
    const uint32_t* xv_pk  = xm + 3*S;

    static bool attr_done = false;
    if (!attr_done) {
        cudaFuncSetAttribute(gemm_tc5, cudaFuncAttributeMaxDynamicSharedMemorySize,
                             2*G5_STG*4);
        attr_done = true;
    }
    const int g5_smem = 2*G5_STG*4;

    // 1) token shift (mix packed)
    shift_kernel<<<(unsigned)((S/4 + 255)/256), 256>>>(x, time_maa_x, xx, mixpk);

    // 2) weight packs
    wpack_kernel<<<(unsigned)((2*NM + 255)/256), 256>>>(Wr, Wk, Wv, Wo, whalf);
    wpack2_kernel<<<(unsigned)((4*HIDW + 255)/256), 256>>>(
        gate_w1, decay_w1, aaa_w1, ma_w1, kkk_w1, mk_w1, maa_w1, whid);

    // 3) maa hidden on tensor cores: hmaa = tanh(mix @ maa_w1^T)
    {
        G5Args ga = {};
        ga.nz = 0;
        ga.HA[0] = mixpk; ga.HB[0] = whid + 3*HIDW; ga.HC[0] = hmaa; ga.tanhN[0] = 128;
        gemm_tc5<<<dim3(1, 32, 1), 256, g5_smem>>>(ga, NEC);
    }

    // 4) xm fused (4 groups, all packed)
    xm_kernel<<<dim3(8, MT/128, 4), 256>>>(hmaa, maa_w2, x, xx, time_maa, xm);

    // 5) mega GEMM: r,k,v (z 0-2) + hidden slices (z 3)
    {
        G5Args ga = {};
        ga.nz = 3;
        ga.A[0] = xrg_pk; ga.B[0] = whalf + 0*NM; ga.C[0] = r;
        ga.A[1] = xk_pk;  ga.B[1] = whalf + 1*NM; ga.C[1] = k;
        ga.A[2] = xv_pk;  ga.B[2] = whalf + 2*NM; ga.C[2] = v;
        ga.HA[0] = xrg_pk; ga.HB[0] = whid + 0*HIDW; ga.HC[0] = hgate; ga.tanhN[0] = 128;
        ga.HA[1] = xwa_pk; ga.HB[1] = whid + 1*HIDW; ga.HC[1] = hwaa;  ga.tanhN[1] = 64;
        ga.HA[2] = xk_pk;  ga.HB[2] = whid + 2*HIDW; ga.HC[2] = hk;    ga.tanhN[2] = 16;
        gemm_tc5<<<dim3(8, 32, 4), 256, g5_smem>>>(ga, NEC);
    }

    // 6) second stage (6 groups from hidden slices)
    {
        NNArgs nn = {};
        nn.g[0] = { hgate, 128, 0,  gate_w2,  gg, 128, EPI_NONE, nullptr };
        nn.g[1] = { hwaa,  128, 0,  decay_w2, w,   64, EPI_W,    time_decay };
        nn.g[2] = { hk,    128, 0,  kkk_w2,   kk,  16, EPI_NONE, nullptr };
        nn.g[3] = { hwaa,  128, 64, aaa_w2,   a,   16, EPI_SIG,  time_aaaaa };
        nn.g[4] = { hwaa,  128, 80, ma_w2,    ma,  16, EPI_SIG,  time_misc_a };
        nn.g[5] = { hk,    128, 16, mk_w2,    mk,  16, EPI_SIG,  time_misc_k };
        lora_nn_kernel<<<dim3(8, MT/128, 6), 256>>>(nn);
    }

    // 7) prep (adds +k to kkraw before norm)
    prep_kernel<<<MT, 512>>>(k, kk, a, ma, mk, w, b);

    // 8) recurrence (2 blocks per head)
    wkv7_kernel<<<BATCH*NH*2, 256>>>(r, w, k, v, kk, b, y);

    // 9) groupnorm + bonus + gate -> packed z
    gn_kernel<<<MT, 512>>>(y, r, k, v, gg, ln_w, ln_b, time_faaaa, zpk);

    // 10) out = z @ Wo.T (2-product)
    {
        G5Args ga = {};
        ga.nz = 1;
        ga.A[0] = zpk; ga.B[0] = whalf + 3*NM; ga.C[0] = out;
        gemm_tc5<<<dim3(8, 32, 1), 256, g5_smem>>>(ga, NEC);
    }
}

// round 15
// speedup vs baseline: 1.3920x; 1.1024x over previous
#include <cuda_runtime.h>
#include <cuda_fp16.h>
#include <math.h>
#include <stdint.h>

// Problem constants
#define BATCH 4
#define TSEQ  1024
#define NEC   1024
#define NH    16
#define HSZ   64
#define MT    (BATCH*TSEQ)      // 4096 rows
#define EPSGN 0.00064f
#define NM    ((size_t)NEC*NEC) // 1M
#define HIDW  ((size_t)128*NEC) // one hidden weight slice
#define HME   ((size_t)MT*128)  // hidden matrix elems

// ---------------------------------------------------------------------------
// Scratch (device globals)
// ---------------------------------------------------------------------------
__device__ float    g_xx   [(size_t)MT*NEC];
__device__ uint32_t g_mixpk[(size_t)MT*NEC];   // packed (hi,lo) mix
__device__ float    g_hpart[4][HME];           // maa split-K partials
__device__ float    g_hmaa [HME];
__device__ float    g_hgate[HME];
__device__ float    g_hwaa [HME];              // decay(0:64) aaa(64:80) ma(80:96)
__device__ float    g_hk   [HME];              // kkk(0:16) mk(16:32)
__device__ uint32_t g_xm   [4][(size_t)MT*NEC]; // all packed (hi,lo) half2
__device__ __half   g_whalf[4*NM];             // Wr,Wk,Wv,Wo plain fp16
__device__ __half   g_whid [4*HIDW];           // hidden w1 slices fp16 (3) + maa_w1 (1)
__device__ uint32_t g_zpk  [(size_t)MT*NEC];
__device__ float    g_r    [(size_t)MT*NEC];
__device__ float    g_gg   [(size_t)MT*NEC];
__device__ float    g_k    [(size_t)MT*NEC];
__device__ float    g_v    [(size_t)MT*NEC];
__device__ float    g_w    [(size_t)MT*NEC];
__device__ float    g_kk   [(size_t)MT*NEC];
__device__ float    g_a    [(size_t)MT*NEC];
__device__ float    g_ma   [(size_t)MT*NEC];
__device__ float    g_mk   [(size_t)MT*NEC];
__device__ float    g_b    [(size_t)MT*NEC];
__device__ float    g_y    [(size_t)MT*NEC];

enum { EPI_NONE=0, EPI_W=3, EPI_SIG=5 };

// ---------------------------------------------------------------------------
// helpers
// ---------------------------------------------------------------------------
__device__ __forceinline__ uint32_t packf(float v){
    __half hi = __float2half_rn(v);
    __half lo = __float2half_rn(v - __half2float(hi));
    __half2 h2 = __halves2half2(hi, lo);
    return *reinterpret_cast<uint32_t*>(&h2);
}
__device__ __forceinline__ void mma_f16(float* c, const uint32_t* a, const uint32_t* b){
    asm volatile("mma.sync.aligned.m16n8k16.row.col.f32.f16.f16.f32 "
        "{%0,%1,%2,%3},{%4,%5,%6,%7},{%8,%9},{%0,%1,%2,%3};\n"
        : "+f"(c[0]), "+f"(c[1]), "+f"(c[2]), "+f"(c[3])
        : "r"(a[0]), "r"(a[1]), "r"(a[2]), "r"(a[3]), "r"(b[0]), "r"(b[1]));
}
__device__ __forceinline__ void cpa16(uint32_t dst, const void* src){
    asm volatile("cp.async.cg.shared.global [%0],[%1],16;\n"::"r"(dst),"l"(src));
}
__device__ __forceinline__ void cpa4(uint32_t dst, const void* src){
    asm volatile("cp.async.ca.shared.global [%0],[%1],4;\n"::"r"(dst),"l"(src));
}
#define CP_COMMIT() asm volatile("cp.async.commit_group;\n")
#define CP_WAIT0()  asm volatile("cp.async.wait_group 0;\n")
#define CP_WAIT1()  asm volatile("cp.async.wait_group 1;\n")

// ---------------------------------------------------------------------------
// Token shift (float4); mix written packed
// ---------------------------------------------------------------------------
__global__ void shift_kernel(const float* __restrict__ x,
                             const float* __restrict__ tmaax,
                             float* __restrict__ xx,
                             uint32_t* __restrict__ mixpk)
{
    size_t i4 = (size_t)blockIdx.x * blockDim.x + threadIdx.x;
    if (i4 >= (size_t)MT * NEC / 4) return;
    size_t idx = i4 * 4;
    int c = (int)(idx % NEC);
    size_t row = idx / NEC;
    int t = (int)(row % TSEQ);
    float4 xv = *(const float4*)&x[idx];
    float4 xp = (t > 0) ? *(const float4*)&x[idx - NEC] : make_float4(0,0,0,0);
    float4 tm = *(const float4*)&tmaax[c];
    float4 d  = make_float4(xp.x-xv.x, xp.y-xv.y, xp.z-xv.z, xp.w-xv.w);
    *(float4*)&xx[idx] = d;
    uint4 m;
    m.x = packf(fmaf(d.x, tm.x, xv.x));
    m.y = packf(fmaf(d.y, tm.y, xv.y));
    m.z = packf(fmaf(d.z, tm.z, xv.z));
    m.w = packf(fmaf(d.w, tm.w, xv.w));
    *(uint4*)&mixpk[idx] = m;
}

// ---------------------------------------------------------------------------
// Weight pack: Wr/Wk/Wv/Wo -> fp16 (half2 stores)
// ---------------------------------------------------------------------------
__global__ void wpack_kernel(const float* __restrict__ Wr, const float* __restrict__ Wk,
                             const float* __restrict__ Wv, const float* __restrict__ Wo,
                             __half* __restrict__ whalf)
{
    size_t i = (size_t)blockIdx.x * blockDim.x + threadIdx.x;   // 2 elems each
    if (i >= 2*NM) return;
    int seg = (int)(i >> 19);
    size_t off2 = (i & ((NM>>1) - 1)) * 2;
    const float* src = (seg==0) ? Wr : (seg==1) ? Wk : (seg==2) ? Wv : Wo;
    float2 v = *(const float2*)&src[off2];
    __half2 h = __halves2half2(__float2half_rn(v.x), __float2half_rn(v.y));
    *(__half2*)&whalf[(size_t)seg*NM + off2] = h;
}

// ---------------------------------------------------------------------------
// Hidden weight pack: 4 padded slices [128][1024] fp16
// ---------------------------------------------------------------------------
__global__ void wpack2_kernel(const float* __restrict__ gate_w1,
                              const float* __restrict__ decay_w1,
                              const float* __restrict__ aaa_w1,
                              const float* __restrict__ ma_w1,
                              const float* __restrict__ kkk_w1,
                              const float* __restrict__ mk_w1,
                              const float* __restrict__ maa_w1,
                              __half* __restrict__ whid)
{
    size_t i = (size_t)blockIdx.x * blockDim.x + threadIdx.x;
    if (i >= 4*HIDW) return;
    int slice = (int)(i / HIDW);
    size_t rem = i - (size_t)slice*HIDW;
    int row = (int)(rem >> 10);
    float v = 0.f;
    if (slice == 0) v = gate_w1[rem];
    else if (slice == 1) {
        if (row < 64)      v = decay_w1[rem];
        else if (row < 80) v = aaa_w1[rem - (size_t)64*NEC];
        else if (row < 96) v = ma_w1[rem - (size_t)80*NEC];
    } else if (slice == 2) {
        if (row < 16)      v = kkk_w1[rem];
        else if (row < 32) v = mk_w1[rem - (size_t)16*NEC];
    } else {
        v = maa_w1[rem];
    }
    whid[i] = __float2half_rn(v);
}

// ---------------------------------------------------------------------------
// Reduce + tanh for maa split-K partials
// ---------------------------------------------------------------------------
__global__ void hred_kernel(const float* __restrict__ hpart,
                            float* __restrict__ hmaa)
{
    size_t i4 = (size_t)blockIdx.x * blockDim.x + threadIdx.x;
    if (i4 >= HME/4) return;
    size_t idx = i4 * 4;
    float4 p0 = *(const float4*)&hpart[0*HME + idx];
    float4 p1 = *(const float4*)&hpart[1*HME + idx];
    float4 p2 = *(const float4*)&hpart[2*HME + idx];
    float4 p3 = *(const float4*)&hpart[3*HME + idx];
    float4 o;
    o.x = tanhf((p0.x+p1.x)+(p2.x+p3.x));
    o.y = tanhf((p0.y+p1.y)+(p2.y+p3.y));
    o.z = tanhf((p0.z+p1.z)+(p2.z+p3.z));
    o.w = tanhf((p0.w+p1.w)+(p2.w+p3.w));
    *(float4*)&hmaa[idx] = o;
}

// ---------------------------------------------------------------------------
// 2-product NT GEMM: grid (gx, 32, nz + maybe-hidden).
//   z < nz: C[4096,1024] = (Ah+Al) * Bh^T
//   z >= nz: blockIdx.x = hidden slice 0..3 (others/null exit); N=128.
// K = loop length; ldab = row stride of A and B (decoupled for split-K).
// ---------------------------------------------------------------------------
#define G5_LDSW 36
#define G5_AW   (128*G5_LDSW)
#define G5_LDHB 40
#define G5_BW   (128*G5_LDHB/2)
#define G5_STG  (G5_AW + G5_BW)

struct G5Args {
    const uint32_t* A[3]; const __half* B[3]; float* C[3];
    const uint32_t* HA[4]; const __half* HB[4]; float* HC[4]; int tanhN[4];
    int nz;
};

__global__ __launch_bounds__(256, 2)
void gemm_tc5(G5Args args, int K, int ldab)
{
    extern __shared__ uint32_t sm5[];
    const int z = blockIdx.z;
    const uint32_t* Apk; const __half* Bhp; float* C;
    int bn0, ldc, tanhN;
    if (z < args.nz) {
        Apk = args.A[z]; Bhp = args.B[z]; C = args.C[z];
        bn0 = blockIdx.x*128; ldc = NEC; tanhN = -1;
    } else {
        int s = blockIdx.x;
        if (s >= 4) return;
        Apk = args.HA[s]; Bhp = args.HB[s]; C = args.HC[s];
        if (!C) return;
        bn0 = 0; ldc = 128; tanhN = args.tanhN[s];
    }
    const int tid = threadIdx.x;
    const int bm0 = blockIdx.y*128;
    const int warp = tid>>5, lane = tid&31, grp = lane>>2, q = lane&3;
    const int wm = (warp&1)*64, wn = (warp>>1)*32;
    const uint32_t sbase = (uint32_t)__cvta_generic_to_shared(sm5);

    float acc[4][4][4];
    #pragma unroll
    for (int mi=0;mi<4;mi++)
        #pragma unroll
        for (int ni=0;ni<4;ni++)
            #pragma unroll
            for (int e=0;e<4;e++) acc[mi][ni][e]=0.f;

    const uint32_t* asrc[4]; uint32_t adst[4];
    #pragma unroll
    for (int l = 0; l < 4; l++) {
        int idx = tid + l*256;
        int r = idx >> 3, c4 = idx & 7;
        asrc[l] = Apk + (size_t)(bm0+r)*ldab + c4*4;
        adst[l] = sbase + (uint32_t)(r*G5_LDSW + c4*4)*4;
    }
    const __half* bsrc[2]; uint32_t bdst[2];
    #pragma unroll
    for (int l = 0; l < 2; l++) {
        int idx = tid + l*256;
        int r = idx >> 2, c4 = idx & 3;
        bsrc[l] = Bhp + (size_t)(bn0+r)*ldab + c4*8;
        bdst[l] = sbase + G5_AW*4 + (uint32_t)(r*G5_LDHB + c4*8)*2;
    }

#define G5_LOAD(st, kb) do {                                   \
        uint32_t _o = (st)*G5_STG*4;                           \
        _Pragma("unroll")                                      \
        for (int l = 0; l < 4; l++)                            \
            cpa16(adst[l] + _o, asrc[l] + (kb));               \
        _Pragma("unroll")                                      \
        for (int l = 0; l < 2; l++)                            \
            cpa16(bdst[l] + _o, bsrc[l] + (kb));               \
    } while(0)

    G5_LOAD(0, 0); CP_COMMIT();

    int p = 0;
    for (int kb = 0; kb < K; kb += 32) {
        CP_WAIT0();
        __syncthreads();
        if (kb + 32 < K) { G5_LOAD(p^1, kb+32); CP_COMMIT(); }

        const uint32_t* SA = sm5 + p*G5_STG;
        const __half*   SB = (const __half*)(sm5 + p*G5_STG + G5_AW);

        #pragma unroll
        for (int kc = 0; kc < 32; kc += 16) {
            uint32_t ah[4][4], al[4][4], bh[4][2];
            #pragma unroll
            for (int mi = 0; mi < 4; mi++) {
                int r0 = (wm + mi*16 + grp)*G5_LDSW + kc + 2*q;
                uint2 w0 = *(const uint2*)&SA[r0];
                uint2 w1 = *(const uint2*)&SA[r0 + 8*G5_LDSW];
                uint2 w2 = *(const uint2*)&SA[r0 + 8];
                uint2 w3 = *(const uint2*)&SA[r0 + 8*G5_LDSW + 8];
                ah[mi][0]=__byte_perm(w0.x,w0.y,0x5410); al[mi][0]=__byte_perm(w0.x,w0.y,0x7632);
                ah[mi][1]=__byte_perm(w1.x,w1.y,0x5410); al[mi][1]=__byte_perm(w1.x,w1.y,0x7632);
                ah[mi][2]=__byte_perm(w2.x,w2.y,0x5410); al[mi][2]=__byte_perm(w2.x,w2.y,0x7632);
                ah[mi][3]=__byte_perm(w3.x,w3.y,0x5410); al[mi][3]=__byte_perm(w3.x,w3.y,0x7632);
            }
            #pragma unroll
            for (int ni = 0; ni < 4; ni++) {
                int c0 = (wn + ni*8 + grp)*G5_LDHB + kc + 2*q;
                bh[ni][0] = *(const uint32_t*)&SB[c0];
                bh[ni][1] = *(const uint32_t*)&SB[c0 + 8];
            }
            #pragma unroll
            for (int mi = 0; mi < 4; mi++)
                #pragma unroll
                for (int ni = 0; ni < 4; ni++) {
                    mma_f16(acc[mi][ni], ah[mi], bh[ni]);
                    mma_f16(acc[mi][ni], al[mi], bh[ni]);
                }
        }
        __syncthreads();
        p ^= 1;
    }

    #pragma unroll
    for (int mi = 0; mi < 4; mi++) {
        int row0 = bm0 + wm + mi*16 + grp;
        #pragma unroll
        for (int ni = 0; ni < 4; ni++) {
            int col = bn0 + wn + ni*8 + 2*q;
            float e0 = acc[mi][ni][0], e1 = acc[mi][ni][1];
            float e2 = acc[mi][ni][2], e3 = acc[mi][ni][3];
            if (tanhN >= 0) {
                if (col   < tanhN) { e0 = tanhf(e0); e2 = tanhf(e2); }
                if (col+1 < tanhN) { e1 = tanhf(e1); e3 = tanhf(e3); }
            }
            *(float2*)&C[(size_t)row0*ldc + col]     = make_float2(e0, e1);
            *(float2*)&C[(size_t)(row0+8)*ldc + col] = make_float2(e2, e3);
        }
    }
#undef G5_LOAD
}

// ---------------------------------------------------------------------------
// Fused xm kernel: val = x + xx*(Ag @ Bg + time_maa[g]); all groups packed.
// ---------------------------------------------------------------------------
__global__ __launch_bounds__(256, 2)
void xm_kernel(const float* __restrict__ hmaa,
               const float* __restrict__ maa_w2,
               const float* __restrict__ x,
               const float* __restrict__ xx,
               const float* __restrict__ time_maa,
               uint32_t* __restrict__ xmbase)
{
    constexpr int BM=128, BN=128, BK=32;
    __shared__ float As[BK][BM+1];
    __shared__ float Bs[BK][BN];
    const int g = blockIdx.z;
    const float* A = hmaa + g*32;
    const float* B = maa_w2 + (size_t)g*32*NEC;
    uint32_t* C = xmbase + (size_t)g*MT*NEC;
    const float* tm = time_maa + g*NEC;
    const int bm0 = blockIdx.y*BM, bn0 = blockIdx.x*BN;
    const int tid = threadIdx.x;
    const int tx = tid & 15, ty = tid >> 4;

    float acc[8][8];
    #pragma unroll
    for (int i=0;i<8;i++)
        #pragma unroll
        for (int j=0;j<8;j++) acc[i][j]=0.f;

    #pragma unroll
    for (int l = 0; l < 4; l++) {
        int idx = tid + l*256;
        int r = idx >> 3, c = (idx & 7)*4;
        float4 val = *(const float4*)(A + (size_t)(bm0+r)*128 + c);
        As[c+0][r]=val.x; As[c+1][r]=val.y; As[c+2][r]=val.z; As[c+3][r]=val.w;
    }
    #pragma unroll
    for (int l = 0; l < 4; l++) {
        int idx = tid + l*256;
        int r = idx >> 5, c = (idx & 31)*4;
        *(float4*)&Bs[r][c] = *(const float4*)(B + (size_t)r*NEC + bn0 + c);
    }
    __syncthreads();
    #pragma unroll
    for (int kk = 0; kk < BK; kk++) {
        float rm[8], rn[8];
        #pragma unroll
        for (int i=0;i<8;i++) rm[i] = As[kk][ty*8+i];
        #pragma unroll
        for (int j=0;j<8;j++) rn[j] = Bs[kk][tx*8+j];
        #pragma unroll
        for (int i=0;i<8;i++)
            #pragma unroll
            for (int j=0;j<8;j++) acc[i][j] = fmaf(rm[i], rn[j], acc[i][j]);
    }
    #pragma unroll
    for (int i=0;i<8;i++) {
        int row = bm0 + ty*8 + i;
        #pragma unroll
        for (int j=0;j<8;j+=2) {
            int col = bn0 + tx*8 + j;
            size_t idx = (size_t)row*NEC + col;
            float2 xv = *(const float2*)&x[idx];
            float2 dv = *(const float2*)&xx[idx];
            float v0 = fmaf(dv.x, acc[i][j]   + tm[col],   xv.x);
            float v1 = fmaf(dv.y, acc[i][j+1] + tm[col+1], xv.y);
            *(uint2*)&C[idx] = make_uint2(packf(v0), packf(v1));
        }
    }
}

// ---------------------------------------------------------------------------
// Grouped second-stage NN kernel (A with lda + column offset)
// ---------------------------------------------------------------------------
struct NNGroup { const float* A; int lda; int koff; const float* B; float* C;
                 int K; int epi; const float* e2; };
struct NNArgs { NNGroup g[6]; };

__global__ __launch_bounds__(256)
void lora_nn_kernel(NNArgs args)
{
    constexpr int BM=128, BN=128, BK=16;
    __shared__ float As[BK][BM+1];
    __shared__ float Bs[BK][BN];
    NNGroup grp = args.g[blockIdx.z];
    const int K = grp.K;
    const int bm0 = blockIdx.y*BM, bn0 = blockIdx.x*BN;
    const int tid = threadIdx.x;
    const int tx = tid & 15, ty = tid >> 4;

    float acc[8][8];
    #pragma unroll
    for (int i=0;i<8;i++)
        #pragma unroll
        for (int j=0;j<8;j++) acc[i][j]=0.f;

    for (int kb = 0; kb < K; kb += BK) {
        #pragma unroll
        for (int l = 0; l < 2; l++) {
            int idx = tid + l*256;
            int r = idx >> 2, c = (idx & 3)*4;
            float4 val = *(const float4*)(grp.A + (size_t)(bm0+r)*grp.lda + grp.koff + kb + c);
            As[c+0][r]=val.x; As[c+1][r]=val.y; As[c+2][r]=val.z; As[c+3][r]=val.w;
        }
        #pragma unroll
        for (int l = 0; l < 2; l++) {
            int idx = tid + l*256;
            int r = idx >> 5, c = (idx & 31)*4;
            *(float4*)&Bs[r][c] = *(const float4*)(grp.B + (size_t)(kb+r)*NEC + bn0 + c);
        }
        __syncthreads();
        #pragma unroll
        for (int kk = 0; kk < BK; kk++) {
            float rm[8], rn[8];
            #pragma unroll
            for (int i=0;i<8;i++) rm[i] = As[kk][ty*8+i];
            #pragma unroll
            for (int j=0;j<8;j++) rn[j] = Bs[kk][tx*8+j];
            #pragma unroll
            for (int i=0;i<8;i++)
                #pragma unroll
                for (int j=0;j<8;j++) acc[i][j] = fmaf(rm[i], rn[j], acc[i][j]);
        }
        __syncthreads();
    }
    #pragma unroll
    for (int i=0;i<8;i++) {
        int row = bm0 + ty*8 + i;
        #pragma unroll
        for (int j=0;j<8;j++) {
            int col = bn0 + tx*8 + j;
            size_t idx = (size_t)row*NEC + col;
            float vv = acc[i][j], outv;
            switch (grp.epi) {
                case EPI_W: {
                    float tt = -(grp.e2[col] + vv);
                    float sp = (tt > 15.f) ? tt : log1pf(expf(tt));
                    outv = -sp - 0.5f;
                } break;
                case EPI_SIG: {
                    float u = grp.e2[col] + vv;
                    outv = 1.f / (1.f + expf(-u));
                } break;
                default: outv = vv;
            }
            grp.C[idx] = outv;
        }
    }
}

// ---------------------------------------------------------------------------
// warp sum
// ---------------------------------------------------------------------------
__device__ __forceinline__ float warp_sum(float v)
{
    #pragma unroll
    for (int o = 16; o > 0; o >>= 1) v += __shfl_xor_sync(0xffffffffu, v, o);
    return v;
}

// ---------------------------------------------------------------------------
// prep: kk = normalize(kkraw + k); b = -kk*a; k final; w transform
// ---------------------------------------------------------------------------
__global__ void prep_kernel(float* kptr, float* kkptr,
                            const float* __restrict__ a,
                            const float* __restrict__ ma,
                            const float* __restrict__ mk,
                            float* wptr,
                            float* __restrict__ b)
{
    int m = blockIdx.x;
    int h = threadIdx.x >> 5;
    int lane = threadIdx.x & 31;
    size_t base = (size_t)m*NEC + h*HSZ;
    size_t i0 = base + lane, i1 = i0 + 32;

    float k0v = kptr[i0], k1v = kptr[i1];
    float kk0 = kkptr[i0] + k0v, kk1 = kkptr[i1] + k1v;
    float ss = warp_sum(kk0*kk0 + kk1*kk1);
    float inv = 1.f / fmaxf(sqrtf(ss), 1e-12f);
    float n0 = kk0*inv, n1 = kk1*inv;
    kkptr[i0] = n0; kkptr[i1] = n1;

    float a0 = a[i0], a1 = a[i1];
    b[i0] = -n0*a0; b[i1] = -n1*a1;

    float ma0 = ma[i0], ma1 = ma[i1];
    float w0 = wptr[i0], w1 = wptr[i1];
    float mk0 = mk[i0], mk1 = mk[i1];
    kptr[i0] = k0v * (ma0 + a0*(1.f - ma0)) * expf(w0*mk0);
    kptr[i1] = k1v * (ma1 + a1*(1.f - ma1)) * expf(w1*mk1);
    wptr[i0] = expf(-expf(w0));
    wptr[i1] = expf(-expf(w1));
}

// ---------------------------------------------------------------------------
// RWKV7 recurrence v5: 2 blocks per head; 32 rows x 8-way column split;
// 3-PAIR cp.async ring, 2 steps per iteration (one sync / 2 steps).
// ---------------------------------------------------------------------------
__device__ __forceinline__ void wkv7_step(const float* __restrict__ bb,
                                          float* __restrict__ s,
                                          int il, int qd,
                                          float* __restrict__ yout)
{
    const int co = qd*8;
    const float4* q4 = (const float4*)(bb +   0 + co);
    const float4* w4 = (const float4*)(bb +  64 + co);
    const float4* k4 = (const float4*)(bb + 128 + co);
    const float4* a4 = (const float4*)(bb + 192 + co);
    const float4* b4 = (const float4*)(bb + 256 + co);
    float vi = bb[320 + il];

    float4 av0 = a4[0], av1 = a4[1];
    float sa0 = fmaf(s[0], av0.x, s[4]*av1.x);
    float sa1 = fmaf(s[1], av0.y, s[5]*av1.y);
    float sa2 = fmaf(s[2], av0.z, s[6]*av1.z);
    float sa3 = fmaf(s[3], av0.w, s[7]*av1.w);
    float sa = (sa0+sa1) + (sa2+sa3);
    sa += __shfl_xor_sync(0xffffffffu, sa, 1);
    sa += __shfl_xor_sync(0xffffffffu, sa, 2);
    sa += __shfl_xor_sync(0xffffffffu, sa, 4);

    float4 wv0 = w4[0], wv1 = w4[1];
    float4 kv0 = k4[0], kv1 = k4[1];
    float4 bv0 = b4[0], bv1 = b4[1];
    float4 qv0 = q4[0], qv1 = q4[1];

    float t0 = fmaf(s[0], wv0.x, fmaf(sa, bv0.x, vi*kv0.x));
    float t1 = fmaf(s[1], wv0.y, fmaf(sa, bv0.y, vi*kv0.y));
    float t2 = fmaf(s[2], wv0.z, fmaf(sa, bv0.z, vi*kv0.z));
    float t3 = fmaf(s[3], wv0.w, fmaf(sa, bv0.w, vi*kv0.w));
    float t4 = fmaf(s[4], wv1.x, fmaf(sa, bv1.x, vi*kv1.x));
    float t5 = fmaf(s[5], wv1.y, fmaf(sa, bv1.y, vi*kv1.y));
    float t6 = fmaf(s[6], wv1.z, fmaf(sa, bv1.z, vi*kv1.z));
    float t7 = fmaf(s[7], wv1.w, fmaf(sa, bv1.w, vi*kv1.w));
    s[0]=t0; s[1]=t1; s[2]=t2; s[3]=t3; s[4]=t4; s[5]=t5; s[6]=t6; s[7]=t7;

    float y0 = fmaf(t0, qv0.x, t4*qv1.x);
    float y1 = fmaf(t1, qv0.y, t5*qv1.y);
    float y2 = fmaf(t2, qv0.z, t6*qv1.z);
    float y3 = fmaf(t3, qv0.w, t7*qv1.w);
    float yi = (y0+y1) + (y2+y3);
    yi += __shfl_xor_sync(0xffffffffu, yi, 1);
    yi += __shfl_xor_sync(0xffffffffu, yi, 2);
    yi += __shfl_xor_sync(0xffffffffu, yi, 4);
    if (qd == 0) *yout = yi;
}

__global__ __launch_bounds__(256)
void wkv7_kernel(const float* __restrict__ q, const float* __restrict__ w,
                 const float* __restrict__ k, const float* __restrict__ v,
                 const float* __restrict__ a, const float* __restrict__ b,
                 float* __restrict__ y)
{
    const int blk = blockIdx.x;            // 0..127
    const int bh = blk >> 1, rh = blk & 1;
    const int batch = bh >> 4, h = bh & 15;
    const int tid = threadIdx.x;
    const int il = tid >> 3, qd = tid & 7;

    __shared__ __align__(16) float buf[3][704];   // pair ring: 2 steps per pair

    float s[8];
    #pragma unroll
    for (int j = 0; j < 8; j++) s[j] = 0.f;

    const size_t base = (size_t)batch * TSEQ * NEC + (size_t)h * HSZ;

    const float* table[4] = {q, w, k, a};
    const float* s0 = table[tid>>6] + base + (tid & 63);
    const float* s1 = nullptr;
    if (tid < 64)       s1 = b + base + tid;
    else if (tid < 96)  s1 = v + base + rh*32 + (tid - 64);
    const uint32_t sb = (uint32_t)__cvta_generic_to_shared(buf);
    const uint32_t d0 = sb + (uint32_t)tid*4;
    const uint32_t d1 = sb + (uint32_t)(256 + tid)*4;
    const uint32_t PAIRB = 704*4;
    const uint32_t STEPB = 352*4;

    // prologue: pair0 = steps 0,1 ; pair1 = steps 2,3
    #pragma unroll
    for (int pr = 0; pr < 2; pr++) {
        size_t o = (size_t)(2*pr)*NEC;
        cpa4(d0 + pr*PAIRB, s0 + o);
        if (tid < 96) cpa4(d1 + pr*PAIRB, s1 + o);
        cpa4(d0 + pr*PAIRB + STEPB, s0 + o + NEC);
        if (tid < 96) cpa4(d1 + pr*PAIRB + STEPB, s1 + o + NEC);
        CP_COMMIT();
    }

    const size_t ybase = base + (size_t)rh*32 + il;

    int pp = 0;
    for (int t = 0; t < TSEQ; t += 2) {
        CP_WAIT1();
        __syncthreads();

        {
            int pf = pp + 2; if (pf >= 3) pf -= 3;
            if (t + 4 < TSEQ) {
                size_t o = (size_t)(t+4)*NEC;
                uint32_t db = (uint32_t)pf*PAIRB;
                cpa4(d0 + db, s0 + o);
                if (tid < 96) cpa4(d1 + db, s1 + o);
                cpa4(d0 + db + STEPB, s0 + o + NEC);
                if (tid < 96) cpa4(d1 + db + STEPB, s1 + o + NEC);
            }
            CP_COMMIT();
        }

        wkv7_step(&buf[pp][0],   s, il, qd, &y[ybase + (size_t)t*NEC]);
        wkv7_step(&buf[pp][352], s, il, qd, &y[ybase + (size_t)(t+1)*NEC]);

        if (++pp == 3) pp = 0;
    }
}

// ---------------------------------------------------------------------------
// GroupNorm + bonus + gate -> packed z
// ---------------------------------------------------------------------------
__global__ void gn_kernel(const float* __restrict__ y,
                          const float* __restrict__ r,
                          const float* __restrict__ k,
                          const float* __restrict__ v,
                          const float* __restrict__ gg,
                          const float* __restrict__ ln_w,
                          const float* __restrict__ ln_b,
                          const float* __restrict__ faaaa,
                          uint32_t* __restrict__ zpk)
{
    int m = blockIdx.x;
    int h = threadIdx.x >> 5;
    int lane = threadIdx.x & 31;
    size_t base = (size_t)m*NEC + h*HSZ;
    int c0 = h*HSZ + lane, c1 = c0 + 32;
    size_t i0 = base + lane, i1 = i0 + 32;

    float y0 = y[i0], y1 = y[i1];
    float mu = warp_sum(y0 + y1) * (1.f/64.f);
    float d0 = y0 - mu, d1 = y1 - mu;
    float var = warp_sum(d0*d0 + d1*d1) * (1.f/64.f);
    float rstd = rsqrtf(var + EPSGN);
    float yn0 = d0*rstd*ln_w[c0] + ln_b[c0];
    float yn1 = d1*rstd*ln_w[c1] + ln_b[c1];

    float r0 = r[i0], r1 = r[i1];
    float k0v = k[i0], k1v = k[i1];
    float rk = warp_sum(r0*k0v*faaaa[c0] + r1*k1v*faaaa[c1]);

    float v0 = v[i0], v1 = v[i1];
    zpk[i0] = packf((yn0 + rk*v0) * gg[i0]);
    zpk[i1] = packf((yn1 + rk*v1) * gg[i1]);
}

// ---------------------------------------------------------------------------
// Host side
// ---------------------------------------------------------------------------
extern "C" void kernel_launch(void* const* d_in, const int* in_sizes, int n_in,
                              void* d_out, int out_size)
{
    const float* x          = (const float*)d_in[0];
    const float* time_maa_x = (const float*)d_in[1];
    const float* time_maa   = (const float*)d_in[2];
    const float* maa_w1     = (const float*)d_in[3];
    const float* maa_w2     = (const float*)d_in[4];
    const float* decay_w1   = (const float*)d_in[5];
    const float* decay_w2   = (const float*)d_in[6];
    const float* aaa_w1     = (const float*)d_in[7];
    const float* aaa_w2     = (const float*)d_in[8];
    const float* kkk_w1     = (const float*)d_in[9];
    const float* kkk_w2     = (const float*)d_in[10];
    const float* gate_w1    = (const float*)d_in[11];
    const float* gate_w2    = (const float*)d_in[12];
    const float* ma_w1      = (const float*)d_in[13];
    const float* ma_w2      = (const float*)d_in[14];
    const float* mk_w1      = (const float*)d_in[15];
    const float* mk_w2      = (const float*)d_in[16];
    const float* time_decay = (const float*)d_in[17];
    const float* time_faaaa = (const float*)d_in[18];
    const float* time_aaaaa = (const float*)d_in[19];
    const float* time_misc_a= (const float*)d_in[20];
    const float* time_misc_k= (const float*)d_in[21];
    const float* Wr         = (const float*)d_in[22];
    const float* Wk         = (const float*)d_in[23];
    const float* Wv         = (const float*)d_in[24];
    const float* Wo         = (const float*)d_in[25];
    const float* ln_w       = (const float*)d_in[26];
    const float* ln_b       = (const float*)d_in[27];
    float* out = (float*)d_out;

    float *xx,*hpart,*hmaa,*hgate,*hwaa,*hk;
    uint32_t *mixpk,*xm,*zpk; __half *whalf,*whid;
    float *r,*gg,*k,*v,*w,*kk,*a,*ma,*mk,*b,*y;
    cudaGetSymbolAddress((void**)&xx,   g_xx);
    cudaGetSymbolAddress((void**)&mixpk,g_mixpk);
    cudaGetSymbolAddress((void**)&hpart,g_hpart);
    cudaGetSymbolAddress((void**)&hmaa, g_hmaa);
    cudaGetSymbolAddress((void**)&hgate,g_hgate);
    cudaGetSymbolAddress((void**)&hwaa, g_hwaa);
    cudaGetSymbolAddress((void**)&hk,   g_hk);
    cudaGetSymbolAddress((void**)&xm,   g_xm);
    cudaGetSymbolAddress((void**)&whalf,g_whalf);
    cudaGetSymbolAddress((void**)&whid, g_whid);
    cudaGetSymbolAddress((void**)&zpk,  g_zpk);
    cudaGetSymbolAddress((void**)&r,    g_r);
    cudaGetSymbolAddress((void**)&gg,   g_gg);
    cudaGetSymbolAddress((void**)&k,    g_k);
    cudaGetSymbolAddress((void**)&v,    g_v);
    cudaGetSymbolAddress((void**)&w,    g_w);
    cudaGetSymbolAddress((void**)&kk,   g_kk);
    cudaGetSymbolAddress((void**)&a,    g_a);
    cudaGetSymbolAddress((void**)&ma,   g_ma);
    cudaGetSymbolAddress((void**)&mk,   g_mk);
    cudaGetSymbolAddress((void**)&b,    g_b);
    cudaGetSymbolAddress((void**)&y,    g_y);

    const size_t S = (size_t)MT*NEC;
    const uint32_t* xrg_pk = xm + 0*S;
    const uint32_t* xwa_pk = xm + 1*S;
    const uint32_t* xk_pk  = xm + 2*S;
    const uint32_t* xv_pk  = xm + 3*S;

    static bool attr_done = false;
    if (!attr_done) {
        cudaFuncSetAttribute(gemm_tc5, cudaFuncAttributeMaxDynamicSharedMemorySize,
                             2*G5_STG*4);
        attr_done = true;
    }
    const int g5_smem = 2*G5_STG*4;

    // 1) token shift (mix packed)
    shift_kernel<<<(unsigned)((S/4 + 255)/256), 256>>>(x, time_maa_x, xx, mixpk);

    // 2) weight packs
    wpack_kernel<<<(unsigned)((2*NM + 255)/256), 256>>>(Wr, Wk, Wv, Wo, whalf);
    wpack2_kernel<<<(unsigned)((4*HIDW + 255)/256), 256>>>(
        gate_w1, decay_w1, aaa_w1, ma_w1, kkk_w1, mk_w1, maa_w1, whid);

    // 3) maa hidden split-K 4 on tensor cores -> partials, then reduce+tanh
    {
        G5Args ga = {};
        ga.nz = 0;
        for (int sK = 0; sK < 4; sK++) {
            ga.HA[sK] = mixpk + sK*256;
            ga.HB[sK] = whid + 3*HIDW + sK*256;
            ga.HC[sK] = hpart + (size_t)sK*HME;
            ga.tanhN[sK] = -1;
        }
        gemm_tc5<<<dim3(4, 32, 1), 256, g5_smem>>>(ga, 256, NEC);
    }
    hred_kernel<<<(unsigned)((HME/4 + 255)/256), 256>>>(hpart, hmaa);

    // 4) xm fused (4 groups, all packed)
    xm_kernel<<<dim3(8, MT/128, 4), 256>>>(hmaa, maa_w2, x, xx, time_maa, xm);

    // 5) mega GEMM: r,k,v (z 0-2) + hidden slices (z 3)
    {
        G5Args ga = {};
        ga.nz = 3;
        ga.A[0] = xrg_pk; ga.B[0] = whalf + 0*NM; ga.C[0] = r;
        ga.A[1] = xk_pk;  ga.B[1] = whalf + 1*NM; ga.C[1] = k;
        ga.A[2] = xv_pk;  ga.B[2] = whalf + 2*NM; ga.C[2] = v;
        ga.HA[0] = xrg_pk; ga.HB[0] = whid + 0*HIDW; ga.HC[0] = hgate; ga.tanhN[0] = 128;
        ga.HA[1] = xwa_pk; ga.HB[1] = whid + 1*HIDW; ga.HC[1] = hwaa;  ga.tanhN[1] = 64;
        ga.HA[2] = xk_pk;  ga.HB[2] = whid + 2*HIDW; ga.HC[2] = hk;    ga.tanhN[2] = 16;
        ga.HC[3] = nullptr;
        gemm_tc5<<<dim3(8, 32, 4), 256, g5_smem>>>(ga, NEC, NEC);
    }

    // 6) second stage (6 groups from hidden slices)
    {
        NNArgs nn = {};
        nn.g[0] = { hgate, 128, 0,  gate_w2,  gg, 128, EPI_NONE, nullptr };
        nn.g[1] = { hwaa,  128, 0,  decay_w2, w,   64, EPI_W,    time_decay };
        nn.g[2] = { hk,    128, 0,  kkk_w2,   kk,  16, EPI_NONE, nullptr };
        nn.g[3] = { hwaa,  128, 64, aaa_w2,   a,   16, EPI_SIG,  time_aaaaa };
        nn.g[4] = { hwaa,  128, 80, ma_w2,    ma,  16, EPI_SIG,  time_misc_a };
        nn.g[5] = { hk,    128, 16, mk_w2,    mk,  16, EPI_SIG,  time_misc_k };
        lora_nn_kernel<<<dim3(8, MT/128, 6), 256>>>(nn);
    }

    // 7) prep (adds +k to kkraw before norm)
    prep_kernel<<<MT, 512>>>(k, kk, a, ma, mk, w, b);

    // 8) recurrence (pair-unrolled)
    wkv7_kernel<<<BATCH*NH*2, 256>>>(r, w, k, v, kk, b, y);

    // 9) groupnorm + bonus + gate -> packed z
    gn_kernel<<<MT, 512>>>(y, r, k, v, gg, ln_w, ln_b, time_faaaa, zpk);

    // 10) out = z @ Wo.T (2-product)
    {
        G5Args ga = {};
        ga.nz = 1;
        ga.A[0] = zpk; ga.B[0] = whalf + 3*NM; ga.C[0] = out;
        gemm_tc5<<<dim3(8, 32, 1), 256, g5_smem>>>(ga, NEC, NEC);
    }
}